// round 1
// baseline (speedup 1.0000x reference)
#include <cuda_runtime.h>
#include <math.h>

// ---------------- problem constants ----------------
#define BBATCH 2
#define LSEQ 2048
#define DMODEL 256
#define DINNER 512
#define DSTATE 128
#define NHEADS 8
#define HEADDIM 64
#define CONVDIM 768          // DINNER + 2*DSTATE
#define DINPROJ 1288         // 2*DINNER + 2*DSTATE + NHEADS
#define AHD 32               // attention head dim (DMODEL / 8)
#define MLPH 1024
#define M4 (BBATCH * LSEQ)   // 4096 rows

// ---------------- scratch buffers (static, no allocation) ----------------
__device__ float g_zxbcdt[(size_t)M4 * DINPROJ];
__device__ float g_xBC[(size_t)M4 * CONVDIM];
__device__ float g_dt[M4 * NHEADS];
__device__ float g_dA[M4 * NHEADS];
__device__ float g_y[(size_t)M4 * DINNER];
__device__ float g_hres[(size_t)M4 * DMODEL];
__device__ float g_q[(size_t)M4 * DMODEL];
__device__ float g_k[(size_t)M4 * DMODEL];
__device__ float g_v[(size_t)M4 * DMODEL];
__device__ float g_o[(size_t)M4 * DMODEL];
__device__ float g_ob[(size_t)M4 * DMODEL];
__device__ float g_mlp[(size_t)M4 * MLPH];
__device__ float g_h2[(size_t)M4 * DMODEL];

// ---------------- generic tiled GEMM: C = A[MxK] @ W[NxK]^T (+epilogue) ----------------
enum { EPI_NONE = 0, EPI_BIAS = 1, EPI_BIAS_GELU = 2, EPI_RES = 3 };

template <int EPI>
__global__ void __launch_bounds__(256)
gemm_kernel(const float* __restrict__ A, const float* __restrict__ W,
            const float* __restrict__ bias, const float* __restrict__ res,
            float* __restrict__ C, int M, int N, int K)
{
    constexpr int BM = 64, BN = 64, BK = 16;
    __shared__ __align__(16) float As[BK][BM + 4];
    __shared__ __align__(16) float Ws[BK][BN + 4];

    const int m0 = blockIdx.y * BM;
    const int n0 = blockIdx.x * BN;
    const int tid = threadIdx.x;
    const int tx = tid & 15;
    const int ty = tid >> 4;
    const int lr = tid >> 2;          // 0..63
    const int lk = (tid & 3) << 2;    // 0,4,8,12

    float acc[4][4];
#pragma unroll
    for (int i = 0; i < 4; i++)
#pragma unroll
        for (int j = 0; j < 4; j++) acc[i][j] = 0.f;

    const float* Aptr = A + (size_t)(m0 + lr) * K + lk;
    const bool wvalid = (n0 + lr) < N;
    const float* Wptr = W + (size_t)(wvalid ? (n0 + lr) : 0) * K + lk;

    for (int k0 = 0; k0 < K; k0 += BK) {
        float4 a4 = *(const float4*)(Aptr + k0);
        float4 w4 = make_float4(0.f, 0.f, 0.f, 0.f);
        if (wvalid) w4 = *(const float4*)(Wptr + k0);
        As[lk + 0][lr] = a4.x; As[lk + 1][lr] = a4.y;
        As[lk + 2][lr] = a4.z; As[lk + 3][lr] = a4.w;
        Ws[lk + 0][lr] = w4.x; Ws[lk + 1][lr] = w4.y;
        Ws[lk + 2][lr] = w4.z; Ws[lk + 3][lr] = w4.w;
        __syncthreads();
#pragma unroll
        for (int kk = 0; kk < BK; kk++) {
            float4 av = *(const float4*)&As[kk][ty << 2];
            float4 wv = *(const float4*)&Ws[kk][tx << 2];
            float a_[4] = {av.x, av.y, av.z, av.w};
            float w_[4] = {wv.x, wv.y, wv.z, wv.w};
#pragma unroll
            for (int i = 0; i < 4; i++)
#pragma unroll
                for (int j = 0; j < 4; j++) acc[i][j] += a_[i] * w_[j];
        }
        __syncthreads();
    }

#pragma unroll
    for (int i = 0; i < 4; i++) {
        int row = m0 + (ty << 2) + i;
#pragma unroll
        for (int j = 0; j < 4; j++) {
            int col = n0 + (tx << 2) + j;
            if (col < N) {
                float v = acc[i][j];
                if (EPI == EPI_BIAS || EPI == EPI_BIAS_GELU) v += bias[col];
                if (EPI == EPI_BIAS_GELU) v = 0.5f * v * (1.f + erff(v * 0.70710678118f));
                if (EPI == EPI_RES) v += res[(size_t)row * N + col];
                C[(size_t)row * N + col] = v;
            }
        }
    }
}

// ---------------- conv1d (causal, 4 taps) + SiLU, plus dt/dA ----------------
__global__ void conv_dt_kernel(const float* __restrict__ conv_w,
                               const float* __restrict__ conv_b,
                               const float* __restrict__ dt_bias,
                               const float* __restrict__ A_log)
{
    int bl = blockIdx.x;          // 0..4095
    int c = threadIdx.x;          // 0..767
    int b = bl / LSEQ, l = bl % LSEQ;

    float accv = conv_b[c];
#pragma unroll
    for (int k = 0; k < 4; k++) {
        int ls = l - 3 + k;
        if (ls >= 0)
            accv += conv_w[c * 4 + k] *
                    g_zxbcdt[(size_t)(b * LSEQ + ls) * DINPROJ + DINNER + c];
    }
    float s = accv / (1.f + expf(-accv));   // SiLU
    g_xBC[(size_t)bl * CONVDIM + c] = s;

    if (c < NHEADS) {
        float v = g_zxbcdt[(size_t)bl * DINPROJ + (DINNER + CONVDIM) + c] + dt_bias[c];
        float dt = (v > 20.f) ? v : log1pf(expf(v));   // softplus
        g_dt[bl * NHEADS + c] = dt;
        g_dA[bl * NHEADS + c] = expf(dt * -expf(A_log[c]));
    }
}

// ---------------- selective scan: one warp per (b,h,p), 4 state cols/lane ----------------
__global__ void __launch_bounds__(128) scan_kernel()
{
    int bidx = blockIdx.x;                 // 256 blocks
    int pg = bidx & 15;
    int h = (bidx >> 4) & 7;
    int b = bidx >> 7;
    int warp = threadIdx.x >> 5;
    int lane = threadIdx.x & 31;
    int p = pg * 4 + warp;                 // 0..63
    int n0 = lane * 4;

    float h0 = 0.f, h1 = 0.f, h2 = 0.f, h3 = 0.f;
    const float* xbase = g_xBC + (size_t)b * LSEQ * CONVDIM;
    const float* dtb = g_dt + (size_t)b * LSEQ * NHEADS + h;
    const float* dab = g_dA + (size_t)b * LSEQ * NHEADS + h;
    float* yout = g_y + (size_t)b * LSEQ * DINNER + h * HEADDIM + p;
    const int coff = h * HEADDIM + p;

    for (int t = 0; t < LSEQ; t++) {
        const float* row = xbase + (size_t)t * CONVDIM;
        float dA = dab[t * NHEADS];
        float dt = dtb[t * NHEADS];
        float xv = row[coff];
        float4 Bv = *(const float4*)(row + DINNER + n0);
        float4 Cv = *(const float4*)(row + DINNER + DSTATE + n0);
        float dtx = dt * xv;
        h0 = h0 * dA + dtx * Bv.x;
        h1 = h1 * dA + dtx * Bv.y;
        h2 = h2 * dA + dtx * Bv.z;
        h3 = h3 * dA + dtx * Bv.w;
        float accr = h0 * Cv.x + h1 * Cv.y + h2 * Cv.z + h3 * Cv.w;
#pragma unroll
        for (int o = 16; o; o >>= 1) accr += __shfl_xor_sync(0xffffffffu, accr, o);
        if (lane == 0) yout[(size_t)t * DINNER] = accr;
    }
}

// ---------------- y = (y + D*xs) * silu(z), RMSNorm * norm_w (in-place on g_y) ----------
__global__ void __launch_bounds__(512) gate_rms_kernel(const float* __restrict__ D_param,
                                                       const float* __restrict__ norm_w)
{
    int bl = blockIdx.x;
    int d = threadIdx.x;                   // 0..511
    float y = g_y[(size_t)bl * DINNER + d] +
              D_param[d >> 6] * g_xBC[(size_t)bl * CONVDIM + d];
    float z = g_zxbcdt[(size_t)bl * DINPROJ + d];
    float g = y * (z / (1.f + expf(-z)));

    __shared__ float sh[16];
    float s = g * g;
    int lane = d & 31, w = d >> 5;
#pragma unroll
    for (int o = 16; o; o >>= 1) s += __shfl_xor_sync(0xffffffffu, s, o);
    if (lane == 0) sh[w] = s;
    __syncthreads();
    if (w == 0) {
        float v = (lane < 16) ? sh[lane] : 0.f;
#pragma unroll
        for (int o = 16; o; o >>= 1) v += __shfl_xor_sync(0xffffffffu, v, o);
        if (lane == 0) sh[0] = v;
    }
    __syncthreads();
    float scale = rsqrtf(sh[0] * (1.f / DINNER) + 1e-5f);
    g_y[(size_t)bl * DINNER + d] = g * scale * norm_w[d];
}

// ---------------- flash attention (non-causal), 1 thread = 1 query -------------
__global__ void __launch_bounds__(128) attn_kernel()
{
    constexpr int KT = 32;
    int qt = blockIdx.x, hh = blockIdx.y, b = blockIdx.z;
    int t = qt * 128 + threadIdx.x;

    __shared__ float ks[KT][AHD];
    __shared__ float vs[KT][AHD];

    float q[AHD], o[AHD];
    const float* qrow = g_q + ((size_t)(b * LSEQ + t)) * DMODEL + hh * AHD;
    const float scale = 0.1767766953f;     // 1/sqrt(32)
#pragma unroll
    for (int d = 0; d < AHD; d++) { q[d] = qrow[d] * scale; o[d] = 0.f; }
    float m = -1e30f, lsum = 0.f;

    for (int s0 = 0; s0 < LSEQ; s0 += KT) {
        __syncthreads();
#pragma unroll
        for (int i = 0; i < 8; i++) {
            int e = threadIdx.x + i * 128;
            int s = e >> 5, d = e & 31;
            size_t gi = ((size_t)(b * LSEQ + s0 + s)) * DMODEL + hh * AHD + d;
            ks[s][d] = g_k[gi];
            vs[s][d] = g_v[gi];
        }
        __syncthreads();
#pragma unroll 4
        for (int s = 0; s < KT; s++) {
            float sc = 0.f;
#pragma unroll
            for (int d = 0; d < AHD; d++) sc += q[d] * ks[s][d];
            if (sc > m) {
                float corr = __expf(m - sc);
                lsum *= corr;
#pragma unroll
                for (int d = 0; d < AHD; d++) o[d] *= corr;
                m = sc;
            }
            float p = __expf(sc - m);
            lsum += p;
#pragma unroll
            for (int d = 0; d < AHD; d++) o[d] += p * vs[s][d];
        }
    }
    float inv = 1.f / lsum;
    float* orow = g_o + ((size_t)(b * LSEQ + t)) * DMODEL + hh * AHD;
#pragma unroll
    for (int d = 0; d < AHD; d++) orow[d] = o[d] * inv;
}

// ---------------- LayerNorm over 1024, in-place on g_mlp ----------------
__global__ void __launch_bounds__(256) layernorm_kernel(const float* __restrict__ ln_w,
                                                        const float* __restrict__ ln_b)
{
    int bl = blockIdx.x, tid = threadIdx.x;
    float4 v = *(const float4*)(g_mlp + (size_t)bl * MLPH + tid * 4);
    float s = v.x + v.y + v.z + v.w;
    float s2 = v.x * v.x + v.y * v.y + v.z * v.z + v.w * v.w;

    __shared__ float shs[8], shs2[8];
    int lane = tid & 31, w = tid >> 5;
#pragma unroll
    for (int o = 16; o; o >>= 1) {
        s += __shfl_xor_sync(0xffffffffu, s, o);
        s2 += __shfl_xor_sync(0xffffffffu, s2, o);
    }
    if (lane == 0) { shs[w] = s; shs2[w] = s2; }
    __syncthreads();
    if (w == 0) {
        float a = (lane < 8) ? shs[lane] : 0.f;
        float b2 = (lane < 8) ? shs2[lane] : 0.f;
#pragma unroll
        for (int o = 4; o; o >>= 1) {
            a += __shfl_xor_sync(0xffffffffu, a, o);
            b2 += __shfl_xor_sync(0xffffffffu, b2, o);
        }
        if (lane == 0) { shs[0] = a; shs2[0] = b2; }
    }
    __syncthreads();
    float mu = shs[0] * (1.f / MLPH);
    float var = shs2[0] * (1.f / MLPH) - mu * mu;
    float inv = rsqrtf(var + 1e-5f);

    float4 wv = *(const float4*)(ln_w + tid * 4);
    float4 bv = *(const float4*)(ln_b + tid * 4);
    float4 r;
    r.x = (v.x - mu) * inv * wv.x + bv.x;
    r.y = (v.y - mu) * inv * wv.y + bv.y;
    r.z = (v.z - mu) * inv * wv.z + bv.z;
    r.w = (v.w - mu) * inv * wv.w + bv.w;
    *(float4*)(g_mlp + (size_t)bl * MLPH + tid * 4) = r;
}

// ---------------- mean-pool over t + classification head ----------------
__global__ void __launch_bounds__(256) pool_head_kernel(const float* __restrict__ head_w,
                                                        const float* __restrict__ head_b,
                                                        float* __restrict__ out)
{
    int b = blockIdx.x;
    int d = threadIdx.x;
    float s = 0.f;
#pragma unroll 8
    for (int t = 0; t < LSEQ; t++)
        s += g_h2[((size_t)(b * LSEQ + t)) * DMODEL + d];
    __shared__ float pooled[DMODEL];
    pooled[d] = s * (1.f / LSEQ);
    __syncthreads();
    if (d < 2) {
        float accv = head_b[d];
        for (int j = 0; j < DMODEL; j++) accv += pooled[j] * head_w[d * DMODEL + j];
        out[b * 2 + d] = accv;
    }
}

// ---------------- host launcher ----------------
extern "C" void kernel_launch(void* const* d_in, const int* in_sizes, int n_in,
                              void* d_out, int out_size)
{
    (void)in_sizes; (void)n_in; (void)out_size;
    const float* x         = (const float*)d_in[0];
    const float* context   = (const float*)d_in[1];
    const float* in_proj_w = (const float*)d_in[2];
    const float* conv_w    = (const float*)d_in[3];
    const float* conv_b    = (const float*)d_in[4];
    const float* dt_bias   = (const float*)d_in[5];
    const float* A_log     = (const float*)d_in[6];
    const float* D_param   = (const float*)d_in[7];
    const float* norm_w    = (const float*)d_in[8];
    const float* out_proj_w= (const float*)d_in[9];
    const float* wq        = (const float*)d_in[10];
    const float* wk        = (const float*)d_in[11];
    const float* wv        = (const float*)d_in[12];
    const float* wo        = (const float*)d_in[13];
    const float* wo_b      = (const float*)d_in[14];
    const float* w1        = (const float*)d_in[15];
    const float* b1        = (const float*)d_in[16];
    const float* ln_w      = (const float*)d_in[17];
    const float* ln_b      = (const float*)d_in[18];
    const float* w2        = (const float*)d_in[19];
    const float* b2        = (const float*)d_in[20];
    const float* head_w    = (const float*)d_in[21];
    const float* head_b    = (const float*)d_in[22];
    float* out = (float*)d_out;

    float *p_zx, *p_y, *p_hres, *p_q, *p_k, *p_v, *p_o, *p_ob, *p_mlp, *p_h2;
    cudaGetSymbolAddress((void**)&p_zx,   g_zxbcdt);
    cudaGetSymbolAddress((void**)&p_y,    g_y);
    cudaGetSymbolAddress((void**)&p_hres, g_hres);
    cudaGetSymbolAddress((void**)&p_q,    g_q);
    cudaGetSymbolAddress((void**)&p_k,    g_k);
    cudaGetSymbolAddress((void**)&p_v,    g_v);
    cudaGetSymbolAddress((void**)&p_o,    g_o);
    cudaGetSymbolAddress((void**)&p_ob,   g_ob);
    cudaGetSymbolAddress((void**)&p_mlp,  g_mlp);
    cudaGetSymbolAddress((void**)&p_h2,   g_h2);

    // 1) in_proj: zxbcdt = x @ in_proj_w^T    [4096 x 1288]
    gemm_kernel<EPI_NONE><<<dim3((DINPROJ + 63) / 64, M4 / 64), 256>>>(
        x, in_proj_w, nullptr, nullptr, p_zx, M4, DINPROJ, DMODEL);
    // 2) causal conv + SiLU; dt = softplus(.+bias); dA = exp(-exp(A_log)*dt)
    conv_dt_kernel<<<M4, CONVDIM>>>(conv_w, conv_b, dt_bias, A_log);
    // 3) selective scan -> g_y
    scan_kernel<<<256, 128>>>();
    // 4) gating + RMSNorm (in-place on g_y)
    gate_rms_kernel<<<M4, DINNER>>>(D_param, norm_w);
    // 5) out_proj + residual with x -> hres
    gemm_kernel<EPI_RES><<<dim3(DMODEL / 64, M4 / 64), 256>>>(
        p_y, out_proj_w, nullptr, x, p_hres, M4, DMODEL, DINNER);
    // 6) q, k, v projections
    gemm_kernel<EPI_NONE><<<dim3(DMODEL / 64, M4 / 64), 256>>>(
        p_hres, wq, nullptr, nullptr, p_q, M4, DMODEL, DMODEL);
    gemm_kernel<EPI_NONE><<<dim3(DMODEL / 64, M4 / 64), 256>>>(
        context, wk, nullptr, nullptr, p_k, M4, DMODEL, DMODEL);
    gemm_kernel<EPI_NONE><<<dim3(DMODEL / 64, M4 / 64), 256>>>(
        context, wv, nullptr, nullptr, p_v, M4, DMODEL, DMODEL);
    // 7) attention -> g_o
    attn_kernel<<<dim3(LSEQ / 128, NHEADS, BBATCH), 128>>>();
    // 8) out proj + bias -> g_ob
    gemm_kernel<EPI_BIAS><<<dim3(DMODEL / 64, M4 / 64), 256>>>(
        p_o, wo, wo_b, nullptr, p_ob, M4, DMODEL, DMODEL);
    // 9) MLP fc1 + bias + GELU -> g_mlp
    gemm_kernel<EPI_BIAS_GELU><<<dim3(MLPH / 64, M4 / 64), 256>>>(
        p_ob, w1, b1, nullptr, p_mlp, M4, MLPH, DMODEL);
    // 10) LayerNorm (in-place)
    layernorm_kernel<<<M4, 256>>>(ln_w, ln_b);
    // 11) MLP fc2 + bias -> g_h2
    gemm_kernel<EPI_BIAS><<<dim3(DMODEL / 64, M4 / 64), 256>>>(
        p_mlp, w2, b2, nullptr, p_h2, M4, DMODEL, MLPH);
    // 12) mean-pool + head -> out (2x2)
    pool_head_kernel<<<BBATCH, DMODEL>>>(head_w, head_b, out);
}

// round 4
// speedup vs baseline: 1.3225x; 1.3225x over previous
#include <cuda_runtime.h>
#include <cuda_bf16.h>
#include <math.h>

// ---------------- problem constants ----------------
#define BBATCH 2
#define LSEQ 2048
#define DMODEL 256
#define DINNER 512
#define DSTATE 128
#define NHEADS 8
#define HEADDIM 64
#define CONVDIM 768          // DINNER + 2*DSTATE
#define DINPROJ 1288         // 2*DINNER + 2*DSTATE + NHEADS
#define AHD 32               // attention head dim
#define MLPH 1024
#define M4 (BBATCH * LSEQ)   // 4096 rows

// ---------------- scratch buffers ----------------
__device__ float g_zxbcdt[(size_t)M4 * DINPROJ];
__device__ float g_xBC[(size_t)M4 * CONVDIM];
__device__ float g_dt[M4 * NHEADS];
__device__ float g_dA[M4 * NHEADS];
__device__ float g_y[(size_t)M4 * DINNER];
__device__ float g_hres[(size_t)M4 * DMODEL];
__device__ float g_q[(size_t)M4 * DMODEL];
__device__ float g_k[(size_t)M4 * DMODEL];
__device__ float g_v[(size_t)M4 * DMODEL];
__device__ float g_o[(size_t)M4 * DMODEL];
__device__ float g_ob[(size_t)M4 * DMODEL];
__device__ float g_mlp[(size_t)M4 * MLPH];
__device__ float g_h2[(size_t)M4 * DMODEL];

// ---------------- helpers ----------------
__device__ __forceinline__ float to_tf32(float x) {
    unsigned r;
    asm("cvt.rna.tf32.f32 %0, %1;" : "=r"(r) : "f"(x));
    return __uint_as_float(r);
}

__device__ __forceinline__ void mma_tf32(float c[4], const unsigned a[4],
                                         unsigned b0, unsigned b1) {
    asm volatile(
        "mma.sync.aligned.m16n8k8.row.col.f32.tf32.tf32.f32 "
        "{%0,%1,%2,%3},{%4,%5,%6,%7},{%8,%9},{%0,%1,%2,%3};"
        : "+f"(c[0]), "+f"(c[1]), "+f"(c[2]), "+f"(c[3])
        : "r"(a[0]), "r"(a[1]), "r"(a[2]), "r"(a[3]), "r"(b0), "r"(b1));
}

__device__ __forceinline__ void mma_bf16(float c[4], unsigned a0, unsigned a1,
                                         unsigned a2, unsigned a3,
                                         unsigned b0, unsigned b1) {
    asm volatile(
        "mma.sync.aligned.m16n8k16.row.col.f32.bf16.bf16.f32 "
        "{%0,%1,%2,%3},{%4,%5,%6,%7},{%8,%9},{%0,%1,%2,%3};"
        : "+f"(c[0]), "+f"(c[1]), "+f"(c[2]), "+f"(c[3])
        : "r"(a0), "r"(a1), "r"(a2), "r"(a3), "r"(b0), "r"(b1));
}

// ---------------- tf32 GEMM with split-precision weights ----------------
// C = A[MxK] @ W[NxK]^T ; W represented as tf32 hi + lo so the *systematic*
// weight-rounding error (which survives the final mean-pool) is ~1e-6.
enum { EPI_NONE = 0, EPI_BIAS = 1, EPI_BIAS_GELU = 2, EPI_RES = 3 };

template <int EPI>
__global__ void __launch_bounds__(128)
gemm_tf32_kernel(const float* __restrict__ A, const float* __restrict__ W,
                 const float* __restrict__ bias, const float* __restrict__ res,
                 float* __restrict__ C, int M, int N, int K)
{
    __shared__ float As[64][20];
    __shared__ float Wh[64][20];
    __shared__ float Wl[64][20];

    const int m0 = blockIdx.y * 64, n0 = blockIdx.x * 64;
    const int tid = threadIdx.x;
    const int w = tid >> 5, lane = tid & 31;
    const int qd = lane & 3, g = lane >> 2;
    const int wm = (w & 1) * 32, wn = (w >> 1) * 32;
    const int lrow = tid >> 2;        // 0..31
    const int lc4 = (tid & 3) * 4;    // 0,4,8,12

    float c[2][4][4];
#pragma unroll
    for (int mt = 0; mt < 2; mt++)
#pragma unroll
        for (int nt = 0; nt < 4; nt++)
#pragma unroll
            for (int i = 0; i < 4; i++) c[mt][nt][i] = 0.f;

    for (int k0 = 0; k0 < K; k0 += 16) {
#pragma unroll
        for (int half = 0; half < 2; half++) {
            int row = lrow + half * 32;
            float4 av = *(const float4*)(A + (size_t)(m0 + row) * K + k0 + lc4);
            float4 ta;
            ta.x = to_tf32(av.x); ta.y = to_tf32(av.y);
            ta.z = to_tf32(av.z); ta.w = to_tf32(av.w);
            *(float4*)&As[row][lc4] = ta;

            int wr = n0 + row;
            float4 wv = make_float4(0.f, 0.f, 0.f, 0.f);
            if (wr < N) wv = *(const float4*)(W + (size_t)wr * K + k0 + lc4);
            float4 th, tl;
            th.x = to_tf32(wv.x); tl.x = to_tf32(wv.x - th.x);
            th.y = to_tf32(wv.y); tl.y = to_tf32(wv.y - th.y);
            th.z = to_tf32(wv.z); tl.z = to_tf32(wv.z - th.z);
            th.w = to_tf32(wv.w); tl.w = to_tf32(wv.w - th.w);
            *(float4*)&Wh[row][lc4] = th;
            *(float4*)&Wl[row][lc4] = tl;
        }
        __syncthreads();
#pragma unroll
        for (int ks = 0; ks < 2; ks++) {
            unsigned a[2][4], bh[4][2], bl[4][2];
#pragma unroll
            for (int mt = 0; mt < 2; mt++) {
                int r = wm + mt * 16;
                a[mt][0] = __float_as_uint(As[r + g][8 * ks + qd]);
                a[mt][1] = __float_as_uint(As[r + g + 8][8 * ks + qd]);
                a[mt][2] = __float_as_uint(As[r + g][8 * ks + qd + 4]);
                a[mt][3] = __float_as_uint(As[r + g + 8][8 * ks + qd + 4]);
            }
#pragma unroll
            for (int nt = 0; nt < 4; nt++) {
                int cn = wn + nt * 8 + g;
                bh[nt][0] = __float_as_uint(Wh[cn][8 * ks + qd]);
                bh[nt][1] = __float_as_uint(Wh[cn][8 * ks + qd + 4]);
                bl[nt][0] = __float_as_uint(Wl[cn][8 * ks + qd]);
                bl[nt][1] = __float_as_uint(Wl[cn][8 * ks + qd + 4]);
            }
#pragma unroll
            for (int mt = 0; mt < 2; mt++)
#pragma unroll
                for (int nt = 0; nt < 4; nt++) {
                    mma_tf32(c[mt][nt], a[mt], bh[nt][0], bh[nt][1]);
                    mma_tf32(c[mt][nt], a[mt], bl[nt][0], bl[nt][1]);
                }
        }
        __syncthreads();
    }

#pragma unroll
    for (int mt = 0; mt < 2; mt++) {
#pragma unroll
        for (int nt = 0; nt < 4; nt++) {
            int row = m0 + wm + mt * 16 + g;
            int col = n0 + wn + nt * 8 + 2 * qd;
            if (col >= N) continue;
            float v0 = c[mt][nt][0], v1 = c[mt][nt][1];
            float v2 = c[mt][nt][2], v3 = c[mt][nt][3];
            if (EPI == EPI_BIAS || EPI == EPI_BIAS_GELU) {
                float2 bv = *(const float2*)(bias + col);
                v0 += bv.x; v1 += bv.y; v2 += bv.x; v3 += bv.y;
            }
            if (EPI == EPI_BIAS_GELU) {
                v0 = 0.5f * v0 * (1.f + erff(v0 * 0.70710678118f));
                v1 = 0.5f * v1 * (1.f + erff(v1 * 0.70710678118f));
                v2 = 0.5f * v2 * (1.f + erff(v2 * 0.70710678118f));
                v3 = 0.5f * v3 * (1.f + erff(v3 * 0.70710678118f));
            }
            if (EPI == EPI_RES) {
                float2 r0 = *(const float2*)(res + (size_t)row * N + col);
                float2 r1 = *(const float2*)(res + (size_t)(row + 8) * N + col);
                v0 += r0.x; v1 += r0.y; v2 += r1.x; v3 += r1.y;
            }
            float2 o0 = make_float2(v0, v1);
            float2 o1 = make_float2(v2, v3);
            *(float2*)(C + (size_t)row * N + col) = o0;
            *(float2*)(C + (size_t)(row + 8) * N + col) = o1;
        }
    }
}

// ---------------- conv1d (causal, 4 taps) + SiLU, plus dt/dA ----------------
__global__ void conv_dt_kernel(const float* __restrict__ conv_w,
                               const float* __restrict__ conv_b,
                               const float* __restrict__ dt_bias,
                               const float* __restrict__ A_log)
{
    int bl = blockIdx.x;
    int c = threadIdx.x;
    int b = bl / LSEQ, l = bl % LSEQ;

    float accv = conv_b[c];
#pragma unroll
    for (int k = 0; k < 4; k++) {
        int ls = l - 3 + k;
        if (ls >= 0)
            accv += conv_w[c * 4 + k] *
                    g_zxbcdt[(size_t)(b * LSEQ + ls) * DINPROJ + DINNER + c];
    }
    float s = accv / (1.f + expf(-accv));
    g_xBC[(size_t)bl * CONVDIM + c] = s;

    if (c < NHEADS) {
        float v = g_zxbcdt[(size_t)bl * DINPROJ + (DINNER + CONVDIM) + c] + dt_bias[c];
        float dt = (v > 20.f) ? v : log1pf(expf(v));
        g_dt[bl * NHEADS + c] = dt;
        g_dA[bl * NHEADS + c] = expf(dt * -expf(A_log[c]));
    }
}

// ---------------- selective scan ----------------
__global__ void __launch_bounds__(128) scan_kernel()
{
    int bidx = blockIdx.x;
    int pg = bidx & 15;
    int h = (bidx >> 4) & 7;
    int b = bidx >> 7;
    int warp = threadIdx.x >> 5;
    int lane = threadIdx.x & 31;
    int p = pg * 4 + warp;
    int n0 = lane * 4;

    float h0 = 0.f, h1 = 0.f, h2 = 0.f, h3 = 0.f;
    const float* xbase = g_xBC + (size_t)b * LSEQ * CONVDIM;
    const float* dtb = g_dt + (size_t)b * LSEQ * NHEADS + h;
    const float* dab = g_dA + (size_t)b * LSEQ * NHEADS + h;
    float* yout = g_y + (size_t)b * LSEQ * DINNER + h * HEADDIM + p;
    const int coff = h * HEADDIM + p;

    for (int t = 0; t < LSEQ; t++) {
        const float* row = xbase + (size_t)t * CONVDIM;
        float dA = dab[t * NHEADS];
        float dt = dtb[t * NHEADS];
        float xv = row[coff];
        float4 Bv = *(const float4*)(row + DINNER + n0);
        float4 Cv = *(const float4*)(row + DINNER + DSTATE + n0);
        float dtx = dt * xv;
        h0 = h0 * dA + dtx * Bv.x;
        h1 = h1 * dA + dtx * Bv.y;
        h2 = h2 * dA + dtx * Bv.z;
        h3 = h3 * dA + dtx * Bv.w;
        float accr = h0 * Cv.x + h1 * Cv.y + h2 * Cv.z + h3 * Cv.w;
#pragma unroll
        for (int o = 16; o; o >>= 1) accr += __shfl_xor_sync(0xffffffffu, accr, o);
        if (lane == 0) yout[(size_t)t * DINNER] = accr;
    }
}

// ---------------- gate + RMSNorm ----------------
__global__ void __launch_bounds__(512) gate_rms_kernel(const float* __restrict__ D_param,
                                                       const float* __restrict__ norm_w)
{
    int bl = blockIdx.x;
    int d = threadIdx.x;
    float y = g_y[(size_t)bl * DINNER + d] +
              D_param[d >> 6] * g_xBC[(size_t)bl * CONVDIM + d];
    float z = g_zxbcdt[(size_t)bl * DINPROJ + d];
    float g = y * (z / (1.f + expf(-z)));

    __shared__ float sh[16];
    float s = g * g;
    int lane = d & 31, w = d >> 5;
#pragma unroll
    for (int o = 16; o; o >>= 1) s += __shfl_xor_sync(0xffffffffu, s, o);
    if (lane == 0) sh[w] = s;
    __syncthreads();
    if (w == 0) {
        float v = (lane < 16) ? sh[lane] : 0.f;
#pragma unroll
        for (int o = 16; o; o >>= 1) v += __shfl_xor_sync(0xffffffffu, v, o);
        if (lane == 0) sh[0] = v;
    }
    __syncthreads();
    float scale = rsqrtf(sh[0] * (1.f / DINNER) + 1e-5f);
    g_y[(size_t)bl * DINNER + d] = g * scale * norm_w[d];
}

// ---------------- flash attention: tf32 QK^T, split-bf16 PV ----------------
__global__ void __launch_bounds__(128) attn_mma_kernel()
{
    __shared__ float Qs[64][40];
    __shared__ float Ks[64][40];
    __shared__ unsigned Vh[32][40];     // bf16x2 hi (pairs along key dim)
    __shared__ unsigned Vl[32][40];     // bf16x2 lo

    const int q0 = blockIdx.x * 64;
    const int h = blockIdx.y;
    const int b = blockIdx.z;
    const int tid = threadIdx.x;
    const int w = tid >> 5, lane = tid & 31;
    const int qd = lane & 3, g = lane >> 2;
    const float scale = 0.1767766953f;  // 1/sqrt(32)

    const size_t base = (size_t)b * LSEQ * DMODEL + h * AHD;

    // stage Q (scaled, tf32)
#pragma unroll
    for (int i = 0; i < 4; i++) {
        int e = tid + i * 128;
        int row = e >> 3, c4 = (e & 7) * 4;
        float4 v = *(const float4*)(g_q + base + (size_t)(q0 + row) * DMODEL + c4);
        float4 t;
        t.x = to_tf32(v.x * scale); t.y = to_tf32(v.y * scale);
        t.z = to_tf32(v.z * scale); t.w = to_tf32(v.w * scale);
        *(float4*)&Qs[row][c4] = t;
    }
    __syncthreads();

    unsigned qa[4][4];
#pragma unroll
    for (int ks = 0; ks < 4; ks++) {
        int r = w * 16;
        qa[ks][0] = __float_as_uint(Qs[r + g][8 * ks + qd]);
        qa[ks][1] = __float_as_uint(Qs[r + g + 8][8 * ks + qd]);
        qa[ks][2] = __float_as_uint(Qs[r + g][8 * ks + qd + 4]);
        qa[ks][3] = __float_as_uint(Qs[r + g + 8][8 * ks + qd + 4]);
    }

    float m0 = -1e30f, m1 = -1e30f, l0 = 0.f, l1 = 0.f;
    float o[4][4];
#pragma unroll
    for (int nt = 0; nt < 4; nt++)
#pragma unroll
        for (int i = 0; i < 4; i++) o[nt][i] = 0.f;

    for (int kt = 0; kt < LSEQ / 64; kt++) {
        __syncthreads();
        const size_t kb = base + (size_t)(kt * 64) * DMODEL;
        // K tile (tf32)
#pragma unroll
        for (int i = 0; i < 4; i++) {
            int e = tid + i * 128;
            int row = e >> 3, c4 = (e & 7) * 4;
            float4 v = *(const float4*)(g_k + kb + (size_t)row * DMODEL + c4);
            float4 t;
            t.x = to_tf32(v.x); t.y = to_tf32(v.y);
            t.z = to_tf32(v.z); t.w = to_tf32(v.w);
            *(float4*)&Ks[row][c4] = t;
        }
        // V tile: split bf16 hi + lo (V rounding is common-mode across queries
        // and would survive the pool — split kills the systematic part)
#pragma unroll
        for (int i = 0; i < 8; i++) {
            int e = tid + i * 128;
            int kp = e >> 5, d = e & 31;
            float v0 = g_v[kb + (size_t)(2 * kp) * DMODEL + d];
            float v1 = g_v[kb + (size_t)(2 * kp + 1) * DMODEL + d];
            __nv_bfloat16 h0b = __float2bfloat16_rn(v0);
            __nv_bfloat16 h1b = __float2bfloat16_rn(v1);
            __nv_bfloat16 l0b = __float2bfloat16_rn(v0 - __bfloat162float(h0b));
            __nv_bfloat16 l1b = __float2bfloat16_rn(v1 - __bfloat162float(h1b));
            __nv_bfloat162 hh = __halves2bfloat162(h0b, h1b);
            __nv_bfloat162 ll = __halves2bfloat162(l0b, l1b);
            Vh[kp][d] = *(unsigned*)&hh;
            Vl[kp][d] = *(unsigned*)&ll;
        }
        __syncthreads();

        // S = Q @ K^T
        float s[8][4];
#pragma unroll
        for (int nt = 0; nt < 8; nt++)
#pragma unroll
            for (int i = 0; i < 4; i++) s[nt][i] = 0.f;
#pragma unroll
        for (int ks = 0; ks < 4; ks++) {
#pragma unroll
            for (int nt = 0; nt < 8; nt++) {
                unsigned b0 = __float_as_uint(Ks[nt * 8 + g][8 * ks + qd]);
                unsigned b1 = __float_as_uint(Ks[nt * 8 + g][8 * ks + qd + 4]);
                mma_tf32(s[nt], qa[ks], b0, b1);
            }
        }

        // online softmax (row spread over quad lanes; m reduced over quad)
        float r0 = -1e30f, r1 = -1e30f;
#pragma unroll
        for (int nt = 0; nt < 8; nt++) {
            r0 = fmaxf(r0, fmaxf(s[nt][0], s[nt][1]));
            r1 = fmaxf(r1, fmaxf(s[nt][2], s[nt][3]));
        }
        r0 = fmaxf(r0, __shfl_xor_sync(0xffffffffu, r0, 1));
        r0 = fmaxf(r0, __shfl_xor_sync(0xffffffffu, r0, 2));
        r1 = fmaxf(r1, __shfl_xor_sync(0xffffffffu, r1, 1));
        r1 = fmaxf(r1, __shfl_xor_sync(0xffffffffu, r1, 2));
        float nm0 = fmaxf(m0, r0), nm1 = fmaxf(m1, r1);
        float cf0 = __expf(m0 - nm0), cf1 = __expf(m1 - nm1);
        m0 = nm0; m1 = nm1;
        l0 *= cf0; l1 *= cf1;
#pragma unroll
        for (int nt = 0; nt < 4; nt++) {
            o[nt][0] *= cf0; o[nt][1] *= cf0;
            o[nt][2] *= cf1; o[nt][3] *= cf1;
        }

        unsigned plo[8], phi[8];
#pragma unroll
        for (int nt = 0; nt < 8; nt++) {
            float p0 = __expf(s[nt][0] - m0);
            float p1 = __expf(s[nt][1] - m0);
            float p2 = __expf(s[nt][2] - m1);
            float p3 = __expf(s[nt][3] - m1);
            l0 += p0 + p1;
            l1 += p2 + p3;
            __nv_bfloat162 lo = __floats2bfloat162_rn(p0, p1);
            __nv_bfloat162 hi = __floats2bfloat162_rn(p2, p3);
            plo[nt] = *(unsigned*)&lo;
            phi[nt] = *(unsigned*)&hi;
        }

        // O += P @ (V_hi + V_lo)
#pragma unroll
        for (int kk = 0; kk < 4; kk++) {
            unsigned a0 = plo[2 * kk], a1 = phi[2 * kk];
            unsigned a2 = plo[2 * kk + 1], a3 = phi[2 * kk + 1];
#pragma unroll
            for (int nt = 0; nt < 4; nt++) {
                unsigned bh0 = Vh[kk * 8 + qd][nt * 8 + g];
                unsigned bh1 = Vh[kk * 8 + qd + 4][nt * 8 + g];
                mma_bf16(o[nt], a0, a1, a2, a3, bh0, bh1);
                unsigned bl0 = Vl[kk * 8 + qd][nt * 8 + g];
                unsigned bl1 = Vl[kk * 8 + qd + 4][nt * 8 + g];
                mma_bf16(o[nt], a0, a1, a2, a3, bl0, bl1);
            }
        }
    }

    // reduce l over the quad (4 lanes share one query row)
    l0 += __shfl_xor_sync(0xffffffffu, l0, 1);
    l0 += __shfl_xor_sync(0xffffffffu, l0, 2);
    l1 += __shfl_xor_sync(0xffffffffu, l1, 1);
    l1 += __shfl_xor_sync(0xffffffffu, l1, 2);

    float inv0 = 1.f / l0, inv1 = 1.f / l1;
    int row = q0 + w * 16 + g;
#pragma unroll
    for (int nt = 0; nt < 4; nt++) {
        int col = h * AHD + nt * 8 + 2 * qd;
        float2 r0v = make_float2(o[nt][0] * inv0, o[nt][1] * inv0);
        float2 r1v = make_float2(o[nt][2] * inv1, o[nt][3] * inv1);
        *(float2*)(g_o + (size_t)(b * LSEQ + row) * DMODEL + col) = r0v;
        *(float2*)(g_o + (size_t)(b * LSEQ + row + 8) * DMODEL + col) = r1v;
    }
}

// ---------------- LayerNorm over 1024 ----------------
__global__ void __launch_bounds__(256) layernorm_kernel(const float* __restrict__ ln_w,
                                                        const float* __restrict__ ln_b)
{
    int bl = blockIdx.x, tid = threadIdx.x;
    float4 v = *(const float4*)(g_mlp + (size_t)bl * MLPH + tid * 4);
    float s = v.x + v.y + v.z + v.w;
    float s2 = v.x * v.x + v.y * v.y + v.z * v.z + v.w * v.w;

    __shared__ float shs[8], shs2[8];
    int lane = tid & 31, w = tid >> 5;
#pragma unroll
    for (int o = 16; o; o >>= 1) {
        s += __shfl_xor_sync(0xffffffffu, s, o);
        s2 += __shfl_xor_sync(0xffffffffu, s2, o);
    }
    if (lane == 0) { shs[w] = s; shs2[w] = s2; }
    __syncthreads();
    if (w == 0) {
        float a = (lane < 8) ? shs[lane] : 0.f;
        float b2 = (lane < 8) ? shs2[lane] : 0.f;
#pragma unroll
        for (int o = 4; o; o >>= 1) {
            a += __shfl_xor_sync(0xffffffffu, a, o);
            b2 += __shfl_xor_sync(0xffffffffu, b2, o);
        }
        if (lane == 0) { shs[0] = a; shs2[0] = b2; }
    }
    __syncthreads();
    float mu = shs[0] * (1.f / MLPH);
    float var = shs2[0] * (1.f / MLPH) - mu * mu;
    float inv = rsqrtf(var + 1e-5f);

    float4 wv = *(const float4*)(ln_w + tid * 4);
    float4 bv = *(const float4*)(ln_b + tid * 4);
    float4 r;
    r.x = (v.x - mu) * inv * wv.x + bv.x;
    r.y = (v.y - mu) * inv * wv.y + bv.y;
    r.z = (v.z - mu) * inv * wv.z + bv.z;
    r.w = (v.w - mu) * inv * wv.w + bv.w;
    *(float4*)(g_mlp + (size_t)bl * MLPH + tid * 4) = r;
}

// ---------------- mean-pool + head ----------------
__global__ void __launch_bounds__(256) pool_head_kernel(const float* __restrict__ head_w,
                                                        const float* __restrict__ head_b,
                                                        float* __restrict__ out)
{
    int b = blockIdx.x;
    int d = threadIdx.x;
    float s = 0.f;
#pragma unroll 8
    for (int t = 0; t < LSEQ; t++)
        s += g_h2[((size_t)(b * LSEQ + t)) * DMODEL + d];
    __shared__ float pooled[DMODEL];
    pooled[d] = s * (1.f / LSEQ);
    __syncthreads();
    if (d < 2) {
        float accv = head_b[d];
        for (int j = 0; j < DMODEL; j++) accv += pooled[j] * head_w[d * DMODEL + j];
        out[b * 2 + d] = accv;
    }
}

// ---------------- host launcher ----------------
extern "C" void kernel_launch(void* const* d_in, const int* in_sizes, int n_in,
                              void* d_out, int out_size)
{
    (void)in_sizes; (void)n_in; (void)out_size;
    const float* x         = (const float*)d_in[0];
    const float* context   = (const float*)d_in[1];
    const float* in_proj_w = (const float*)d_in[2];
    const float* conv_w    = (const float*)d_in[3];
    const float* conv_b    = (const float*)d_in[4];
    const float* dt_bias   = (const float*)d_in[5];
    const float* A_log     = (const float*)d_in[6];
    const float* D_param   = (const float*)d_in[7];
    const float* norm_w    = (const float*)d_in[8];
    const float* out_proj_w= (const float*)d_in[9];
    const float* wq        = (const float*)d_in[10];
    const float* wk        = (const float*)d_in[11];
    const float* wv        = (const float*)d_in[12];
    const float* wo        = (const float*)d_in[13];
    const float* wo_b      = (const float*)d_in[14];
    const float* w1        = (const float*)d_in[15];
    const float* b1        = (const float*)d_in[16];
    const float* ln_w      = (const float*)d_in[17];
    const float* ln_b      = (const float*)d_in[18];
    const float* w2        = (const float*)d_in[19];
    const float* b2        = (const float*)d_in[20];
    const float* head_w    = (const float*)d_in[21];
    const float* head_b    = (const float*)d_in[22];
    float* out = (float*)d_out;

    float *p_zx, *p_y, *p_hres, *p_q, *p_k, *p_v, *p_o, *p_ob, *p_mlp, *p_h2;
    cudaGetSymbolAddress((void**)&p_zx,   g_zxbcdt);
    cudaGetSymbolAddress((void**)&p_y,    g_y);
    cudaGetSymbolAddress((void**)&p_hres, g_hres);
    cudaGetSymbolAddress((void**)&p_q,    g_q);
    cudaGetSymbolAddress((void**)&p_k,    g_k);
    cudaGetSymbolAddress((void**)&p_v,    g_v);
    cudaGetSymbolAddress((void**)&p_o,    g_o);
    cudaGetSymbolAddress((void**)&p_ob,   g_ob);
    cudaGetSymbolAddress((void**)&p_mlp,  g_mlp);
    cudaGetSymbolAddress((void**)&p_h2,   g_h2);

    // 1) in_proj
    gemm_tf32_kernel<EPI_NONE><<<dim3((DINPROJ + 63) / 64, M4 / 64), 128>>>(
        x, in_proj_w, nullptr, nullptr, p_zx, M4, DINPROJ, DMODEL);
    // 2) conv + dt/dA
    conv_dt_kernel<<<M4, CONVDIM>>>(conv_w, conv_b, dt_bias, A_log);
    // 3) selective scan
    scan_kernel<<<256, 128>>>();
    // 4) gate + RMSNorm
    gate_rms_kernel<<<M4, DINNER>>>(D_param, norm_w);
    // 5) out_proj + residual
    gemm_tf32_kernel<EPI_RES><<<dim3(DMODEL / 64, M4 / 64), 128>>>(
        p_y, out_proj_w, nullptr, x, p_hres, M4, DMODEL, DINNER);
    // 6) q, k, v
    gemm_tf32_kernel<EPI_NONE><<<dim3(DMODEL / 64, M4 / 64), 128>>>(
        p_hres, wq, nullptr, nullptr, p_q, M4, DMODEL, DMODEL);
    gemm_tf32_kernel<EPI_NONE><<<dim3(DMODEL / 64, M4 / 64), 128>>>(
        context, wk, nullptr, nullptr, p_k, M4, DMODEL, DMODEL);
    gemm_tf32_kernel<EPI_NONE><<<dim3(DMODEL / 64, M4 / 64), 128>>>(
        context, wv, nullptr, nullptr, p_v, M4, DMODEL, DMODEL);
    // 7) attention
    attn_mma_kernel<<<dim3(LSEQ / 64, NHEADS, BBATCH), 128>>>();
    // 8) attn out proj
    gemm_tf32_kernel<EPI_BIAS><<<dim3(DMODEL / 64, M4 / 64), 128>>>(
        p_o, wo, wo_b, nullptr, p_ob, M4, DMODEL, DMODEL);
    // 9) MLP fc1 + GELU
    gemm_tf32_kernel<EPI_BIAS_GELU><<<dim3(MLPH / 64, M4 / 64), 128>>>(
        p_ob, w1, b1, nullptr, p_mlp, M4, MLPH, DMODEL);
    // 10) LayerNorm
    layernorm_kernel<<<M4, 256>>>(ln_w, ln_b);
    // 11) MLP fc2
    gemm_tf32_kernel<EPI_BIAS><<<dim3(DMODEL / 64, M4 / 64), 128>>>(
        p_mlp, w2, b2, nullptr, p_h2, M4, DMODEL, MLPH);
    // 12) pool + head
    pool_head_kernel<<<BBATCH, DMODEL>>>(head_w, head_b, out);
}

// round 5
// speedup vs baseline: 2.1681x; 1.6393x over previous
#include <cuda_runtime.h>
#include <cuda_bf16.h>
#include <math.h>

// ---------------- problem constants ----------------
#define BBATCH 2
#define LSEQ 2048
#define DMODEL 256
#define DINNER 512
#define DSTATE 128
#define NHEADS 8
#define HEADDIM 64
#define CONVDIM 768          // DINNER + 2*DSTATE
#define DINPROJ 1288         // 2*DINNER + 2*DSTATE + NHEADS
#define AHD 32               // attention head dim
#define MLPH 1024
#define M4 (BBATCH * LSEQ)   // 4096 rows
#define NCHUNK 32
#define CHUNK 64             // LSEQ / NCHUNK

// ---------------- scratch buffers ----------------
__device__ float g_zxbcdt[(size_t)M4 * DINPROJ];
__device__ float g_xBC[(size_t)M4 * CONVDIM];
__device__ float g_dt[M4 * NHEADS];
__device__ float g_dA[M4 * NHEADS];
__device__ float g_y[(size_t)M4 * DINNER];
__device__ float g_hres[(size_t)M4 * DMODEL];
__device__ float g_q[(size_t)M4 * DMODEL];
__device__ float g_k[(size_t)M4 * DMODEL];
__device__ float g_v[(size_t)M4 * DMODEL];
__device__ float g_o[(size_t)M4 * DMODEL];
__device__ float g_ob[(size_t)M4 * DMODEL];
__device__ float g_mlp[(size_t)M4 * MLPH];
__device__ float g_h2[(size_t)M4 * DMODEL];
// chunked-scan buffers
__device__ float g_state[(size_t)BBATCH * NHEADS * NCHUNK * HEADDIM * DSTATE];
__device__ float g_H0[(size_t)BBATCH * NHEADS * NCHUNK * HEADDIM * DSTATE];
__device__ float g_P[BBATCH * NHEADS * NCHUNK];
__device__ float g_cumA[BBATCH * NHEADS * LSEQ];

// ---------------- helpers ----------------
__device__ __forceinline__ float to_tf32(float x) {
    unsigned r;
    asm("cvt.rna.tf32.f32 %0, %1;" : "=r"(r) : "f"(x));
    return __uint_as_float(r);
}

__device__ __forceinline__ void mma_tf32(float c[4], const unsigned a[4],
                                         unsigned b0, unsigned b1) {
    asm volatile(
        "mma.sync.aligned.m16n8k8.row.col.f32.tf32.tf32.f32 "
        "{%0,%1,%2,%3},{%4,%5,%6,%7},{%8,%9},{%0,%1,%2,%3};"
        : "+f"(c[0]), "+f"(c[1]), "+f"(c[2]), "+f"(c[3])
        : "r"(a[0]), "r"(a[1]), "r"(a[2]), "r"(a[3]), "r"(b0), "r"(b1));
}

__device__ __forceinline__ void mma_bf16(float c[4], unsigned a0, unsigned a1,
                                         unsigned a2, unsigned a3,
                                         unsigned b0, unsigned b1) {
    asm volatile(
        "mma.sync.aligned.m16n8k16.row.col.f32.bf16.bf16.f32 "
        "{%0,%1,%2,%3},{%4,%5,%6,%7},{%8,%9},{%0,%1,%2,%3};"
        : "+f"(c[0]), "+f"(c[1]), "+f"(c[2]), "+f"(c[3])
        : "r"(a0), "r"(a1), "r"(a2), "r"(a3), "r"(b0), "r"(b1));
}

// fast erf (Abramowitz-Stegun 7.1.26, abs err < 1.5e-7)
__device__ __forceinline__ float fast_erf(float x) {
    float ax = fabsf(x);
    float t = __frcp_rn(1.f + 0.3275911f * ax);
    float p = 1.061405429f;
    p = p * t - 1.453152027f;
    p = p * t + 1.421413741f;
    p = p * t - 0.284496736f;
    p = p * t + 0.254829592f;
    float r = 1.f - p * t * __expf(-ax * ax);
    return copysignf(r, x);
}
__device__ __forceinline__ float gelu(float v) {
    return 0.5f * v * (1.f + fast_erf(v * 0.70710678118f));
}

// ---------------- tf32 GEMM (64x64 tile) with split-precision weights --------
enum { EPI_NONE = 0, EPI_BIAS = 1, EPI_BIAS_GELU = 2, EPI_RES = 3 };

template <int EPI>
__global__ void __launch_bounds__(128)
gemm_tf32_kernel(const float* __restrict__ A, const float* __restrict__ W,
                 const float* __restrict__ bias, const float* __restrict__ res,
                 float* __restrict__ C, int M, int N, int K)
{
    __shared__ float As[64][20];
    __shared__ float Wh[64][20];
    __shared__ float Wl[64][20];

    const int m0 = blockIdx.y * 64, n0 = blockIdx.x * 64;
    const int tid = threadIdx.x;
    const int w = tid >> 5, lane = tid & 31;
    const int qd = lane & 3, g = lane >> 2;
    const int wm = (w & 1) * 32, wn = (w >> 1) * 32;
    const int lrow = tid >> 2;        // 0..31
    const int lc4 = (tid & 3) * 4;    // 0,4,8,12

    float c[2][4][4];
#pragma unroll
    for (int mt = 0; mt < 2; mt++)
#pragma unroll
        for (int nt = 0; nt < 4; nt++)
#pragma unroll
            for (int i = 0; i < 4; i++) c[mt][nt][i] = 0.f;

    const float* Aptr0 = A + (size_t)(m0 + lrow) * K + lc4;
    const float* Aptr1 = A + (size_t)(m0 + lrow + 32) * K + lc4;
    const bool wv0 = (n0 + lrow) < N;
    const bool wv1 = (n0 + lrow + 32) < N;
    const float* Wptr0 = W + (size_t)(wv0 ? (n0 + lrow) : 0) * K + lc4;
    const float* Wptr1 = W + (size_t)(wv1 ? (n0 + lrow + 32) : 0) * K + lc4;

    // register prefetch
    float4 pa0 = *(const float4*)Aptr0;
    float4 pa1 = *(const float4*)Aptr1;
    float4 pw0 = wv0 ? *(const float4*)Wptr0 : make_float4(0.f, 0.f, 0.f, 0.f);
    float4 pw1 = wv1 ? *(const float4*)Wptr1 : make_float4(0.f, 0.f, 0.f, 0.f);

    for (int k0 = 0; k0 < K; k0 += 16) {
        // commit prefetched tile (convert in-flight)
        float4 t0, t1, th, tl;
        t0.x = to_tf32(pa0.x); t0.y = to_tf32(pa0.y); t0.z = to_tf32(pa0.z); t0.w = to_tf32(pa0.w);
        t1.x = to_tf32(pa1.x); t1.y = to_tf32(pa1.y); t1.z = to_tf32(pa1.z); t1.w = to_tf32(pa1.w);
        *(float4*)&As[lrow][lc4] = t0;
        *(float4*)&As[lrow + 32][lc4] = t1;
        th.x = to_tf32(pw0.x); tl.x = to_tf32(pw0.x - th.x);
        th.y = to_tf32(pw0.y); tl.y = to_tf32(pw0.y - th.y);
        th.z = to_tf32(pw0.z); tl.z = to_tf32(pw0.z - th.z);
        th.w = to_tf32(pw0.w); tl.w = to_tf32(pw0.w - th.w);
        *(float4*)&Wh[lrow][lc4] = th;
        *(float4*)&Wl[lrow][lc4] = tl;
        th.x = to_tf32(pw1.x); tl.x = to_tf32(pw1.x - th.x);
        th.y = to_tf32(pw1.y); tl.y = to_tf32(pw1.y - th.y);
        th.z = to_tf32(pw1.z); tl.z = to_tf32(pw1.z - th.z);
        th.w = to_tf32(pw1.w); tl.w = to_tf32(pw1.w - th.w);
        *(float4*)&Wh[lrow + 32][lc4] = th;
        *(float4*)&Wl[lrow + 32][lc4] = tl;
        __syncthreads();

        if (k0 + 16 < K) {
            pa0 = *(const float4*)(Aptr0 + k0 + 16);
            pa1 = *(const float4*)(Aptr1 + k0 + 16);
            pw0 = wv0 ? *(const float4*)(Wptr0 + k0 + 16) : make_float4(0.f, 0.f, 0.f, 0.f);
            pw1 = wv1 ? *(const float4*)(Wptr1 + k0 + 16) : make_float4(0.f, 0.f, 0.f, 0.f);
        }

#pragma unroll
        for (int ks = 0; ks < 2; ks++) {
            unsigned a[2][4], bh[4][2], bl[4][2];
#pragma unroll
            for (int mt = 0; mt < 2; mt++) {
                int r = wm + mt * 16;
                a[mt][0] = __float_as_uint(As[r + g][8 * ks + qd]);
                a[mt][1] = __float_as_uint(As[r + g + 8][8 * ks + qd]);
                a[mt][2] = __float_as_uint(As[r + g][8 * ks + qd + 4]);
                a[mt][3] = __float_as_uint(As[r + g + 8][8 * ks + qd + 4]);
            }
#pragma unroll
            for (int nt = 0; nt < 4; nt++) {
                int cn = wn + nt * 8 + g;
                bh[nt][0] = __float_as_uint(Wh[cn][8 * ks + qd]);
                bh[nt][1] = __float_as_uint(Wh[cn][8 * ks + qd + 4]);
                bl[nt][0] = __float_as_uint(Wl[cn][8 * ks + qd]);
                bl[nt][1] = __float_as_uint(Wl[cn][8 * ks + qd + 4]);
            }
#pragma unroll
            for (int mt = 0; mt < 2; mt++)
#pragma unroll
                for (int nt = 0; nt < 4; nt++) {
                    mma_tf32(c[mt][nt], a[mt], bh[nt][0], bh[nt][1]);
                    mma_tf32(c[mt][nt], a[mt], bl[nt][0], bl[nt][1]);
                }
        }
        __syncthreads();
    }

#pragma unroll
    for (int mt = 0; mt < 2; mt++) {
#pragma unroll
        for (int nt = 0; nt < 4; nt++) {
            int row = m0 + wm + mt * 16 + g;
            int col = n0 + wn + nt * 8 + 2 * qd;
            if (col >= N) continue;
            float v0 = c[mt][nt][0], v1 = c[mt][nt][1];
            float v2 = c[mt][nt][2], v3 = c[mt][nt][3];
            if (EPI == EPI_BIAS || EPI == EPI_BIAS_GELU) {
                float2 bv = *(const float2*)(bias + col);
                v0 += bv.x; v1 += bv.y; v2 += bv.x; v3 += bv.y;
            }
            if (EPI == EPI_BIAS_GELU) {
                v0 = gelu(v0); v1 = gelu(v1); v2 = gelu(v2); v3 = gelu(v3);
            }
            if (EPI == EPI_RES) {
                float2 r0 = *(const float2*)(res + (size_t)row * N + col);
                float2 r1 = *(const float2*)(res + (size_t)(row + 8) * N + col);
                v0 += r0.x; v1 += r0.y; v2 += r1.x; v3 += r1.y;
            }
            *(float2*)(C + (size_t)row * N + col) = make_float2(v0, v1);
            *(float2*)(C + (size_t)(row + 8) * N + col) = make_float2(v2, v3);
        }
    }
}

// ---------------- tf32 GEMM (128x128 tile, 256 threads) ----------------
template <int EPI>
__global__ void __launch_bounds__(256, 2)
gemm128_kernel(const float* __restrict__ A, const float* __restrict__ W,
               const float* __restrict__ bias, const float* __restrict__ res,
               float* __restrict__ C, int M, int N, int K)
{
    __shared__ float As[128][20];
    __shared__ float Wh[128][20];
    __shared__ float Wl[128][20];

    const int m0 = blockIdx.y * 128, n0 = blockIdx.x * 128;
    const int tid = threadIdx.x;
    const int w = tid >> 5, lane = tid & 31;
    const int qd = lane & 3, g = lane >> 2;
    const int wm = (w & 1) * 64;       // 2 warp rows of 64
    const int wn = (w >> 1) * 32;      // 4 warp cols of 32
    const int lrow = tid >> 1;         // 0..127
    const int lc4 = (tid & 1) * 8;     // 0 or 8

    float c[4][4][4];
#pragma unroll
    for (int mt = 0; mt < 4; mt++)
#pragma unroll
        for (int nt = 0; nt < 4; nt++)
#pragma unroll
            for (int i = 0; i < 4; i++) c[mt][nt][i] = 0.f;

    const float* Aptr = A + (size_t)(m0 + lrow) * K + lc4;
    const bool wvalid = (n0 + lrow) < N;
    const float* Wptr = W + (size_t)(wvalid ? (n0 + lrow) : 0) * K + lc4;

    float4 pa0 = *(const float4*)Aptr;
    float4 pa1 = *(const float4*)(Aptr + 4);
    float4 pw0 = wvalid ? *(const float4*)Wptr : make_float4(0.f, 0.f, 0.f, 0.f);
    float4 pw1 = wvalid ? *(const float4*)(Wptr + 4) : make_float4(0.f, 0.f, 0.f, 0.f);

    for (int k0 = 0; k0 < K; k0 += 16) {
        float4 t, th, tl;
        t.x = to_tf32(pa0.x); t.y = to_tf32(pa0.y); t.z = to_tf32(pa0.z); t.w = to_tf32(pa0.w);
        *(float4*)&As[lrow][lc4] = t;
        t.x = to_tf32(pa1.x); t.y = to_tf32(pa1.y); t.z = to_tf32(pa1.z); t.w = to_tf32(pa1.w);
        *(float4*)&As[lrow][lc4 + 4] = t;
        th.x = to_tf32(pw0.x); tl.x = to_tf32(pw0.x - th.x);
        th.y = to_tf32(pw0.y); tl.y = to_tf32(pw0.y - th.y);
        th.z = to_tf32(pw0.z); tl.z = to_tf32(pw0.z - th.z);
        th.w = to_tf32(pw0.w); tl.w = to_tf32(pw0.w - th.w);
        *(float4*)&Wh[lrow][lc4] = th;
        *(float4*)&Wl[lrow][lc4] = tl;
        th.x = to_tf32(pw1.x); tl.x = to_tf32(pw1.x - th.x);
        th.y = to_tf32(pw1.y); tl.y = to_tf32(pw1.y - th.y);
        th.z = to_tf32(pw1.z); tl.z = to_tf32(pw1.z - th.z);
        th.w = to_tf32(pw1.w); tl.w = to_tf32(pw1.w - th.w);
        *(float4*)&Wh[lrow][lc4 + 4] = th;
        *(float4*)&Wl[lrow][lc4 + 4] = tl;
        __syncthreads();

        if (k0 + 16 < K) {
            pa0 = *(const float4*)(Aptr + k0 + 16);
            pa1 = *(const float4*)(Aptr + k0 + 20);
            pw0 = wvalid ? *(const float4*)(Wptr + k0 + 16) : make_float4(0.f, 0.f, 0.f, 0.f);
            pw1 = wvalid ? *(const float4*)(Wptr + k0 + 20) : make_float4(0.f, 0.f, 0.f, 0.f);
        }

#pragma unroll
        for (int ks = 0; ks < 2; ks++) {
            unsigned a[4][4];
#pragma unroll
            for (int mt = 0; mt < 4; mt++) {
                int r = wm + mt * 16;
                a[mt][0] = __float_as_uint(As[r + g][8 * ks + qd]);
                a[mt][1] = __float_as_uint(As[r + g + 8][8 * ks + qd]);
                a[mt][2] = __float_as_uint(As[r + g][8 * ks + qd + 4]);
                a[mt][3] = __float_as_uint(As[r + g + 8][8 * ks + qd + 4]);
            }
#pragma unroll
            for (int nt = 0; nt < 4; nt++) {
                int cn = wn + nt * 8 + g;
                unsigned bh0 = __float_as_uint(Wh[cn][8 * ks + qd]);
                unsigned bh1 = __float_as_uint(Wh[cn][8 * ks + qd + 4]);
                unsigned bl0 = __float_as_uint(Wl[cn][8 * ks + qd]);
                unsigned bl1 = __float_as_uint(Wl[cn][8 * ks + qd + 4]);
#pragma unroll
                for (int mt = 0; mt < 4; mt++) {
                    mma_tf32(c[mt][nt], a[mt], bh0, bh1);
                    mma_tf32(c[mt][nt], a[mt], bl0, bl1);
                }
            }
        }
        __syncthreads();
    }

#pragma unroll
    for (int mt = 0; mt < 4; mt++) {
#pragma unroll
        for (int nt = 0; nt < 4; nt++) {
            int row = m0 + wm + mt * 16 + g;
            int col = n0 + wn + nt * 8 + 2 * qd;
            if (col >= N) continue;
            float v0 = c[mt][nt][0], v1 = c[mt][nt][1];
            float v2 = c[mt][nt][2], v3 = c[mt][nt][3];
            if (EPI == EPI_BIAS || EPI == EPI_BIAS_GELU) {
                float2 bv = *(const float2*)(bias + col);
                v0 += bv.x; v1 += bv.y; v2 += bv.x; v3 += bv.y;
            }
            if (EPI == EPI_BIAS_GELU) {
                v0 = gelu(v0); v1 = gelu(v1); v2 = gelu(v2); v3 = gelu(v3);
            }
            if (EPI == EPI_RES) {
                float2 r0 = *(const float2*)(res + (size_t)row * N + col);
                float2 r1 = *(const float2*)(res + (size_t)(row + 8) * N + col);
                v0 += r0.x; v1 += r0.y; v2 += r1.x; v3 += r1.y;
            }
            *(float2*)(C + (size_t)row * N + col) = make_float2(v0, v1);
            *(float2*)(C + (size_t)(row + 8) * N + col) = make_float2(v2, v3);
        }
    }
}

// ---------------- conv1d (causal, 4 taps) + SiLU, plus dt/dA ----------------
__global__ void conv_dt_kernel(const float* __restrict__ conv_w,
                               const float* __restrict__ conv_b,
                               const float* __restrict__ dt_bias,
                               const float* __restrict__ A_log)
{
    int bl = blockIdx.x;
    int c = threadIdx.x;
    int b = bl / LSEQ, l = bl % LSEQ;

    float accv = conv_b[c];
#pragma unroll
    for (int k = 0; k < 4; k++) {
        int ls = l - 3 + k;
        if (ls >= 0)
            accv += conv_w[c * 4 + k] *
                    g_zxbcdt[(size_t)(b * LSEQ + ls) * DINPROJ + DINNER + c];
    }
    float s = accv / (1.f + __expf(-accv));
    g_xBC[(size_t)bl * CONVDIM + c] = s;

    if (c < NHEADS) {
        float v = g_zxbcdt[(size_t)bl * DINPROJ + (DINNER + CONVDIM) + c] + dt_bias[c];
        float dt = (v > 20.f) ? v : log1pf(__expf(v));
        g_dt[bl * NHEADS + c] = dt;
        g_dA[bl * NHEADS + c] = __expf(dt * -__expf(A_log[c]));
    }
}

// ---------------- chunked selective scan: pass A (local scans) --------------
__global__ void __launch_bounds__(128) scan_chunk_kernel()
{
    int bidx = blockIdx.x;               // pg + 16*(h + 8*(b + 2*c))
    int pg = bidx & 15;
    int h  = (bidx >> 4) & 7;
    int b  = (bidx >> 7) & 1;
    int cch = bidx >> 8;                 // 0..31
    int warp = threadIdx.x >> 5;
    int lane = threadIdx.x & 31;
    int p = pg * 4 + warp;
    int n0 = lane * 4;
    int bh = b * NHEADS + h;
    int t0 = cch * CHUNK;

    float h0 = 0.f, h1 = 0.f, h2 = 0.f, h3 = 0.f;
    float prod = 1.f;
    const float* xbase = g_xBC + (size_t)b * LSEQ * CONVDIM;
    const float* dtb = g_dt + (size_t)b * LSEQ * NHEADS + h;
    const float* dab = g_dA + (size_t)b * LSEQ * NHEADS + h;
    float* yout = g_y + (size_t)b * LSEQ * DINNER + h * HEADDIM + p;
    const int coff = h * HEADDIM + p;

    for (int tl = 0; tl < CHUNK; tl++) {
        int t = t0 + tl;
        const float* row = xbase + (size_t)t * CONVDIM;
        float dA = dab[t * NHEADS];
        float dt = dtb[t * NHEADS];
        float xv = row[coff];
        float4 Bv = *(const float4*)(row + DINNER + n0);
        float4 Cv = *(const float4*)(row + DINNER + DSTATE + n0);
        float dtx = dt * xv;
        h0 = h0 * dA + dtx * Bv.x;
        h1 = h1 * dA + dtx * Bv.y;
        h2 = h2 * dA + dtx * Bv.z;
        h3 = h3 * dA + dtx * Bv.w;
        prod *= dA;
        float accr = h0 * Cv.x + h1 * Cv.y + h2 * Cv.z + h3 * Cv.w;
#pragma unroll
        for (int o = 16; o; o >>= 1) accr += __shfl_xor_sync(0xffffffffu, accr, o);
        if (lane == 0) yout[(size_t)t * DINNER] = accr;
        if (threadIdx.x == 0 && pg == 0)
            g_cumA[(size_t)bh * LSEQ + t] = prod;
    }
    // store chunk-local end state
    *(float4*)&g_state[(((size_t)bh * NCHUNK + cch) * HEADDIM + p) * DSTATE + n0] =
        make_float4(h0, h1, h2, h3);
    if (threadIdx.x == 0 && pg == 0)
        g_P[bh * NCHUNK + cch] = prod;
}

// ---------------- pass B: sequential combine of 32 chunk states -------------
__global__ void __launch_bounds__(256) combine_state_kernel()
{
    int idx = blockIdx.x * blockDim.x + threadIdx.x;   // 0..32767
    int nq = idx & 31;            // n0 = nq*4
    int p  = (idx >> 5) & 63;
    int bh = idx >> 11;           // 0..15
    float4 H = make_float4(0.f, 0.f, 0.f, 0.f);
    for (int cc = 0; cc < NCHUNK; cc++) {
        size_t off = (((size_t)bh * NCHUNK + cc) * HEADDIM + p) * DSTATE + nq * 4;
        *(float4*)&g_H0[off] = H;
        float4 S = *(const float4*)&g_state[off];
        float P = g_P[bh * NCHUNK + cc];
        H.x = S.x + P * H.x;
        H.y = S.y + P * H.y;
        H.z = S.z + P * H.z;
        H.w = S.w + P * H.w;
    }
}

// ---------------- pass C: cross-chunk correction y += cumA * (C · H0) -------
__global__ void __launch_bounds__(128) scan_fix_kernel()
{
    int bidx = blockIdx.x;               // chunks 1..31 only
    int pg = bidx & 15;
    int h  = (bidx >> 4) & 7;
    int b  = (bidx >> 7) & 1;
    int cch = (bidx >> 8) + 1;           // 1..31
    int warp = threadIdx.x >> 5;
    int lane = threadIdx.x & 31;
    int p = pg * 4 + warp;
    int n0 = lane * 4;
    int bh = b * NHEADS + h;
    int t0 = cch * CHUNK;

    float4 H = *(const float4*)&g_H0[(((size_t)bh * NCHUNK + cch) * HEADDIM + p) * DSTATE + n0];
    const float* cb = g_xBC + (size_t)b * LSEQ * CONVDIM + DINNER + DSTATE + n0;
    const float* cum = g_cumA + (size_t)bh * LSEQ;
    float* yout = g_y + (size_t)b * LSEQ * DINNER + h * HEADDIM + p;

    for (int tl = 0; tl < CHUNK; tl++) {
        int t = t0 + tl;
        float4 Cv = *(const float4*)(cb + (size_t)t * CONVDIM);
        float acc = H.x * Cv.x + H.y * Cv.y + H.z * Cv.z + H.w * Cv.w;
#pragma unroll
        for (int o = 16; o; o >>= 1) acc += __shfl_xor_sync(0xffffffffu, acc, o);
        if (lane == 0) yout[(size_t)t * DINNER] += cum[t] * acc;
    }
}

// ---------------- gate + RMSNorm ----------------
__global__ void __launch_bounds__(512) gate_rms_kernel(const float* __restrict__ D_param,
                                                       const float* __restrict__ norm_w)
{
    int bl = blockIdx.x;
    int d = threadIdx.x;
    float y = g_y[(size_t)bl * DINNER + d] +
              D_param[d >> 6] * g_xBC[(size_t)bl * CONVDIM + d];
    float z = g_zxbcdt[(size_t)bl * DINPROJ + d];
    float g = y * (z / (1.f + __expf(-z)));

    __shared__ float sh[16];
    float s = g * g;
    int lane = d & 31, w = d >> 5;
#pragma unroll
    for (int o = 16; o; o >>= 1) s += __shfl_xor_sync(0xffffffffu, s, o);
    if (lane == 0) sh[w] = s;
    __syncthreads();
    if (w == 0) {
        float v = (lane < 16) ? sh[lane] : 0.f;
#pragma unroll
        for (int o = 16; o; o >>= 1) v += __shfl_xor_sync(0xffffffffu, v, o);
        if (lane == 0) sh[0] = v;
    }
    __syncthreads();
    float scale = rsqrtf(sh[0] * (1.f / DINNER) + 1e-5f);
    g_y[(size_t)bl * DINNER + d] = g * scale * norm_w[d];
}

// ---------------- flash attention: tf32 QK^T, split-bf16 PV ----------------
__global__ void __launch_bounds__(128) attn_mma_kernel()
{
    __shared__ float Qs[64][40];
    __shared__ float Ks[64][40];
    __shared__ unsigned Vh[32][40];
    __shared__ unsigned Vl[32][40];

    const int q0 = blockIdx.x * 64;
    const int h = blockIdx.y;
    const int b = blockIdx.z;
    const int tid = threadIdx.x;
    const int w = tid >> 5, lane = tid & 31;
    const int qd = lane & 3, g = lane >> 2;
    const float scale = 0.1767766953f;

    const size_t base = (size_t)b * LSEQ * DMODEL + h * AHD;

#pragma unroll
    for (int i = 0; i < 4; i++) {
        int e = tid + i * 128;
        int row = e >> 3, c4 = (e & 7) * 4;
        float4 v = *(const float4*)(g_q + base + (size_t)(q0 + row) * DMODEL + c4);
        float4 t;
        t.x = to_tf32(v.x * scale); t.y = to_tf32(v.y * scale);
        t.z = to_tf32(v.z * scale); t.w = to_tf32(v.w * scale);
        *(float4*)&Qs[row][c4] = t;
    }
    __syncthreads();

    unsigned qa[4][4];
#pragma unroll
    for (int ks = 0; ks < 4; ks++) {
        int r = w * 16;
        qa[ks][0] = __float_as_uint(Qs[r + g][8 * ks + qd]);
        qa[ks][1] = __float_as_uint(Qs[r + g + 8][8 * ks + qd]);
        qa[ks][2] = __float_as_uint(Qs[r + g][8 * ks + qd + 4]);
        qa[ks][3] = __float_as_uint(Qs[r + g + 8][8 * ks + qd + 4]);
    }

    float m0 = -1e30f, m1 = -1e30f, l0 = 0.f, l1 = 0.f;
    float o[4][4];
#pragma unroll
    for (int nt = 0; nt < 4; nt++)
#pragma unroll
        for (int i = 0; i < 4; i++) o[nt][i] = 0.f;

    for (int kt = 0; kt < LSEQ / 64; kt++) {
        __syncthreads();
        const size_t kb = base + (size_t)(kt * 64) * DMODEL;
#pragma unroll
        for (int i = 0; i < 4; i++) {
            int e = tid + i * 128;
            int row = e >> 3, c4 = (e & 7) * 4;
            float4 v = *(const float4*)(g_k + kb + (size_t)row * DMODEL + c4);
            float4 t;
            t.x = to_tf32(v.x); t.y = to_tf32(v.y);
            t.z = to_tf32(v.z); t.w = to_tf32(v.w);
            *(float4*)&Ks[row][c4] = t;
        }
#pragma unroll
        for (int i = 0; i < 8; i++) {
            int e = tid + i * 128;
            int kp = e >> 5, d = e & 31;
            float v0 = g_v[kb + (size_t)(2 * kp) * DMODEL + d];
            float v1 = g_v[kb + (size_t)(2 * kp + 1) * DMODEL + d];
            __nv_bfloat16 h0b = __float2bfloat16_rn(v0);
            __nv_bfloat16 h1b = __float2bfloat16_rn(v1);
            __nv_bfloat16 l0b = __float2bfloat16_rn(v0 - __bfloat162float(h0b));
            __nv_bfloat16 l1b = __float2bfloat16_rn(v1 - __bfloat162float(h1b));
            __nv_bfloat162 hh = __halves2bfloat162(h0b, h1b);
            __nv_bfloat162 ll = __halves2bfloat162(l0b, l1b);
            Vh[kp][d] = *(unsigned*)&hh;
            Vl[kp][d] = *(unsigned*)&ll;
        }
        __syncthreads();

        float s[8][4];
#pragma unroll
        for (int nt = 0; nt < 8; nt++)
#pragma unroll
            for (int i = 0; i < 4; i++) s[nt][i] = 0.f;
#pragma unroll
        for (int ks = 0; ks < 4; ks++) {
#pragma unroll
            for (int nt = 0; nt < 8; nt++) {
                unsigned b0 = __float_as_uint(Ks[nt * 8 + g][8 * ks + qd]);
                unsigned b1 = __float_as_uint(Ks[nt * 8 + g][8 * ks + qd + 4]);
                mma_tf32(s[nt], qa[ks], b0, b1);
            }
        }

        float r0 = -1e30f, r1 = -1e30f;
#pragma unroll
        for (int nt = 0; nt < 8; nt++) {
            r0 = fmaxf(r0, fmaxf(s[nt][0], s[nt][1]));
            r1 = fmaxf(r1, fmaxf(s[nt][2], s[nt][3]));
        }
        r0 = fmaxf(r0, __shfl_xor_sync(0xffffffffu, r0, 1));
        r0 = fmaxf(r0, __shfl_xor_sync(0xffffffffu, r0, 2));
        r1 = fmaxf(r1, __shfl_xor_sync(0xffffffffu, r1, 1));
        r1 = fmaxf(r1, __shfl_xor_sync(0xffffffffu, r1, 2));
        float nm0 = fmaxf(m0, r0), nm1 = fmaxf(m1, r1);
        float cf0 = __expf(m0 - nm0), cf1 = __expf(m1 - nm1);
        m0 = nm0; m1 = nm1;
        l0 *= cf0; l1 *= cf1;
#pragma unroll
        for (int nt = 0; nt < 4; nt++) {
            o[nt][0] *= cf0; o[nt][1] *= cf0;
            o[nt][2] *= cf1; o[nt][3] *= cf1;
        }

        unsigned plo[8], phi[8];
#pragma unroll
        for (int nt = 0; nt < 8; nt++) {
            float p0 = __expf(s[nt][0] - m0);
            float p1 = __expf(s[nt][1] - m0);
            float p2 = __expf(s[nt][2] - m1);
            float p3 = __expf(s[nt][3] - m1);
            l0 += p0 + p1;
            l1 += p2 + p3;
            __nv_bfloat162 lo = __floats2bfloat162_rn(p0, p1);
            __nv_bfloat162 hi = __floats2bfloat162_rn(p2, p3);
            plo[nt] = *(unsigned*)&lo;
            phi[nt] = *(unsigned*)&hi;
        }

#pragma unroll
        for (int kk = 0; kk < 4; kk++) {
            unsigned a0 = plo[2 * kk], a1 = phi[2 * kk];
            unsigned a2 = plo[2 * kk + 1], a3 = phi[2 * kk + 1];
#pragma unroll
            for (int nt = 0; nt < 4; nt++) {
                unsigned bh0 = Vh[kk * 8 + qd][nt * 8 + g];
                unsigned bh1 = Vh[kk * 8 + qd + 4][nt * 8 + g];
                mma_bf16(o[nt], a0, a1, a2, a3, bh0, bh1);
                unsigned bl0 = Vl[kk * 8 + qd][nt * 8 + g];
                unsigned bl1 = Vl[kk * 8 + qd + 4][nt * 8 + g];
                mma_bf16(o[nt], a0, a1, a2, a3, bl0, bl1);
            }
        }
    }

    l0 += __shfl_xor_sync(0xffffffffu, l0, 1);
    l0 += __shfl_xor_sync(0xffffffffu, l0, 2);
    l1 += __shfl_xor_sync(0xffffffffu, l1, 1);
    l1 += __shfl_xor_sync(0xffffffffu, l1, 2);

    float inv0 = 1.f / l0, inv1 = 1.f / l1;
    int row = q0 + w * 16 + g;
#pragma unroll
    for (int nt = 0; nt < 4; nt++) {
        int col = h * AHD + nt * 8 + 2 * qd;
        *(float2*)(g_o + (size_t)(b * LSEQ + row) * DMODEL + col) =
            make_float2(o[nt][0] * inv0, o[nt][1] * inv0);
        *(float2*)(g_o + (size_t)(b * LSEQ + row + 8) * DMODEL + col) =
            make_float2(o[nt][2] * inv1, o[nt][3] * inv1);
    }
}

// ---------------- LayerNorm over 1024 ----------------
__global__ void __launch_bounds__(256) layernorm_kernel(const float* __restrict__ ln_w,
                                                        const float* __restrict__ ln_b)
{
    int bl = blockIdx.x, tid = threadIdx.x;
    float4 v = *(const float4*)(g_mlp + (size_t)bl * MLPH + tid * 4);
    float s = v.x + v.y + v.z + v.w;
    float s2 = v.x * v.x + v.y * v.y + v.z * v.z + v.w * v.w;

    __shared__ float shs[8], shs2[8];
    int lane = tid & 31, w = tid >> 5;
#pragma unroll
    for (int o = 16; o; o >>= 1) {
        s += __shfl_xor_sync(0xffffffffu, s, o);
        s2 += __shfl_xor_sync(0xffffffffu, s2, o);
    }
    if (lane == 0) { shs[w] = s; shs2[w] = s2; }
    __syncthreads();
    if (w == 0) {
        float a = (lane < 8) ? shs[lane] : 0.f;
        float b2 = (lane < 8) ? shs2[lane] : 0.f;
#pragma unroll
        for (int o = 4; o; o >>= 1) {
            a += __shfl_xor_sync(0xffffffffu, a, o);
            b2 += __shfl_xor_sync(0xffffffffu, b2, o);
        }
        if (lane == 0) { shs[0] = a; shs2[0] = b2; }
    }
    __syncthreads();
    float mu = shs[0] * (1.f / MLPH);
    float var = shs2[0] * (1.f / MLPH) - mu * mu;
    float inv = rsqrtf(var + 1e-5f);

    float4 wv = *(const float4*)(ln_w + tid * 4);
    float4 bv = *(const float4*)(ln_b + tid * 4);
    float4 r;
    r.x = (v.x - mu) * inv * wv.x + bv.x;
    r.y = (v.y - mu) * inv * wv.y + bv.y;
    r.z = (v.z - mu) * inv * wv.z + bv.z;
    r.w = (v.w - mu) * inv * wv.w + bv.w;
    *(float4*)(g_mlp + (size_t)bl * MLPH + tid * 4) = r;
}

// ---------------- mean-pool + head ----------------
__global__ void __launch_bounds__(256) pool_head_kernel(const float* __restrict__ head_w,
                                                        const float* __restrict__ head_b,
                                                        float* __restrict__ out)
{
    int b = blockIdx.x;
    int d = threadIdx.x;
    float s = 0.f;
#pragma unroll 8
    for (int t = 0; t < LSEQ; t++)
        s += g_h2[((size_t)(b * LSEQ + t)) * DMODEL + d];
    __shared__ float pooled[DMODEL];
    pooled[d] = s * (1.f / LSEQ);
    __syncthreads();
    if (d < 2) {
        float accv = head_b[d];
        for (int j = 0; j < DMODEL; j++) accv += pooled[j] * head_w[d * DMODEL + j];
        out[b * 2 + d] = accv;
    }
}

// ---------------- host launcher ----------------
extern "C" void kernel_launch(void* const* d_in, const int* in_sizes, int n_in,
                              void* d_out, int out_size)
{
    (void)in_sizes; (void)n_in; (void)out_size;
    const float* x         = (const float*)d_in[0];
    const float* context   = (const float*)d_in[1];
    const float* in_proj_w = (const float*)d_in[2];
    const float* conv_w    = (const float*)d_in[3];
    const float* conv_b    = (const float*)d_in[4];
    const float* dt_bias   = (const float*)d_in[5];
    const float* A_log     = (const float*)d_in[6];
    const float* D_param   = (const float*)d_in[7];
    const float* norm_w    = (const float*)d_in[8];
    const float* out_proj_w= (const float*)d_in[9];
    const float* wq        = (const float*)d_in[10];
    const float* wk        = (const float*)d_in[11];
    const float* wv        = (const float*)d_in[12];
    const float* wo        = (const float*)d_in[13];
    const float* wo_b      = (const float*)d_in[14];
    const float* w1        = (const float*)d_in[15];
    const float* b1        = (const float*)d_in[16];
    const float* ln_w      = (const float*)d_in[17];
    const float* ln_b      = (const float*)d_in[18];
    const float* w2        = (const float*)d_in[19];
    const float* b2        = (const float*)d_in[20];
    const float* head_w    = (const float*)d_in[21];
    const float* head_b    = (const float*)d_in[22];
    float* out = (float*)d_out;

    float *p_zx, *p_y, *p_hres, *p_q, *p_k, *p_v, *p_o, *p_ob, *p_mlp, *p_h2;
    cudaGetSymbolAddress((void**)&p_zx,   g_zxbcdt);
    cudaGetSymbolAddress((void**)&p_y,    g_y);
    cudaGetSymbolAddress((void**)&p_hres, g_hres);
    cudaGetSymbolAddress((void**)&p_q,    g_q);
    cudaGetSymbolAddress((void**)&p_k,    g_k);
    cudaGetSymbolAddress((void**)&p_v,    g_v);
    cudaGetSymbolAddress((void**)&p_o,    g_o);
    cudaGetSymbolAddress((void**)&p_ob,   g_ob);
    cudaGetSymbolAddress((void**)&p_mlp,  g_mlp);
    cudaGetSymbolAddress((void**)&p_h2,   g_h2);

    // 1) in_proj (big tile)
    gemm128_kernel<EPI_NONE><<<dim3((DINPROJ + 127) / 128, M4 / 128), 256>>>(
        x, in_proj_w, nullptr, nullptr, p_zx, M4, DINPROJ, DMODEL);
    // 2) conv + dt/dA
    conv_dt_kernel<<<M4, CONVDIM>>>(conv_w, conv_b, dt_bias, A_log);
    // 3) chunked selective scan
    scan_chunk_kernel<<<16 * 8 * 2 * NCHUNK, 128>>>();
    combine_state_kernel<<<128, 256>>>();
    scan_fix_kernel<<<16 * 8 * 2 * (NCHUNK - 1), 128>>>();
    // 4) gate + RMSNorm
    gate_rms_kernel<<<M4, DINNER>>>(D_param, norm_w);
    // 5) out_proj + residual
    gemm_tf32_kernel<EPI_RES><<<dim3(DMODEL / 64, M4 / 64), 128>>>(
        p_y, out_proj_w, nullptr, x, p_hres, M4, DMODEL, DINNER);
    // 6) q, k, v
    gemm_tf32_kernel<EPI_NONE><<<dim3(DMODEL / 64, M4 / 64), 128>>>(
        p_hres, wq, nullptr, nullptr, p_q, M4, DMODEL, DMODEL);
    gemm_tf32_kernel<EPI_NONE><<<dim3(DMODEL / 64, M4 / 64), 128>>>(
        context, wk, nullptr, nullptr, p_k, M4, DMODEL, DMODEL);
    gemm_tf32_kernel<EPI_NONE><<<dim3(DMODEL / 64, M4 / 64), 128>>>(
        context, wv, nullptr, nullptr, p_v, M4, DMODEL, DMODEL);
    // 7) attention
    attn_mma_kernel<<<dim3(LSEQ / 64, NHEADS, BBATCH), 128>>>();
    // 8) attn out proj
    gemm_tf32_kernel<EPI_BIAS><<<dim3(DMODEL / 64, M4 / 64), 128>>>(
        p_o, wo, wo_b, nullptr, p_ob, M4, DMODEL, DMODEL);
    // 9) MLP fc1 + GELU (big tile)
    gemm128_kernel<EPI_BIAS_GELU><<<dim3(MLPH / 128, M4 / 128), 256>>>(
        p_ob, w1, b1, nullptr, p_mlp, M4, MLPH, DMODEL);
    // 10) LayerNorm
    layernorm_kernel<<<M4, 256>>>(ln_w, ln_b);
    // 11) MLP fc2
    gemm_tf32_kernel<EPI_BIAS><<<dim3(DMODEL / 64, M4 / 64), 128>>>(
        p_mlp, w2, b2, nullptr, p_h2, M4, DMODEL, MLPH);
    // 12) pool + head
    pool_head_kernel<<<BBATCH, DMODEL>>>(head_w, head_b, out);
}

// round 6
// speedup vs baseline: 2.4621x; 1.1356x over previous
#include <cuda_runtime.h>
#include <cuda_bf16.h>
#include <math.h>

// ---------------- problem constants ----------------
#define BBATCH 2
#define LSEQ 2048
#define DMODEL 256
#define DINNER 512
#define DSTATE 128
#define NHEADS 8
#define HEADDIM 64
#define CONVDIM 768          // DINNER + 2*DSTATE
#define DINPROJ 1288         // 2*DINNER + 2*DSTATE + NHEADS
#define AHD 32               // attention head dim
#define MLPH 1024
#define M4 (BBATCH * LSEQ)   // 4096 rows
#define NCHUNK 32
#define CHUNK 64             // LSEQ / NCHUNK

// ---------------- scratch buffers ----------------
__device__ float g_zxbcdt[(size_t)M4 * DINPROJ];
__device__ float g_xBC[(size_t)M4 * CONVDIM];
__device__ float g_dt[M4 * NHEADS];
__device__ float g_dA[M4 * NHEADS];
__device__ float g_y[(size_t)M4 * DINNER];
__device__ float g_hres[(size_t)M4 * DMODEL];
__device__ float g_q[(size_t)M4 * DMODEL];
__device__ float g_k[(size_t)M4 * DMODEL];
__device__ float g_v[(size_t)M4 * DMODEL];
__device__ float g_o[(size_t)M4 * DMODEL];
__device__ float g_ob[(size_t)M4 * DMODEL];
__device__ float g_mlp[(size_t)M4 * MLPH];
__device__ float g_h2[(size_t)M4 * DMODEL];
// chunked-scan buffers
__device__ float g_state[(size_t)BBATCH * NHEADS * NCHUNK * HEADDIM * DSTATE];
__device__ float g_H0[(size_t)BBATCH * NHEADS * NCHUNK * HEADDIM * DSTATE];
__device__ float g_P[BBATCH * NHEADS * NCHUNK];
__device__ float g_cumA[BBATCH * NHEADS * LSEQ];
// attention packed operands
__device__ float g_qp[(size_t)M4 * DMODEL];                      // tf32(q*scale)
__device__ float g_kp[(size_t)M4 * DMODEL];                      // tf32(k)
__device__ unsigned g_vhi[(size_t)BBATCH * NHEADS * 1024 * 32];  // bf16x2 hi, [bh][kp][d]
__device__ unsigned g_vlo[(size_t)BBATCH * NHEADS * 1024 * 32];  // bf16x2 lo
// pooling partials
__device__ float g_pool[BBATCH * 16 * DMODEL];

// ---------------- helpers ----------------
__device__ __forceinline__ float to_tf32(float x) {
    unsigned r;
    asm("cvt.rna.tf32.f32 %0, %1;" : "=r"(r) : "f"(x));
    return __uint_as_float(r);
}

__device__ __forceinline__ void mma_tf32(float c[4], const unsigned a[4],
                                         unsigned b0, unsigned b1) {
    asm volatile(
        "mma.sync.aligned.m16n8k8.row.col.f32.tf32.tf32.f32 "
        "{%0,%1,%2,%3},{%4,%5,%6,%7},{%8,%9},{%0,%1,%2,%3};"
        : "+f"(c[0]), "+f"(c[1]), "+f"(c[2]), "+f"(c[3])
        : "r"(a[0]), "r"(a[1]), "r"(a[2]), "r"(a[3]), "r"(b0), "r"(b1));
}

__device__ __forceinline__ void mma_bf16(float c[4], unsigned a0, unsigned a1,
                                         unsigned a2, unsigned a3,
                                         unsigned b0, unsigned b1) {
    asm volatile(
        "mma.sync.aligned.m16n8k16.row.col.f32.bf16.bf16.f32 "
        "{%0,%1,%2,%3},{%4,%5,%6,%7},{%8,%9},{%0,%1,%2,%3};"
        : "+f"(c[0]), "+f"(c[1]), "+f"(c[2]), "+f"(c[3])
        : "r"(a0), "r"(a1), "r"(a2), "r"(a3), "r"(b0), "r"(b1));
}

// fast erf (Abramowitz-Stegun 7.1.26, abs err < 1.5e-7)
__device__ __forceinline__ float fast_erf(float x) {
    float ax = fabsf(x);
    float t = __frcp_rn(1.f + 0.3275911f * ax);
    float p = 1.061405429f;
    p = p * t - 1.453152027f;
    p = p * t + 1.421413741f;
    p = p * t - 0.284496736f;
    p = p * t + 0.254829592f;
    float r = 1.f - p * t * __expf(-ax * ax);
    return copysignf(r, x);
}
__device__ __forceinline__ float gelu(float v) {
    return 0.5f * v * (1.f + fast_erf(v * 0.70710678118f));
}

// ---------------- tf32 GEMM (64x64 tile, double-buffered smem) --------------
enum { EPI_NONE = 0, EPI_BIAS = 1, EPI_BIAS_GELU = 2, EPI_RES = 3 };

template <int EPI>
__global__ void __launch_bounds__(128)
gemm_tf32_kernel(const float* __restrict__ A, const float* __restrict__ W,
                 const float* __restrict__ bias, const float* __restrict__ res,
                 float* __restrict__ C, int M, int N, int K)
{
    __shared__ float As[2][64][20];
    __shared__ float Wh[2][64][20];
    __shared__ float Wl[2][64][20];

    const int m0 = blockIdx.y * 64, n0 = blockIdx.x * 64;
    const int tid = threadIdx.x;
    const int w = tid >> 5, lane = tid & 31;
    const int qd = lane & 3, g = lane >> 2;
    const int wm = (w & 1) * 32, wn = (w >> 1) * 32;
    const int lrow = tid >> 2;        // 0..31
    const int lc4 = (tid & 3) * 4;    // 0,4,8,12

    float c[2][4][4];
#pragma unroll
    for (int mt = 0; mt < 2; mt++)
#pragma unroll
        for (int nt = 0; nt < 4; nt++)
#pragma unroll
            for (int i = 0; i < 4; i++) c[mt][nt][i] = 0.f;

    const float* Aptr0 = A + (size_t)(m0 + lrow) * K + lc4;
    const float* Aptr1 = A + (size_t)(m0 + lrow + 32) * K + lc4;
    const bool wv0 = (n0 + lrow) < N;
    const bool wv1 = (n0 + lrow + 32) < N;
    const float* Wptr0 = W + (size_t)(wv0 ? (n0 + lrow) : 0) * K + lc4;
    const float* Wptr1 = W + (size_t)(wv1 ? (n0 + lrow + 32) : 0) * K + lc4;

    float4 pa0 = *(const float4*)Aptr0;
    float4 pa1 = *(const float4*)Aptr1;
    float4 pw0 = wv0 ? *(const float4*)Wptr0 : make_float4(0.f, 0.f, 0.f, 0.f);
    float4 pw1 = wv1 ? *(const float4*)Wptr1 : make_float4(0.f, 0.f, 0.f, 0.f);

    int buf = 0;
    for (int k0 = 0; k0 < K; k0 += 16) {
        float4 t0, t1, th, tl;
        t0.x = to_tf32(pa0.x); t0.y = to_tf32(pa0.y); t0.z = to_tf32(pa0.z); t0.w = to_tf32(pa0.w);
        t1.x = to_tf32(pa1.x); t1.y = to_tf32(pa1.y); t1.z = to_tf32(pa1.z); t1.w = to_tf32(pa1.w);
        *(float4*)&As[buf][lrow][lc4] = t0;
        *(float4*)&As[buf][lrow + 32][lc4] = t1;
        th.x = to_tf32(pw0.x); tl.x = to_tf32(pw0.x - th.x);
        th.y = to_tf32(pw0.y); tl.y = to_tf32(pw0.y - th.y);
        th.z = to_tf32(pw0.z); tl.z = to_tf32(pw0.z - th.z);
        th.w = to_tf32(pw0.w); tl.w = to_tf32(pw0.w - th.w);
        *(float4*)&Wh[buf][lrow][lc4] = th;
        *(float4*)&Wl[buf][lrow][lc4] = tl;
        th.x = to_tf32(pw1.x); tl.x = to_tf32(pw1.x - th.x);
        th.y = to_tf32(pw1.y); tl.y = to_tf32(pw1.y - th.y);
        th.z = to_tf32(pw1.z); tl.z = to_tf32(pw1.z - th.z);
        th.w = to_tf32(pw1.w); tl.w = to_tf32(pw1.w - th.w);
        *(float4*)&Wh[buf][lrow + 32][lc4] = th;
        *(float4*)&Wl[buf][lrow + 32][lc4] = tl;
        __syncthreads();

        if (k0 + 16 < K) {
            pa0 = *(const float4*)(Aptr0 + k0 + 16);
            pa1 = *(const float4*)(Aptr1 + k0 + 16);
            pw0 = wv0 ? *(const float4*)(Wptr0 + k0 + 16) : make_float4(0.f, 0.f, 0.f, 0.f);
            pw1 = wv1 ? *(const float4*)(Wptr1 + k0 + 16) : make_float4(0.f, 0.f, 0.f, 0.f);
        }

#pragma unroll
        for (int ks = 0; ks < 2; ks++) {
            unsigned a[2][4], bh[4][2], bl[4][2];
#pragma unroll
            for (int mt = 0; mt < 2; mt++) {
                int r = wm + mt * 16;
                a[mt][0] = __float_as_uint(As[buf][r + g][8 * ks + qd]);
                a[mt][1] = __float_as_uint(As[buf][r + g + 8][8 * ks + qd]);
                a[mt][2] = __float_as_uint(As[buf][r + g][8 * ks + qd + 4]);
                a[mt][3] = __float_as_uint(As[buf][r + g + 8][8 * ks + qd + 4]);
            }
#pragma unroll
            for (int nt = 0; nt < 4; nt++) {
                int cn = wn + nt * 8 + g;
                bh[nt][0] = __float_as_uint(Wh[buf][cn][8 * ks + qd]);
                bh[nt][1] = __float_as_uint(Wh[buf][cn][8 * ks + qd + 4]);
                bl[nt][0] = __float_as_uint(Wl[buf][cn][8 * ks + qd]);
                bl[nt][1] = __float_as_uint(Wl[buf][cn][8 * ks + qd + 4]);
            }
#pragma unroll
            for (int mt = 0; mt < 2; mt++)
#pragma unroll
                for (int nt = 0; nt < 4; nt++) {
                    mma_tf32(c[mt][nt], a[mt], bh[nt][0], bh[nt][1]);
                    mma_tf32(c[mt][nt], a[mt], bl[nt][0], bl[nt][1]);
                }
        }
        buf ^= 1;   // next store goes to the other buffer; no 2nd sync needed
    }

#pragma unroll
    for (int mt = 0; mt < 2; mt++) {
#pragma unroll
        for (int nt = 0; nt < 4; nt++) {
            int row = m0 + wm + mt * 16 + g;
            int col = n0 + wn + nt * 8 + 2 * qd;
            if (col >= N) continue;
            float v0 = c[mt][nt][0], v1 = c[mt][nt][1];
            float v2 = c[mt][nt][2], v3 = c[mt][nt][3];
            if (EPI == EPI_BIAS || EPI == EPI_BIAS_GELU) {
                float2 bv = *(const float2*)(bias + col);
                v0 += bv.x; v1 += bv.y; v2 += bv.x; v3 += bv.y;
            }
            if (EPI == EPI_BIAS_GELU) {
                v0 = gelu(v0); v1 = gelu(v1); v2 = gelu(v2); v3 = gelu(v3);
            }
            if (EPI == EPI_RES) {
                float2 r0 = *(const float2*)(res + (size_t)row * N + col);
                float2 r1 = *(const float2*)(res + (size_t)(row + 8) * N + col);
                v0 += r0.x; v1 += r0.y; v2 += r1.x; v3 += r1.y;
            }
            *(float2*)(C + (size_t)row * N + col) = make_float2(v0, v1);
            *(float2*)(C + (size_t)(row + 8) * N + col) = make_float2(v2, v3);
        }
    }
}

// ---------------- tf32 GEMM (128x128 tile, 256 threads) ----------------
template <int EPI>
__global__ void __launch_bounds__(256, 2)
gemm128_kernel(const float* __restrict__ A, const float* __restrict__ W,
               const float* __restrict__ bias, const float* __restrict__ res,
               float* __restrict__ C, int M, int N, int K)
{
    __shared__ float As[128][20];
    __shared__ float Wh[128][20];
    __shared__ float Wl[128][20];

    const int m0 = blockIdx.y * 128, n0 = blockIdx.x * 128;
    const int tid = threadIdx.x;
    const int w = tid >> 5, lane = tid & 31;
    const int qd = lane & 3, g = lane >> 2;
    const int wm = (w & 1) * 64;
    const int wn = (w >> 1) * 32;
    const int lrow = tid >> 1;         // 0..127
    const int lc4 = (tid & 1) * 8;     // 0 or 8

    float c[4][4][4];
#pragma unroll
    for (int mt = 0; mt < 4; mt++)
#pragma unroll
        for (int nt = 0; nt < 4; nt++)
#pragma unroll
            for (int i = 0; i < 4; i++) c[mt][nt][i] = 0.f;

    const float* Aptr = A + (size_t)(m0 + lrow) * K + lc4;
    const bool wvalid = (n0 + lrow) < N;
    const float* Wptr = W + (size_t)(wvalid ? (n0 + lrow) : 0) * K + lc4;

    float4 pa0 = *(const float4*)Aptr;
    float4 pa1 = *(const float4*)(Aptr + 4);
    float4 pw0 = wvalid ? *(const float4*)Wptr : make_float4(0.f, 0.f, 0.f, 0.f);
    float4 pw1 = wvalid ? *(const float4*)(Wptr + 4) : make_float4(0.f, 0.f, 0.f, 0.f);

    for (int k0 = 0; k0 < K; k0 += 16) {
        float4 t, th, tl;
        t.x = to_tf32(pa0.x); t.y = to_tf32(pa0.y); t.z = to_tf32(pa0.z); t.w = to_tf32(pa0.w);
        *(float4*)&As[lrow][lc4] = t;
        t.x = to_tf32(pa1.x); t.y = to_tf32(pa1.y); t.z = to_tf32(pa1.z); t.w = to_tf32(pa1.w);
        *(float4*)&As[lrow][lc4 + 4] = t;
        th.x = to_tf32(pw0.x); tl.x = to_tf32(pw0.x - th.x);
        th.y = to_tf32(pw0.y); tl.y = to_tf32(pw0.y - th.y);
        th.z = to_tf32(pw0.z); tl.z = to_tf32(pw0.z - th.z);
        th.w = to_tf32(pw0.w); tl.w = to_tf32(pw0.w - th.w);
        *(float4*)&Wh[lrow][lc4] = th;
        *(float4*)&Wl[lrow][lc4] = tl;
        th.x = to_tf32(pw1.x); tl.x = to_tf32(pw1.x - th.x);
        th.y = to_tf32(pw1.y); tl.y = to_tf32(pw1.y - th.y);
        th.z = to_tf32(pw1.z); tl.z = to_tf32(pw1.z - th.z);
        th.w = to_tf32(pw1.w); tl.w = to_tf32(pw1.w - th.w);
        *(float4*)&Wh[lrow][lc4 + 4] = th;
        *(float4*)&Wl[lrow][lc4 + 4] = tl;
        __syncthreads();

        if (k0 + 16 < K) {
            pa0 = *(const float4*)(Aptr + k0 + 16);
            pa1 = *(const float4*)(Aptr + k0 + 20);
            pw0 = wvalid ? *(const float4*)(Wptr + k0 + 16) : make_float4(0.f, 0.f, 0.f, 0.f);
            pw1 = wvalid ? *(const float4*)(Wptr + k0 + 20) : make_float4(0.f, 0.f, 0.f, 0.f);
        }

#pragma unroll
        for (int ks = 0; ks < 2; ks++) {
            unsigned a[4][4];
#pragma unroll
            for (int mt = 0; mt < 4; mt++) {
                int r = wm + mt * 16;
                a[mt][0] = __float_as_uint(As[r + g][8 * ks + qd]);
                a[mt][1] = __float_as_uint(As[r + g + 8][8 * ks + qd]);
                a[mt][2] = __float_as_uint(As[r + g][8 * ks + qd + 4]);
                a[mt][3] = __float_as_uint(As[r + g + 8][8 * ks + qd + 4]);
            }
#pragma unroll
            for (int nt = 0; nt < 4; nt++) {
                int cn = wn + nt * 8 + g;
                unsigned bh0 = __float_as_uint(Wh[cn][8 * ks + qd]);
                unsigned bh1 = __float_as_uint(Wh[cn][8 * ks + qd + 4]);
                unsigned bl0 = __float_as_uint(Wl[cn][8 * ks + qd]);
                unsigned bl1 = __float_as_uint(Wl[cn][8 * ks + qd + 4]);
#pragma unroll
                for (int mt = 0; mt < 4; mt++) {
                    mma_tf32(c[mt][nt], a[mt], bh0, bh1);
                    mma_tf32(c[mt][nt], a[mt], bl0, bl1);
                }
            }
        }
        __syncthreads();
    }

#pragma unroll
    for (int mt = 0; mt < 4; mt++) {
#pragma unroll
        for (int nt = 0; nt < 4; nt++) {
            int row = m0 + wm + mt * 16 + g;
            int col = n0 + wn + nt * 8 + 2 * qd;
            if (col >= N) continue;
            float v0 = c[mt][nt][0], v1 = c[mt][nt][1];
            float v2 = c[mt][nt][2], v3 = c[mt][nt][3];
            if (EPI == EPI_BIAS || EPI == EPI_BIAS_GELU) {
                float2 bv = *(const float2*)(bias + col);
                v0 += bv.x; v1 += bv.y; v2 += bv.x; v3 += bv.y;
            }
            if (EPI == EPI_BIAS_GELU) {
                v0 = gelu(v0); v1 = gelu(v1); v2 = gelu(v2); v3 = gelu(v3);
            }
            if (EPI == EPI_RES) {
                float2 r0 = *(const float2*)(res + (size_t)row * N + col);
                float2 r1 = *(const float2*)(res + (size_t)(row + 8) * N + col);
                v0 += r0.x; v1 += r0.y; v2 += r1.x; v3 += r1.y;
            }
            *(float2*)(C + (size_t)row * N + col) = make_float2(v0, v1);
            *(float2*)(C + (size_t)(row + 8) * N + col) = make_float2(v2, v3);
        }
    }
}

// ---------------- conv1d: 16 timesteps per block, sliding register window ----
__global__ void __launch_bounds__(CONVDIM) conv_dt_kernel(
    const float* __restrict__ conv_w, const float* __restrict__ conv_b,
    const float* __restrict__ dt_bias, const float* __restrict__ A_log)
{
    int blk = blockIdx.x;                // 256 blocks
    int b = blk >> 7;
    int l0 = (blk & 127) << 4;
    int c = threadIdx.x;

    const float* src = g_zxbcdt + (size_t)b * LSEQ * DINPROJ + DINNER + c;
    float cw0 = conv_w[c * 4 + 0], cw1 = conv_w[c * 4 + 1];
    float cw2 = conv_w[c * 4 + 2], cw3 = conv_w[c * 4 + 3];
    float cb = conv_b[c];

    float x0 = 0.f, x1 = 0.f, x2 = 0.f;
    if (l0 >= 3) {
        x0 = src[(size_t)(l0 - 3) * DINPROJ];
        x1 = src[(size_t)(l0 - 2) * DINPROJ];
        x2 = src[(size_t)(l0 - 1) * DINPROJ];
    }
    float* dst = g_xBC + (size_t)(b * LSEQ + l0) * CONVDIM + c;
#pragma unroll
    for (int tl = 0; tl < 16; tl++) {
        float x3 = src[(size_t)(l0 + tl) * DINPROJ];
        float accv = cb + cw0 * x0 + cw1 * x1 + cw2 * x2 + cw3 * x3;
        dst[(size_t)tl * CONVDIM] = accv / (1.f + __expf(-accv));
        x0 = x1; x1 = x2; x2 = x3;
    }

    if (c < NHEADS) {
        float aexp = __expf(A_log[c]);
        float db = dt_bias[c];
        const float* dsrc = g_zxbcdt + (size_t)(b * LSEQ + l0) * DINPROJ + DINNER + CONVDIM + c;
#pragma unroll
        for (int tl = 0; tl < 16; tl++) {
            float v = dsrc[(size_t)tl * DINPROJ] + db;
            float dt = (v > 20.f) ? v : log1pf(__expf(v));
            int off = (b * LSEQ + l0 + tl) * NHEADS + c;
            g_dt[off] = dt;
            g_dA[off] = __expf(dt * -aexp);
        }
    }
}

// ---------------- chunked selective scan: pass A (local scans) --------------
__global__ void __launch_bounds__(128) scan_chunk_kernel()
{
    int bidx = blockIdx.x;
    int pg = bidx & 15;
    int h  = (bidx >> 4) & 7;
    int b  = (bidx >> 7) & 1;
    int cch = bidx >> 8;
    int warp = threadIdx.x >> 5;
    int lane = threadIdx.x & 31;
    int p = pg * 4 + warp;
    int n0 = lane * 4;
    int bh = b * NHEADS + h;
    int t0 = cch * CHUNK;

    float h0 = 0.f, h1 = 0.f, h2 = 0.f, h3 = 0.f;
    float prod = 1.f;
    const float* xbase = g_xBC + (size_t)b * LSEQ * CONVDIM;
    const float* dtb = g_dt + (size_t)b * LSEQ * NHEADS + h;
    const float* dab = g_dA + (size_t)b * LSEQ * NHEADS + h;
    float* yout = g_y + (size_t)b * LSEQ * DINNER + h * HEADDIM + p;
    const int coff = h * HEADDIM + p;

    for (int tl = 0; tl < CHUNK; tl++) {
        int t = t0 + tl;
        const float* row = xbase + (size_t)t * CONVDIM;
        float dA = dab[t * NHEADS];
        float dt = dtb[t * NHEADS];
        float xv = row[coff];
        float4 Bv = *(const float4*)(row + DINNER + n0);
        float4 Cv = *(const float4*)(row + DINNER + DSTATE + n0);
        float dtx = dt * xv;
        h0 = h0 * dA + dtx * Bv.x;
        h1 = h1 * dA + dtx * Bv.y;
        h2 = h2 * dA + dtx * Bv.z;
        h3 = h3 * dA + dtx * Bv.w;
        prod *= dA;
        float accr = h0 * Cv.x + h1 * Cv.y + h2 * Cv.z + h3 * Cv.w;
#pragma unroll
        for (int o = 16; o; o >>= 1) accr += __shfl_xor_sync(0xffffffffu, accr, o);
        if (lane == 0) yout[(size_t)t * DINNER] = accr;
        if (threadIdx.x == 0 && pg == 0)
            g_cumA[(size_t)bh * LSEQ + t] = prod;
    }
    *(float4*)&g_state[(((size_t)bh * NCHUNK + cch) * HEADDIM + p) * DSTATE + n0] =
        make_float4(h0, h1, h2, h3);
    if (threadIdx.x == 0 && pg == 0)
        g_P[bh * NCHUNK + cch] = prod;
}

// ---------------- pass B: sequential combine (float2 granularity) -----------
__global__ void __launch_bounds__(256) combine_state_kernel()
{
    int idx = blockIdx.x * blockDim.x + threadIdx.x;   // 0..65535
    int nq = idx & 63;            // n offset = nq*2
    int p  = (idx >> 6) & 63;
    int bh = idx >> 12;
    float2 H = make_float2(0.f, 0.f);
    const float* Pb = g_P + bh * NCHUNK;
#pragma unroll 8
    for (int cc = 0; cc < NCHUNK; cc++) {
        size_t off = (((size_t)bh * NCHUNK + cc) * HEADDIM + p) * DSTATE + nq * 2;
        *(float2*)&g_H0[off] = H;
        float2 S = *(const float2*)&g_state[off];
        float P = Pb[cc];
        H.x = S.x + P * H.x;
        H.y = S.y + P * H.y;
    }
}

// ---------------- pass C: cross-chunk correction y += cumA * (C · H0) -------
__global__ void __launch_bounds__(128) scan_fix_kernel()
{
    int bidx = blockIdx.x;
    int pg = bidx & 15;
    int h  = (bidx >> 4) & 7;
    int b  = (bidx >> 7) & 1;
    int cch = (bidx >> 8) + 1;
    int warp = threadIdx.x >> 5;
    int lane = threadIdx.x & 31;
    int p = pg * 4 + warp;
    int n0 = lane * 4;
    int bh = b * NHEADS + h;
    int t0 = cch * CHUNK;

    float4 H = *(const float4*)&g_H0[(((size_t)bh * NCHUNK + cch) * HEADDIM + p) * DSTATE + n0];
    const float* cb = g_xBC + (size_t)b * LSEQ * CONVDIM + DINNER + DSTATE + n0;
    const float* cum = g_cumA + (size_t)bh * LSEQ;
    float* yout = g_y + (size_t)b * LSEQ * DINNER + h * HEADDIM + p;

    for (int tl = 0; tl < CHUNK; tl++) {
        int t = t0 + tl;
        float4 Cv = *(const float4*)(cb + (size_t)t * CONVDIM);
        float acc = H.x * Cv.x + H.y * Cv.y + H.z * Cv.z + H.w * Cv.w;
#pragma unroll
        for (int o = 16; o; o >>= 1) acc += __shfl_xor_sync(0xffffffffu, acc, o);
        if (lane == 0) yout[(size_t)t * DINNER] += cum[t] * acc;
    }
}

// ---------------- gate + RMSNorm ----------------
__global__ void __launch_bounds__(512) gate_rms_kernel(const float* __restrict__ D_param,
                                                       const float* __restrict__ norm_w)
{
    int bl = blockIdx.x;
    int d = threadIdx.x;
    float y = g_y[(size_t)bl * DINNER + d] +
              D_param[d >> 6] * g_xBC[(size_t)bl * CONVDIM + d];
    float z = g_zxbcdt[(size_t)bl * DINPROJ + d];
    float g = y * (z / (1.f + __expf(-z)));

    __shared__ float sh[16];
    float s = g * g;
    int lane = d & 31, w = d >> 5;
#pragma unroll
    for (int o = 16; o; o >>= 1) s += __shfl_xor_sync(0xffffffffu, s, o);
    if (lane == 0) sh[w] = s;
    __syncthreads();
    if (w == 0) {
        float v = (lane < 16) ? sh[lane] : 0.f;
#pragma unroll
        for (int o = 16; o; o >>= 1) v += __shfl_xor_sync(0xffffffffu, v, o);
        if (lane == 0) sh[0] = v;
    }
    __syncthreads();
    float scale = rsqrtf(sh[0] * (1.f / DINNER) + 1e-5f);
    g_y[(size_t)bl * DINNER + d] = g * scale * norm_w[d];
}

// ---------------- attention operand packing ----------------
__global__ void __launch_bounds__(256) qk_pack_kernel()
{
    const float scale = 0.1767766953f;
    int idx = blockIdx.x * blockDim.x + threadIdx.x;    // float4 index
    float4 q = *(const float4*)(g_q + (size_t)idx * 4);
    float4 k = *(const float4*)(g_k + (size_t)idx * 4);
    float4 tq, tk;
    tq.x = to_tf32(q.x * scale); tq.y = to_tf32(q.y * scale);
    tq.z = to_tf32(q.z * scale); tq.w = to_tf32(q.w * scale);
    tk.x = to_tf32(k.x); tk.y = to_tf32(k.y);
    tk.z = to_tf32(k.z); tk.w = to_tf32(k.w);
    *(float4*)(g_qp + (size_t)idx * 4) = tq;
    *(float4*)(g_kp + (size_t)idx * 4) = tk;
}

__global__ void __launch_bounds__(256) v_pack_kernel()
{
    int idx = blockIdx.x * blockDim.x + threadIdx.x;    // 0..524287
    int d  = idx & 31;
    int kp = (idx >> 5) & 1023;
    int h  = (idx >> 15) & 7;
    int b  = idx >> 18;
    size_t src = ((size_t)(b * LSEQ + 2 * kp)) * DMODEL + h * AHD + d;
    float v0 = g_v[src];
    float v1 = g_v[src + DMODEL];
    __nv_bfloat16 h0b = __float2bfloat16_rn(v0);
    __nv_bfloat16 h1b = __float2bfloat16_rn(v1);
    __nv_bfloat16 l0b = __float2bfloat16_rn(v0 - __bfloat162float(h0b));
    __nv_bfloat16 l1b = __float2bfloat16_rn(v1 - __bfloat162float(h1b));
    __nv_bfloat162 hh = __halves2bfloat162(h0b, h1b);
    __nv_bfloat162 ll = __halves2bfloat162(l0b, l1b);
    g_vhi[idx] = *(unsigned*)&hh;
    g_vlo[idx] = *(unsigned*)&ll;
}

// ---------------- flash attention: 128 queries/block, 8 warps ---------------
__global__ void __launch_bounds__(256) attn_mma_kernel()
{
    __shared__ float Qs[128][40];
    __shared__ float Ks[64][40];
    __shared__ unsigned Vh[32][40];
    __shared__ unsigned Vl[32][40];

    const int q0 = blockIdx.x * 128;
    const int h = blockIdx.y;
    const int b = blockIdx.z;
    const int tid = threadIdx.x;
    const int w = tid >> 5, lane = tid & 31;
    const int qd = lane & 3, g = lane >> 2;

    const size_t base = (size_t)b * LSEQ * DMODEL + h * AHD;
    const unsigned* vhib = g_vhi + ((size_t)(b * NHEADS + h)) * 1024 * 32;
    const unsigned* vlob = g_vlo + ((size_t)(b * NHEADS + h)) * 1024 * 32;

    // stage Q (already scaled+tf32)
#pragma unroll
    for (int i = 0; i < 4; i++) {
        int e = tid + i * 256;
        int row = e >> 3, c4 = (e & 7) * 4;
        *(float4*)&Qs[row][c4] =
            *(const float4*)(g_qp + base + (size_t)(q0 + row) * DMODEL + c4);
    }
    __syncthreads();

    unsigned qa[4][4];
#pragma unroll
    for (int ks = 0; ks < 4; ks++) {
        int r = w * 16;
        qa[ks][0] = __float_as_uint(Qs[r + g][8 * ks + qd]);
        qa[ks][1] = __float_as_uint(Qs[r + g + 8][8 * ks + qd]);
        qa[ks][2] = __float_as_uint(Qs[r + g][8 * ks + qd + 4]);
        qa[ks][3] = __float_as_uint(Qs[r + g + 8][8 * ks + qd + 4]);
    }

    float m0 = -1e30f, m1 = -1e30f, l0 = 0.f, l1 = 0.f;
    float o[4][4];
#pragma unroll
    for (int nt = 0; nt < 4; nt++)
#pragma unroll
        for (int i = 0; i < 4; i++) o[nt][i] = 0.f;

    for (int kt = 0; kt < LSEQ / 64; kt++) {
        __syncthreads();
        // K tile (pre-tf32)
#pragma unroll
        for (int i = 0; i < 2; i++) {
            int e = tid + i * 256;
            int row = e >> 3, c4 = (e & 7) * 4;
            *(float4*)&Ks[row][c4] =
                *(const float4*)(g_kp + base + (size_t)(kt * 64 + row) * DMODEL + c4);
        }
        // V tile (pre-packed bf16x2 hi/lo): 256 uint4 each
        {
            int kp = tid >> 3, q4 = (tid & 7) * 4;
            size_t gsrc = (size_t)(kt * 32 + kp) * 32 + q4;
            *(uint4*)&Vh[kp][q4] = *(const uint4*)(vhib + gsrc);
            *(uint4*)&Vl[kp][q4] = *(const uint4*)(vlob + gsrc);
        }
        __syncthreads();

        float s[8][4];
#pragma unroll
        for (int nt = 0; nt < 8; nt++)
#pragma unroll
            for (int i = 0; i < 4; i++) s[nt][i] = 0.f;
#pragma unroll
        for (int ks = 0; ks < 4; ks++) {
#pragma unroll
            for (int nt = 0; nt < 8; nt++) {
                unsigned b0 = __float_as_uint(Ks[nt * 8 + g][8 * ks + qd]);
                unsigned b1 = __float_as_uint(Ks[nt * 8 + g][8 * ks + qd + 4]);
                mma_tf32(s[nt], qa[ks], b0, b1);
            }
        }

        float r0 = -1e30f, r1 = -1e30f;
#pragma unroll
        for (int nt = 0; nt < 8; nt++) {
            r0 = fmaxf(r0, fmaxf(s[nt][0], s[nt][1]));
            r1 = fmaxf(r1, fmaxf(s[nt][2], s[nt][3]));
        }
        r0 = fmaxf(r0, __shfl_xor_sync(0xffffffffu, r0, 1));
        r0 = fmaxf(r0, __shfl_xor_sync(0xffffffffu, r0, 2));
        r1 = fmaxf(r1, __shfl_xor_sync(0xffffffffu, r1, 1));
        r1 = fmaxf(r1, __shfl_xor_sync(0xffffffffu, r1, 2));
        float nm0 = fmaxf(m0, r0), nm1 = fmaxf(m1, r1);
        float cf0 = __expf(m0 - nm0), cf1 = __expf(m1 - nm1);
        m0 = nm0; m1 = nm1;
        l0 *= cf0; l1 *= cf1;
#pragma unroll
        for (int nt = 0; nt < 4; nt++) {
            o[nt][0] *= cf0; o[nt][1] *= cf0;
            o[nt][2] *= cf1; o[nt][3] *= cf1;
        }

        unsigned plo[8], phi[8];
#pragma unroll
        for (int nt = 0; nt < 8; nt++) {
            float p0 = __expf(s[nt][0] - m0);
            float p1 = __expf(s[nt][1] - m0);
            float p2 = __expf(s[nt][2] - m1);
            float p3 = __expf(s[nt][3] - m1);
            l0 += p0 + p1;
            l1 += p2 + p3;
            __nv_bfloat162 lo = __floats2bfloat162_rn(p0, p1);
            __nv_bfloat162 hi = __floats2bfloat162_rn(p2, p3);
            plo[nt] = *(unsigned*)&lo;
            phi[nt] = *(unsigned*)&hi;
        }

#pragma unroll
        for (int kk = 0; kk < 4; kk++) {
            unsigned a0 = plo[2 * kk], a1 = phi[2 * kk];
            unsigned a2 = plo[2 * kk + 1], a3 = phi[2 * kk + 1];
#pragma unroll
            for (int nt = 0; nt < 4; nt++) {
                unsigned bh0 = Vh[kk * 8 + qd][nt * 8 + g];
                unsigned bh1 = Vh[kk * 8 + qd + 4][nt * 8 + g];
                mma_bf16(o[nt], a0, a1, a2, a3, bh0, bh1);
                unsigned bl0 = Vl[kk * 8 + qd][nt * 8 + g];
                unsigned bl1 = Vl[kk * 8 + qd + 4][nt * 8 + g];
                mma_bf16(o[nt], a0, a1, a2, a3, bl0, bl1);
            }
        }
    }

    l0 += __shfl_xor_sync(0xffffffffu, l0, 1);
    l0 += __shfl_xor_sync(0xffffffffu, l0, 2);
    l1 += __shfl_xor_sync(0xffffffffu, l1, 1);
    l1 += __shfl_xor_sync(0xffffffffu, l1, 2);

    float inv0 = 1.f / l0, inv1 = 1.f / l1;
    int row = q0 + w * 16 + g;
#pragma unroll
    for (int nt = 0; nt < 4; nt++) {
        int col = h * AHD + nt * 8 + 2 * qd;
        *(float2*)(g_o + (size_t)(b * LSEQ + row) * DMODEL + col) =
            make_float2(o[nt][0] * inv0, o[nt][1] * inv0);
        *(float2*)(g_o + (size_t)(b * LSEQ + row + 8) * DMODEL + col) =
            make_float2(o[nt][2] * inv1, o[nt][3] * inv1);
    }
}

// ---------------- LayerNorm over 1024 ----------------
__global__ void __launch_bounds__(256) layernorm_kernel(const float* __restrict__ ln_w,
                                                        const float* __restrict__ ln_b)
{
    int bl = blockIdx.x, tid = threadIdx.x;
    float4 v = *(const float4*)(g_mlp + (size_t)bl * MLPH + tid * 4);
    float s = v.x + v.y + v.z + v.w;
    float s2 = v.x * v.x + v.y * v.y + v.z * v.z + v.w * v.w;

    __shared__ float shs[8], shs2[8];
    int lane = tid & 31, w = tid >> 5;
#pragma unroll
    for (int o = 16; o; o >>= 1) {
        s += __shfl_xor_sync(0xffffffffu, s, o);
        s2 += __shfl_xor_sync(0xffffffffu, s2, o);
    }
    if (lane == 0) { shs[w] = s; shs2[w] = s2; }
    __syncthreads();
    if (w == 0) {
        float a = (lane < 8) ? shs[lane] : 0.f;
        float b2 = (lane < 8) ? shs2[lane] : 0.f;
#pragma unroll
        for (int o = 4; o; o >>= 1) {
            a += __shfl_xor_sync(0xffffffffu, a, o);
            b2 += __shfl_xor_sync(0xffffffffu, b2, o);
        }
        if (lane == 0) { shs[0] = a; shs2[0] = b2; }
    }
    __syncthreads();
    float mu = shs[0] * (1.f / MLPH);
    float var = shs2[0] * (1.f / MLPH) - mu * mu;
    float inv = rsqrtf(var + 1e-5f);

    float4 wv = *(const float4*)(ln_w + tid * 4);
    float4 bv = *(const float4*)(ln_b + tid * 4);
    float4 r;
    r.x = (v.x - mu) * inv * wv.x + bv.x;
    r.y = (v.y - mu) * inv * wv.y + bv.y;
    r.z = (v.z - mu) * inv * wv.z + bv.z;
    r.w = (v.w - mu) * inv * wv.w + bv.w;
    *(float4*)(g_mlp + (size_t)bl * MLPH + tid * 4) = r;
}

// ---------------- two-stage mean-pool + head ----------------
__global__ void __launch_bounds__(256) pool1_kernel()
{
    int b = blockIdx.x, seg = blockIdx.y;
    int d = threadIdx.x;
    float s = 0.f;
    int t0 = seg * 128;
#pragma unroll 8
    for (int t = 0; t < 128; t++)
        s += g_h2[((size_t)(b * LSEQ + t0 + t)) * DMODEL + d];
    g_pool[(b * 16 + seg) * DMODEL + d] = s;
}

__global__ void __launch_bounds__(256) pool2_kernel(const float* __restrict__ head_w,
                                                    const float* __restrict__ head_b,
                                                    float* __restrict__ out)
{
    int b = blockIdx.x;
    int d = threadIdx.x;
    float s = 0.f;
#pragma unroll
    for (int seg = 0; seg < 16; seg++)
        s += g_pool[(b * 16 + seg) * DMODEL + d];
    __shared__ float pooled[DMODEL];
    pooled[d] = s * (1.f / LSEQ);
    __syncthreads();
    if (d < 2) {
        float accv = head_b[d];
        for (int j = 0; j < DMODEL; j++) accv += pooled[j] * head_w[d * DMODEL + j];
        out[b * 2 + d] = accv;
    }
}

// ---------------- host launcher ----------------
extern "C" void kernel_launch(void* const* d_in, const int* in_sizes, int n_in,
                              void* d_out, int out_size)
{
    (void)in_sizes; (void)n_in; (void)out_size;
    const float* x         = (const float*)d_in[0];
    const float* context   = (const float*)d_in[1];
    const float* in_proj_w = (const float*)d_in[2];
    const float* conv_w    = (const float*)d_in[3];
    const float* conv_b    = (const float*)d_in[4];
    const float* dt_bias   = (const float*)d_in[5];
    const float* A_log     = (const float*)d_in[6];
    const float* D_param   = (const float*)d_in[7];
    const float* norm_w    = (const float*)d_in[8];
    const float* out_proj_w= (const float*)d_in[9];
    const float* wq        = (const float*)d_in[10];
    const float* wk        = (const float*)d_in[11];
    const float* wv        = (const float*)d_in[12];
    const float* wo        = (const float*)d_in[13];
    const float* wo_b      = (const float*)d_in[14];
    const float* w1        = (const float*)d_in[15];
    const float* b1        = (const float*)d_in[16];
    const float* ln_w      = (const float*)d_in[17];
    const float* ln_b      = (const float*)d_in[18];
    const float* w2        = (const float*)d_in[19];
    const float* b2        = (const float*)d_in[20];
    const float* head_w    = (const float*)d_in[21];
    const float* head_b    = (const float*)d_in[22];
    float* out = (float*)d_out;

    float *p_zx, *p_y, *p_hres, *p_q, *p_k, *p_v, *p_o, *p_ob, *p_mlp, *p_h2;
    cudaGetSymbolAddress((void**)&p_zx,   g_zxbcdt);
    cudaGetSymbolAddress((void**)&p_y,    g_y);
    cudaGetSymbolAddress((void**)&p_hres, g_hres);
    cudaGetSymbolAddress((void**)&p_q,    g_q);
    cudaGetSymbolAddress((void**)&p_k,    g_k);
    cudaGetSymbolAddress((void**)&p_v,    g_v);
    cudaGetSymbolAddress((void**)&p_o,    g_o);
    cudaGetSymbolAddress((void**)&p_ob,   g_ob);
    cudaGetSymbolAddress((void**)&p_mlp,  g_mlp);
    cudaGetSymbolAddress((void**)&p_h2,   g_h2);

    // 1) in_proj (big tile)
    gemm128_kernel<EPI_NONE><<<dim3((DINPROJ + 127) / 128, M4 / 128), 256>>>(
        x, in_proj_w, nullptr, nullptr, p_zx, M4, DINPROJ, DMODEL);
    // 2) conv + dt/dA (16 timesteps per block)
    conv_dt_kernel<<<M4 / 16, CONVDIM>>>(conv_w, conv_b, dt_bias, A_log);
    // 3) chunked selective scan
    scan_chunk_kernel<<<16 * 8 * 2 * NCHUNK, 128>>>();
    combine_state_kernel<<<256, 256>>>();
    scan_fix_kernel<<<16 * 8 * 2 * (NCHUNK - 1), 128>>>();
    // 4) gate + RMSNorm
    gate_rms_kernel<<<M4, DINNER>>>(D_param, norm_w);
    // 5) out_proj + residual
    gemm_tf32_kernel<EPI_RES><<<dim3(DMODEL / 64, M4 / 64), 128>>>(
        p_y, out_proj_w, nullptr, x, p_hres, M4, DMODEL, DINNER);
    // 6) q, k, v
    gemm_tf32_kernel<EPI_NONE><<<dim3(DMODEL / 64, M4 / 64), 128>>>(
        p_hres, wq, nullptr, nullptr, p_q, M4, DMODEL, DMODEL);
    gemm_tf32_kernel<EPI_NONE><<<dim3(DMODEL / 64, M4 / 64), 128>>>(
        context, wk, nullptr, nullptr, p_k, M4, DMODEL, DMODEL);
    gemm_tf32_kernel<EPI_NONE><<<dim3(DMODEL / 64, M4 / 64), 128>>>(
        context, wv, nullptr, nullptr, p_v, M4, DMODEL, DMODEL);
    // 6b) pack attention operands once
    qk_pack_kernel<<<(M4 * DMODEL / 4) / 256, 256>>>();
    v_pack_kernel<<<(BBATCH * NHEADS * 1024 * 32) / 256, 256>>>();
    // 7) attention (128 queries per block)
    attn_mma_kernel<<<dim3(LSEQ / 128, NHEADS, BBATCH), 256>>>();
    // 8) attn out proj
    gemm_tf32_kernel<EPI_BIAS><<<dim3(DMODEL / 64, M4 / 64), 128>>>(
        p_o, wo, wo_b, nullptr, p_ob, M4, DMODEL, DMODEL);
    // 9) MLP fc1 + GELU (big tile)
    gemm128_kernel<EPI_BIAS_GELU><<<dim3(MLPH / 128, M4 / 128), 256>>>(
        p_ob, w1, b1, nullptr, p_mlp, M4, MLPH, DMODEL);
    // 10) LayerNorm
    layernorm_kernel<<<M4, 256>>>(ln_w, ln_b);
    // 11) MLP fc2
    gemm_tf32_kernel<EPI_BIAS><<<dim3(DMODEL / 64, M4 / 64), 128>>>(
        p_mlp, w2, b2, nullptr, p_h2, M4, DMODEL, MLPH);
    // 12) two-stage pool + head
    pool1_kernel<<<dim3(BBATCH, 16), 256>>>();
    pool2_kernel<<<BBATCH, 256>>>(head_w, head_b, out);
}

// round 7
// speedup vs baseline: 2.7999x; 1.1372x over previous
#include <cuda_runtime.h>
#include <cuda_bf16.h>
#include <math.h>

// ---------------- problem constants ----------------
#define BBATCH 2
#define LSEQ 2048
#define DMODEL 256
#define DINNER 512
#define DSTATE 128
#define NHEADS 8
#define HEADDIM 64
#define CONVDIM 768          // DINNER + 2*DSTATE
#define DINPROJ 1288         // 2*DINNER + 2*DSTATE + NHEADS
#define AHD 32               // attention head dim
#define MLPH 1024
#define M4 (BBATCH * LSEQ)   // 4096 rows
#define NCHUNK 32
#define CHUNK 64             // LSEQ / NCHUNK

// ---------------- scratch buffers ----------------
__device__ float g_zxbcdt[(size_t)M4 * DINPROJ];
__device__ float g_xBC[(size_t)M4 * CONVDIM];
__device__ float g_dt[M4 * NHEADS];
__device__ float g_dA[M4 * NHEADS];
__device__ float g_y[(size_t)M4 * DINNER];
__device__ float g_hres[(size_t)M4 * DMODEL];
__device__ float g_q[(size_t)M4 * DMODEL];
__device__ float g_k[(size_t)M4 * DMODEL];
__device__ float g_v[(size_t)M4 * DMODEL];
__device__ float g_o[(size_t)M4 * DMODEL];
__device__ float g_ob[(size_t)M4 * DMODEL];
__device__ float g_mlp[(size_t)M4 * MLPH];
__device__ float g_h2[(size_t)M4 * DMODEL];
// chunked-scan buffers
__device__ float g_state[(size_t)BBATCH * NHEADS * NCHUNK * HEADDIM * DSTATE];
__device__ float g_H0[(size_t)BBATCH * NHEADS * NCHUNK * HEADDIM * DSTATE];
__device__ float g_P[BBATCH * NHEADS * NCHUNK];
__device__ float g_cumA[BBATCH * NHEADS * LSEQ];
// attention packed operands
__device__ float g_qp[(size_t)M4 * DMODEL];
__device__ float g_kp[(size_t)M4 * DMODEL];
__device__ unsigned g_vhi[(size_t)BBATCH * NHEADS * 1024 * 32];
__device__ unsigned g_vlo[(size_t)BBATCH * NHEADS * 1024 * 32];
// pooling partials
__device__ float g_pool[BBATCH * 16 * DMODEL];

// ---------------- helpers ----------------
__device__ __forceinline__ float to_tf32(float x) {
    unsigned r;
    asm("cvt.rna.tf32.f32 %0, %1;" : "=r"(r) : "f"(x));
    return __uint_as_float(r);
}

__device__ __forceinline__ void mma_tf32(float c[4], const unsigned a[4],
                                         unsigned b0, unsigned b1) {
    asm volatile(
        "mma.sync.aligned.m16n8k8.row.col.f32.tf32.tf32.f32 "
        "{%0,%1,%2,%3},{%4,%5,%6,%7},{%8,%9},{%0,%1,%2,%3};"
        : "+f"(c[0]), "+f"(c[1]), "+f"(c[2]), "+f"(c[3])
        : "r"(a[0]), "r"(a[1]), "r"(a[2]), "r"(a[3]), "r"(b0), "r"(b1));
}

__device__ __forceinline__ void mma_bf16(float c[4], unsigned a0, unsigned a1,
                                         unsigned a2, unsigned a3,
                                         unsigned b0, unsigned b1) {
    asm volatile(
        "mma.sync.aligned.m16n8k16.row.col.f32.bf16.bf16.f32 "
        "{%0,%1,%2,%3},{%4,%5,%6,%7},{%8,%9},{%0,%1,%2,%3};"
        : "+f"(c[0]), "+f"(c[1]), "+f"(c[2]), "+f"(c[3])
        : "r"(a0), "r"(a1), "r"(a2), "r"(a3), "r"(b0), "r"(b1));
}

// split a pair of floats into bf16x2 hi + lo words
__device__ __forceinline__ void bf16_split2(float x, float y,
                                            unsigned& hi, unsigned& lo) {
    __nv_bfloat16 hx = __float2bfloat16_rn(x);
    __nv_bfloat16 hy = __float2bfloat16_rn(y);
    __nv_bfloat16 lx = __float2bfloat16_rn(x - __bfloat162float(hx));
    __nv_bfloat16 ly = __float2bfloat16_rn(y - __bfloat162float(hy));
    __nv_bfloat162 hh = __halves2bfloat162(hx, hy);
    __nv_bfloat162 ll = __halves2bfloat162(lx, ly);
    hi = *(unsigned*)&hh;
    lo = *(unsigned*)&ll;
}

// fast erf (Abramowitz-Stegun 7.1.26, abs err < 1.5e-7)
__device__ __forceinline__ float fast_erf(float x) {
    float ax = fabsf(x);
    float t = __frcp_rn(1.f + 0.3275911f * ax);
    float p = 1.061405429f;
    p = p * t - 1.453152027f;
    p = p * t + 1.421413741f;
    p = p * t - 0.284496736f;
    p = p * t + 0.254829592f;
    float r = 1.f - p * t * __expf(-ax * ax);
    return copysignf(r, x);
}
__device__ __forceinline__ float gelu(float v) {
    return 0.5f * v * (1.f + fast_erf(v * 0.70710678118f));
}

// ---------------- bf16 split GEMM (64x64 tile, double-buffered) -------------
// C = A @ W^T, A and W both split hi+lo bf16; 3 MMAs per K16 slab:
// AhWh + AhWl + AlWh (AlWl ~2^-16, dropped).
enum { EPI_NONE = 0, EPI_BIAS = 1, EPI_BIAS_GELU = 2, EPI_RES = 3 };

template <int EPI>
__global__ void __launch_bounds__(128)
gemm_bf16_kernel(const float* __restrict__ A, const float* __restrict__ W,
                 const float* __restrict__ bias, const float* __restrict__ res,
                 float* __restrict__ C, int M, int N, int K)
{
    __shared__ unsigned Ah[2][64][9], Al[2][64][9];
    __shared__ unsigned Wh[2][64][9], Wl[2][64][9];

    const int m0 = blockIdx.y * 64, n0 = blockIdx.x * 64;
    const int tid = threadIdx.x;
    const int w = tid >> 5, lane = tid & 31;
    const int qd = lane & 3, g = lane >> 2;
    const int wm = (w & 1) * 32, wn = (w >> 1) * 32;
    const int lrow = tid >> 2;        // 0..31
    const int lc4 = (tid & 3) * 4;    // 0,4,8,12  (K offsets)
    const int lp  = lc4 >> 1;         // pair index 0,2,4,6

    float c[2][4][4];
#pragma unroll
    for (int mt = 0; mt < 2; mt++)
#pragma unroll
        for (int nt = 0; nt < 4; nt++)
#pragma unroll
            for (int i = 0; i < 4; i++) c[mt][nt][i] = 0.f;

    const float* Aptr0 = A + (size_t)(m0 + lrow) * K + lc4;
    const float* Aptr1 = A + (size_t)(m0 + lrow + 32) * K + lc4;
    const bool wv0 = (n0 + lrow) < N;
    const bool wv1 = (n0 + lrow + 32) < N;
    const float* Wptr0 = W + (size_t)(wv0 ? (n0 + lrow) : 0) * K + lc4;
    const float* Wptr1 = W + (size_t)(wv1 ? (n0 + lrow + 32) : 0) * K + lc4;

    float4 pa0 = *(const float4*)Aptr0;
    float4 pa1 = *(const float4*)Aptr1;
    float4 pw0 = wv0 ? *(const float4*)Wptr0 : make_float4(0.f, 0.f, 0.f, 0.f);
    float4 pw1 = wv1 ? *(const float4*)Wptr1 : make_float4(0.f, 0.f, 0.f, 0.f);

    int buf = 0;
    for (int k0 = 0; k0 < K; k0 += 16) {
        unsigned hi, lo;
        bf16_split2(pa0.x, pa0.y, hi, lo); Ah[buf][lrow][lp] = hi; Al[buf][lrow][lp] = lo;
        bf16_split2(pa0.z, pa0.w, hi, lo); Ah[buf][lrow][lp + 1] = hi; Al[buf][lrow][lp + 1] = lo;
        bf16_split2(pa1.x, pa1.y, hi, lo); Ah[buf][lrow + 32][lp] = hi; Al[buf][lrow + 32][lp] = lo;
        bf16_split2(pa1.z, pa1.w, hi, lo); Ah[buf][lrow + 32][lp + 1] = hi; Al[buf][lrow + 32][lp + 1] = lo;
        bf16_split2(pw0.x, pw0.y, hi, lo); Wh[buf][lrow][lp] = hi; Wl[buf][lrow][lp] = lo;
        bf16_split2(pw0.z, pw0.w, hi, lo); Wh[buf][lrow][lp + 1] = hi; Wl[buf][lrow][lp + 1] = lo;
        bf16_split2(pw1.x, pw1.y, hi, lo); Wh[buf][lrow + 32][lp] = hi; Wl[buf][lrow + 32][lp] = lo;
        bf16_split2(pw1.z, pw1.w, hi, lo); Wh[buf][lrow + 32][lp + 1] = hi; Wl[buf][lrow + 32][lp + 1] = lo;
        __syncthreads();

        if (k0 + 16 < K) {
            pa0 = *(const float4*)(Aptr0 + k0 + 16);
            pa1 = *(const float4*)(Aptr1 + k0 + 16);
            pw0 = wv0 ? *(const float4*)(Wptr0 + k0 + 16) : make_float4(0.f, 0.f, 0.f, 0.f);
            pw1 = wv1 ? *(const float4*)(Wptr1 + k0 + 16) : make_float4(0.f, 0.f, 0.f, 0.f);
        }

        unsigned ah[2][4], al[2][4];
#pragma unroll
        for (int mt = 0; mt < 2; mt++) {
            int r = wm + mt * 16;
            ah[mt][0] = Ah[buf][r + g][qd];     ah[mt][1] = Ah[buf][r + g + 8][qd];
            ah[mt][2] = Ah[buf][r + g][qd + 4]; ah[mt][3] = Ah[buf][r + g + 8][qd + 4];
            al[mt][0] = Al[buf][r + g][qd];     al[mt][1] = Al[buf][r + g + 8][qd];
            al[mt][2] = Al[buf][r + g][qd + 4]; al[mt][3] = Al[buf][r + g + 8][qd + 4];
        }
#pragma unroll
        for (int nt = 0; nt < 4; nt++) {
            int cn = wn + nt * 8 + g;
            unsigned bh0 = Wh[buf][cn][qd], bh1 = Wh[buf][cn][qd + 4];
            unsigned bl0 = Wl[buf][cn][qd], bl1 = Wl[buf][cn][qd + 4];
#pragma unroll
            for (int mt = 0; mt < 2; mt++) {
                mma_bf16(c[mt][nt], ah[mt][0], ah[mt][1], ah[mt][2], ah[mt][3], bh0, bh1);
                mma_bf16(c[mt][nt], ah[mt][0], ah[mt][1], ah[mt][2], ah[mt][3], bl0, bl1);
                mma_bf16(c[mt][nt], al[mt][0], al[mt][1], al[mt][2], al[mt][3], bh0, bh1);
            }
        }
        buf ^= 1;
    }

#pragma unroll
    for (int mt = 0; mt < 2; mt++) {
#pragma unroll
        for (int nt = 0; nt < 4; nt++) {
            int row = m0 + wm + mt * 16 + g;
            int col = n0 + wn + nt * 8 + 2 * qd;
            if (col >= N) continue;
            float v0 = c[mt][nt][0], v1 = c[mt][nt][1];
            float v2 = c[mt][nt][2], v3 = c[mt][nt][3];
            if (EPI == EPI_BIAS || EPI == EPI_BIAS_GELU) {
                float2 bv = *(const float2*)(bias + col);
                v0 += bv.x; v1 += bv.y; v2 += bv.x; v3 += bv.y;
            }
            if (EPI == EPI_BIAS_GELU) {
                v0 = gelu(v0); v1 = gelu(v1); v2 = gelu(v2); v3 = gelu(v3);
            }
            if (EPI == EPI_RES) {
                float2 r0 = *(const float2*)(res + (size_t)row * N + col);
                float2 r1 = *(const float2*)(res + (size_t)(row + 8) * N + col);
                v0 += r0.x; v1 += r0.y; v2 += r1.x; v3 += r1.y;
            }
            *(float2*)(C + (size_t)row * N + col) = make_float2(v0, v1);
            *(float2*)(C + (size_t)(row + 8) * N + col) = make_float2(v2, v3);
        }
    }
}

// ---------------- bf16 split GEMM (128x128 tile, 256 threads) ----------------
template <int EPI>
__global__ void __launch_bounds__(256, 2)
gemm128_kernel(const float* __restrict__ A, const float* __restrict__ W,
               const float* __restrict__ bias, const float* __restrict__ res,
               float* __restrict__ C, int M, int N, int K)
{
    __shared__ unsigned Ah[128][9], Al[128][9];
    __shared__ unsigned Wh[128][9], Wl[128][9];

    const int m0 = blockIdx.y * 128, n0 = blockIdx.x * 128;
    const int tid = threadIdx.x;
    const int w = tid >> 5, lane = tid & 31;
    const int qd = lane & 3, g = lane >> 2;
    const int wm = (w & 1) * 64;
    const int wn = (w >> 1) * 32;
    const int lrow = tid >> 1;         // 0..127
    const int lc8 = (tid & 1) * 8;     // 0 or 8 (K offsets, 8 floats)
    const int lp  = lc8 >> 1;          // pair index 0 or 4

    float c[4][4][4];
#pragma unroll
    for (int mt = 0; mt < 4; mt++)
#pragma unroll
        for (int nt = 0; nt < 4; nt++)
#pragma unroll
            for (int i = 0; i < 4; i++) c[mt][nt][i] = 0.f;

    const float* Aptr = A + (size_t)(m0 + lrow) * K + lc8;
    const bool wvalid = (n0 + lrow) < N;
    const float* Wptr = W + (size_t)(wvalid ? (n0 + lrow) : 0) * K + lc8;

    float4 pa0 = *(const float4*)Aptr;
    float4 pa1 = *(const float4*)(Aptr + 4);
    float4 pw0 = wvalid ? *(const float4*)Wptr : make_float4(0.f, 0.f, 0.f, 0.f);
    float4 pw1 = wvalid ? *(const float4*)(Wptr + 4) : make_float4(0.f, 0.f, 0.f, 0.f);

    for (int k0 = 0; k0 < K; k0 += 16) {
        unsigned hi, lo;
        bf16_split2(pa0.x, pa0.y, hi, lo); Ah[lrow][lp] = hi;     Al[lrow][lp] = lo;
        bf16_split2(pa0.z, pa0.w, hi, lo); Ah[lrow][lp + 1] = hi; Al[lrow][lp + 1] = lo;
        bf16_split2(pa1.x, pa1.y, hi, lo); Ah[lrow][lp + 2] = hi; Al[lrow][lp + 2] = lo;
        bf16_split2(pa1.z, pa1.w, hi, lo); Ah[lrow][lp + 3] = hi; Al[lrow][lp + 3] = lo;
        bf16_split2(pw0.x, pw0.y, hi, lo); Wh[lrow][lp] = hi;     Wl[lrow][lp] = lo;
        bf16_split2(pw0.z, pw0.w, hi, lo); Wh[lrow][lp + 1] = hi; Wl[lrow][lp + 1] = lo;
        bf16_split2(pw1.x, pw1.y, hi, lo); Wh[lrow][lp + 2] = hi; Wl[lrow][lp + 2] = lo;
        bf16_split2(pw1.z, pw1.w, hi, lo); Wh[lrow][lp + 3] = hi; Wl[lrow][lp + 3] = lo;
        __syncthreads();

        if (k0 + 16 < K) {
            pa0 = *(const float4*)(Aptr + k0 + 16);
            pa1 = *(const float4*)(Aptr + k0 + 20);
            pw0 = wvalid ? *(const float4*)(Wptr + k0 + 16) : make_float4(0.f, 0.f, 0.f, 0.f);
            pw1 = wvalid ? *(const float4*)(Wptr + k0 + 20) : make_float4(0.f, 0.f, 0.f, 0.f);
        }

        unsigned ah[4][4], al[4][4];
#pragma unroll
        for (int mt = 0; mt < 4; mt++) {
            int r = wm + mt * 16;
            ah[mt][0] = Ah[r + g][qd];     ah[mt][1] = Ah[r + g + 8][qd];
            ah[mt][2] = Ah[r + g][qd + 4]; ah[mt][3] = Ah[r + g + 8][qd + 4];
            al[mt][0] = Al[r + g][qd];     al[mt][1] = Al[r + g + 8][qd];
            al[mt][2] = Al[r + g][qd + 4]; al[mt][3] = Al[r + g + 8][qd + 4];
        }
#pragma unroll
        for (int nt = 0; nt < 4; nt++) {
            int cn = wn + nt * 8 + g;
            unsigned bh0 = Wh[cn][qd], bh1 = Wh[cn][qd + 4];
            unsigned bl0 = Wl[cn][qd], bl1 = Wl[cn][qd + 4];
#pragma unroll
            for (int mt = 0; mt < 4; mt++) {
                mma_bf16(c[mt][nt], ah[mt][0], ah[mt][1], ah[mt][2], ah[mt][3], bh0, bh1);
                mma_bf16(c[mt][nt], ah[mt][0], ah[mt][1], ah[mt][2], ah[mt][3], bl0, bl1);
                mma_bf16(c[mt][nt], al[mt][0], al[mt][1], al[mt][2], al[mt][3], bh0, bh1);
            }
        }
        __syncthreads();
    }

#pragma unroll
    for (int mt = 0; mt < 4; mt++) {
#pragma unroll
        for (int nt = 0; nt < 4; nt++) {
            int row = m0 + wm + mt * 16 + g;
            int col = n0 + wn + nt * 8 + 2 * qd;
            if (col >= N) continue;
            float v0 = c[mt][nt][0], v1 = c[mt][nt][1];
            float v2 = c[mt][nt][2], v3 = c[mt][nt][3];
            if (EPI == EPI_BIAS || EPI == EPI_BIAS_GELU) {
                float2 bv = *(const float2*)(bias + col);
                v0 += bv.x; v1 += bv.y; v2 += bv.x; v3 += bv.y;
            }
            if (EPI == EPI_BIAS_GELU) {
                v0 = gelu(v0); v1 = gelu(v1); v2 = gelu(v2); v3 = gelu(v3);
            }
            if (EPI == EPI_RES) {
                float2 r0 = *(const float2*)(res + (size_t)row * N + col);
                float2 r1 = *(const float2*)(res + (size_t)(row + 8) * N + col);
                v0 += r0.x; v1 += r0.y; v2 += r1.x; v3 += r1.y;
            }
            *(float2*)(C + (size_t)row * N + col) = make_float2(v0, v1);
            *(float2*)(C + (size_t)(row + 8) * N + col) = make_float2(v2, v3);
        }
    }
}

// ---------------- conv1d: 16 timesteps per block, sliding register window ----
__global__ void __launch_bounds__(CONVDIM) conv_dt_kernel(
    const float* __restrict__ conv_w, const float* __restrict__ conv_b,
    const float* __restrict__ dt_bias, const float* __restrict__ A_log)
{
    int blk = blockIdx.x;
    int b = blk >> 7;
    int l0 = (blk & 127) << 4;
    int c = threadIdx.x;

    const float* src = g_zxbcdt + (size_t)b * LSEQ * DINPROJ + DINNER + c;
    float cw0 = conv_w[c * 4 + 0], cw1 = conv_w[c * 4 + 1];
    float cw2 = conv_w[c * 4 + 2], cw3 = conv_w[c * 4 + 3];
    float cb = conv_b[c];

    float x0 = 0.f, x1 = 0.f, x2 = 0.f;
    if (l0 >= 3) {
        x0 = src[(size_t)(l0 - 3) * DINPROJ];
        x1 = src[(size_t)(l0 - 2) * DINPROJ];
        x2 = src[(size_t)(l0 - 1) * DINPROJ];
    }
    float* dst = g_xBC + (size_t)(b * LSEQ + l0) * CONVDIM + c;
#pragma unroll
    for (int tl = 0; tl < 16; tl++) {
        float x3 = src[(size_t)(l0 + tl) * DINPROJ];
        float accv = cb + cw0 * x0 + cw1 * x1 + cw2 * x2 + cw3 * x3;
        dst[(size_t)tl * CONVDIM] = accv / (1.f + __expf(-accv));
        x0 = x1; x1 = x2; x2 = x3;
    }

    if (c < NHEADS) {
        float aexp = __expf(A_log[c]);
        float db = dt_bias[c];
        const float* dsrc = g_zxbcdt + (size_t)(b * LSEQ + l0) * DINPROJ + DINNER + CONVDIM + c;
#pragma unroll
        for (int tl = 0; tl < 16; tl++) {
            float v = dsrc[(size_t)tl * DINPROJ] + db;
            float dt = (v > 20.f) ? v : log1pf(__expf(v));
            int off = (b * LSEQ + l0 + tl) * NHEADS + c;
            g_dt[off] = dt;
            g_dA[off] = __expf(dt * -aexp);
        }
    }
}

// ---------------- chunked selective scan: pass A (4 p per warp) -------------
__global__ void __launch_bounds__(128) scan_chunk_kernel()
{
    int bidx = blockIdx.x;               // pg + 4*(h + 8*(b + 2*cch))
    int pg = bidx & 3;
    int h  = (bidx >> 2) & 7;
    int b  = (bidx >> 5) & 1;
    int cch = bidx >> 6;
    int warp = threadIdx.x >> 5;
    int lane = threadIdx.x & 31;
    int p0 = pg * 16 + warp * 4;         // this warp handles p0..p0+3
    int n0 = lane * 4;
    int bh = b * NHEADS + h;
    int t0 = cch * CHUNK;

    float4 hh[4];
#pragma unroll
    for (int j = 0; j < 4; j++) hh[j] = make_float4(0.f, 0.f, 0.f, 0.f);
    float prod = 1.f;

    const float* xbase = g_xBC + (size_t)b * LSEQ * CONVDIM;
    const float* dtb = g_dt + (size_t)b * LSEQ * NHEADS + h;
    const float* dab = g_dA + (size_t)b * LSEQ * NHEADS + h;
    float* yout = g_y + (size_t)b * LSEQ * DINNER + h * HEADDIM + p0;
    const int coff = h * HEADDIM + p0;

    for (int tl = 0; tl < CHUNK; tl++) {
        int t = t0 + tl;
        const float* row = xbase + (size_t)t * CONVDIM;
        float dA = dab[t * NHEADS];
        float dt = dtb[t * NHEADS];
        float4 xv = *(const float4*)(row + coff);
        float4 Bv = *(const float4*)(row + DINNER + n0);
        float4 Cv = *(const float4*)(row + DINNER + DSTATE + n0);
        float dtx[4] = {dt * xv.x, dt * xv.y, dt * xv.z, dt * xv.w};
        float acc[4];
#pragma unroll
        for (int j = 0; j < 4; j++) {
            hh[j].x = hh[j].x * dA + dtx[j] * Bv.x;
            hh[j].y = hh[j].y * dA + dtx[j] * Bv.y;
            hh[j].z = hh[j].z * dA + dtx[j] * Bv.z;
            hh[j].w = hh[j].w * dA + dtx[j] * Bv.w;
            acc[j] = hh[j].x * Cv.x + hh[j].y * Cv.y + hh[j].z * Cv.z + hh[j].w * Cv.w;
        }
        prod *= dA;
#pragma unroll
        for (int o = 16; o; o >>= 1) {
#pragma unroll
            for (int j = 0; j < 4; j++)
                acc[j] += __shfl_xor_sync(0xffffffffu, acc[j], o);
        }
        if (lane == 0) {
#pragma unroll
            for (int j = 0; j < 4; j++)
                yout[(size_t)t * DINNER + j] = acc[j];
        }
        if (threadIdx.x == 0 && pg == 0)
            g_cumA[(size_t)bh * LSEQ + t] = prod;
    }
#pragma unroll
    for (int j = 0; j < 4; j++)
        *(float4*)&g_state[(((size_t)bh * NCHUNK + cch) * HEADDIM + p0 + j) * DSTATE + n0] = hh[j];
    if (threadIdx.x == 0 && pg == 0)
        g_P[bh * NCHUNK + cch] = prod;
}

// ---------------- pass B: sequential combine with batched prefetch ----------
__global__ void __launch_bounds__(256) combine_state_kernel()
{
    int idx = blockIdx.x * blockDim.x + threadIdx.x;   // 0..65535
    int nq = idx & 63;
    int p  = (idx >> 6) & 63;
    int bh = idx >> 12;
    float2 H = make_float2(0.f, 0.f);
    const float* Pb = g_P + bh * NCHUNK;
    size_t base = (((size_t)bh * NCHUNK) * HEADDIM + p) * DSTATE + nq * 2;
    const size_t cstride = (size_t)HEADDIM * DSTATE;

    for (int cc0 = 0; cc0 < NCHUNK; cc0 += 8) {
        float2 S[8];
#pragma unroll
        for (int j = 0; j < 8; j++)
            S[j] = *(const float2*)&g_state[base + (size_t)(cc0 + j) * cstride];
#pragma unroll
        for (int j = 0; j < 8; j++) {
            *(float2*)&g_H0[base + (size_t)(cc0 + j) * cstride] = H;
            float P = Pb[cc0 + j];
            H.x = S[j].x + P * H.x;
            H.y = S[j].y + P * H.y;
        }
    }
}

// ---------------- pass C: correction y += cumA * (C · H0), 4 p per warp -----
__global__ void __launch_bounds__(128) scan_fix_kernel()
{
    int bidx = blockIdx.x;               // chunks 1..31
    int pg = bidx & 3;
    int h  = (bidx >> 2) & 7;
    int b  = (bidx >> 5) & 1;
    int cch = (bidx >> 6) + 1;
    int warp = threadIdx.x >> 5;
    int lane = threadIdx.x & 31;
    int p0 = pg * 16 + warp * 4;
    int n0 = lane * 4;
    int bh = b * NHEADS + h;
    int t0 = cch * CHUNK;

    float4 H[4];
#pragma unroll
    for (int j = 0; j < 4; j++)
        H[j] = *(const float4*)&g_H0[(((size_t)bh * NCHUNK + cch) * HEADDIM + p0 + j) * DSTATE + n0];

    const float* cb = g_xBC + (size_t)b * LSEQ * CONVDIM + DINNER + DSTATE + n0;
    const float* cum = g_cumA + (size_t)bh * LSEQ;
    float* yout = g_y + (size_t)b * LSEQ * DINNER + h * HEADDIM + p0;

    for (int tl = 0; tl < CHUNK; tl++) {
        int t = t0 + tl;
        float4 Cv = *(const float4*)(cb + (size_t)t * CONVDIM);
        float acc[4];
#pragma unroll
        for (int j = 0; j < 4; j++)
            acc[j] = H[j].x * Cv.x + H[j].y * Cv.y + H[j].z * Cv.z + H[j].w * Cv.w;
#pragma unroll
        for (int o = 16; o; o >>= 1) {
#pragma unroll
            for (int j = 0; j < 4; j++)
                acc[j] += __shfl_xor_sync(0xffffffffu, acc[j], o);
        }
        if (lane == 0) {
            float cm = cum[t];
#pragma unroll
            for (int j = 0; j < 4; j++)
                yout[(size_t)t * DINNER + j] += cm * acc[j];
        }
    }
}

// ---------------- gate + RMSNorm ----------------
__global__ void __launch_bounds__(512) gate_rms_kernel(const float* __restrict__ D_param,
                                                       const float* __restrict__ norm_w)
{
    int bl = blockIdx.x;
    int d = threadIdx.x;
    float y = g_y[(size_t)bl * DINNER + d] +
              D_param[d >> 6] * g_xBC[(size_t)bl * CONVDIM + d];
    float z = g_zxbcdt[(size_t)bl * DINPROJ + d];
    float g = y * (z / (1.f + __expf(-z)));

    __shared__ float sh[16];
    float s = g * g;
    int lane = d & 31, w = d >> 5;
#pragma unroll
    for (int o = 16; o; o >>= 1) s += __shfl_xor_sync(0xffffffffu, s, o);
    if (lane == 0) sh[w] = s;
    __syncthreads();
    if (w == 0) {
        float v = (lane < 16) ? sh[lane] : 0.f;
#pragma unroll
        for (int o = 16; o; o >>= 1) v += __shfl_xor_sync(0xffffffffu, v, o);
        if (lane == 0) sh[0] = v;
    }
    __syncthreads();
    float scale = rsqrtf(sh[0] * (1.f / DINNER) + 1e-5f);
    g_y[(size_t)bl * DINNER + d] = g * scale * norm_w[d];
}

// ---------------- attention operand packing ----------------
__global__ void __launch_bounds__(256) qk_pack_kernel()
{
    const float scale = 0.1767766953f;
    int idx = blockIdx.x * blockDim.x + threadIdx.x;
    float4 q = *(const float4*)(g_q + (size_t)idx * 4);
    float4 k = *(const float4*)(g_k + (size_t)idx * 4);
    float4 tq, tk;
    tq.x = to_tf32(q.x * scale); tq.y = to_tf32(q.y * scale);
    tq.z = to_tf32(q.z * scale); tq.w = to_tf32(q.w * scale);
    tk.x = to_tf32(k.x); tk.y = to_tf32(k.y);
    tk.z = to_tf32(k.z); tk.w = to_tf32(k.w);
    *(float4*)(g_qp + (size_t)idx * 4) = tq;
    *(float4*)(g_kp + (size_t)idx * 4) = tk;
}

__global__ void __launch_bounds__(256) v_pack_kernel()
{
    int idx = blockIdx.x * blockDim.x + threadIdx.x;
    int d  = idx & 31;
    int kp = (idx >> 5) & 1023;
    int h  = (idx >> 15) & 7;
    int b  = idx >> 18;
    size_t src = ((size_t)(b * LSEQ + 2 * kp)) * DMODEL + h * AHD + d;
    float v0 = g_v[src];
    float v1 = g_v[src + DMODEL];
    unsigned hi, lo;
    bf16_split2(v0, v1, hi, lo);
    g_vhi[idx] = hi;
    g_vlo[idx] = lo;
}

// ---------------- flash attention: 128 queries/block, 8 warps ---------------
__global__ void __launch_bounds__(256) attn_mma_kernel()
{
    __shared__ float Qs[128][40];
    __shared__ float Ks[64][40];
    __shared__ unsigned Vh[32][40];
    __shared__ unsigned Vl[32][40];

    const int q0 = blockIdx.x * 128;
    const int h = blockIdx.y;
    const int b = blockIdx.z;
    const int tid = threadIdx.x;
    const int w = tid >> 5, lane = tid & 31;
    const int qd = lane & 3, g = lane >> 2;

    const size_t base = (size_t)b * LSEQ * DMODEL + h * AHD;
    const unsigned* vhib = g_vhi + ((size_t)(b * NHEADS + h)) * 1024 * 32;
    const unsigned* vlob = g_vlo + ((size_t)(b * NHEADS + h)) * 1024 * 32;

#pragma unroll
    for (int i = 0; i < 4; i++) {
        int e = tid + i * 256;
        int row = e >> 3, c4 = (e & 7) * 4;
        *(float4*)&Qs[row][c4] =
            *(const float4*)(g_qp + base + (size_t)(q0 + row) * DMODEL + c4);
    }
    __syncthreads();

    unsigned qa[4][4];
#pragma unroll
    for (int ks = 0; ks < 4; ks++) {
        int r = w * 16;
        qa[ks][0] = __float_as_uint(Qs[r + g][8 * ks + qd]);
        qa[ks][1] = __float_as_uint(Qs[r + g + 8][8 * ks + qd]);
        qa[ks][2] = __float_as_uint(Qs[r + g][8 * ks + qd + 4]);
        qa[ks][3] = __float_as_uint(Qs[r + g + 8][8 * ks + qd + 4]);
    }

    float m0 = -1e30f, m1 = -1e30f, l0 = 0.f, l1 = 0.f;
    float o[4][4];
#pragma unroll
    for (int nt = 0; nt < 4; nt++)
#pragma unroll
        for (int i = 0; i < 4; i++) o[nt][i] = 0.f;

    for (int kt = 0; kt < LSEQ / 64; kt++) {
        __syncthreads();
#pragma unroll
        for (int i = 0; i < 2; i++) {
            int e = tid + i * 256;
            int row = e >> 3, c4 = (e & 7) * 4;
            *(float4*)&Ks[row][c4] =
                *(const float4*)(g_kp + base + (size_t)(kt * 64 + row) * DMODEL + c4);
        }
        {
            int kp = tid >> 3, q4 = (tid & 7) * 4;
            size_t gsrc = (size_t)(kt * 32 + kp) * 32 + q4;
            *(uint4*)&Vh[kp][q4] = *(const uint4*)(vhib + gsrc);
            *(uint4*)&Vl[kp][q4] = *(const uint4*)(vlob + gsrc);
        }
        __syncthreads();

        float s[8][4];
#pragma unroll
        for (int nt = 0; nt < 8; nt++)
#pragma unroll
            for (int i = 0; i < 4; i++) s[nt][i] = 0.f;
#pragma unroll
        for (int ks = 0; ks < 4; ks++) {
#pragma unroll
            for (int nt = 0; nt < 8; nt++) {
                unsigned b0 = __float_as_uint(Ks[nt * 8 + g][8 * ks + qd]);
                unsigned b1 = __float_as_uint(Ks[nt * 8 + g][8 * ks + qd + 4]);
                mma_tf32(s[nt], qa[ks], b0, b1);
            }
        }

        float r0 = -1e30f, r1 = -1e30f;
#pragma unroll
        for (int nt = 0; nt < 8; nt++) {
            r0 = fmaxf(r0, fmaxf(s[nt][0], s[nt][1]));
            r1 = fmaxf(r1, fmaxf(s[nt][2], s[nt][3]));
        }
        r0 = fmaxf(r0, __shfl_xor_sync(0xffffffffu, r0, 1));
        r0 = fmaxf(r0, __shfl_xor_sync(0xffffffffu, r0, 2));
        r1 = fmaxf(r1, __shfl_xor_sync(0xffffffffu, r1, 1));
        r1 = fmaxf(r1, __shfl_xor_sync(0xffffffffu, r1, 2));
        float nm0 = fmaxf(m0, r0), nm1 = fmaxf(m1, r1);
        float cf0 = __expf(m0 - nm0), cf1 = __expf(m1 - nm1);
        m0 = nm0; m1 = nm1;
        l0 *= cf0; l1 *= cf1;
#pragma unroll
        for (int nt = 0; nt < 4; nt++) {
            o[nt][0] *= cf0; o[nt][1] *= cf0;
            o[nt][2] *= cf1; o[nt][3] *= cf1;
        }

        unsigned plo[8], phi[8];
#pragma unroll
        for (int nt = 0; nt < 8; nt++) {
            float p0 = __expf(s[nt][0] - m0);
            float p1 = __expf(s[nt][1] - m0);
            float p2 = __expf(s[nt][2] - m1);
            float p3 = __expf(s[nt][3] - m1);
            l0 += p0 + p1;
            l1 += p2 + p3;
            __nv_bfloat162 lo = __floats2bfloat162_rn(p0, p1);
            __nv_bfloat162 hi = __floats2bfloat162_rn(p2, p3);
            plo[nt] = *(unsigned*)&lo;
            phi[nt] = *(unsigned*)&hi;
        }

#pragma unroll
        for (int kk = 0; kk < 4; kk++) {
            unsigned a0 = plo[2 * kk], a1 = phi[2 * kk];
            unsigned a2 = plo[2 * kk + 1], a3 = phi[2 * kk + 1];
#pragma unroll
            for (int nt = 0; nt < 4; nt++) {
                unsigned bh0 = Vh[kk * 8 + qd][nt * 8 + g];
                unsigned bh1 = Vh[kk * 8 + qd + 4][nt * 8 + g];
                mma_bf16(o[nt], a0, a1, a2, a3, bh0, bh1);
                unsigned bl0 = Vl[kk * 8 + qd][nt * 8 + g];
                unsigned bl1 = Vl[kk * 8 + qd + 4][nt * 8 + g];
                mma_bf16(o[nt], a0, a1, a2, a3, bl0, bl1);
            }
        }
    }

    l0 += __shfl_xor_sync(0xffffffffu, l0, 1);
    l0 += __shfl_xor_sync(0xffffffffu, l0, 2);
    l1 += __shfl_xor_sync(0xffffffffu, l1, 1);
    l1 += __shfl_xor_sync(0xffffffffu, l1, 2);

    float inv0 = 1.f / l0, inv1 = 1.f / l1;
    int row = q0 + w * 16 + g;
#pragma unroll
    for (int nt = 0; nt < 4; nt++) {
        int col = h * AHD + nt * 8 + 2 * qd;
        *(float2*)(g_o + (size_t)(b * LSEQ + row) * DMODEL + col) =
            make_float2(o[nt][0] * inv0, o[nt][1] * inv0);
        *(float2*)(g_o + (size_t)(b * LSEQ + row + 8) * DMODEL + col) =
            make_float2(o[nt][2] * inv1, o[nt][3] * inv1);
    }
}

// ---------------- LayerNorm over 1024 ----------------
__global__ void __launch_bounds__(256) layernorm_kernel(const float* __restrict__ ln_w,
                                                        const float* __restrict__ ln_b)
{
    int bl = blockIdx.x, tid = threadIdx.x;
    float4 v = *(const float4*)(g_mlp + (size_t)bl * MLPH + tid * 4);
    float s = v.x + v.y + v.z + v.w;
    float s2 = v.x * v.x + v.y * v.y + v.z * v.z + v.w * v.w;

    __shared__ float shs[8], shs2[8];
    int lane = tid & 31, w = tid >> 5;
#pragma unroll
    for (int o = 16; o; o >>= 1) {
        s += __shfl_xor_sync(0xffffffffu, s, o);
        s2 += __shfl_xor_sync(0xffffffffu, s2, o);
    }
    if (lane == 0) { shs[w] = s; shs2[w] = s2; }
    __syncthreads();
    if (w == 0) {
        float a = (lane < 8) ? shs[lane] : 0.f;
        float b2 = (lane < 8) ? shs2[lane] : 0.f;
#pragma unroll
        for (int o = 4; o; o >>= 1) {
            a += __shfl_xor_sync(0xffffffffu, a, o);
            b2 += __shfl_xor_sync(0xffffffffu, b2, o);
        }
        if (lane == 0) { shs[0] = a; shs2[0] = b2; }
    }
    __syncthreads();
    float mu = shs[0] * (1.f / MLPH);
    float var = shs2[0] * (1.f / MLPH) - mu * mu;
    float inv = rsqrtf(var + 1e-5f);

    float4 wv = *(const float4*)(ln_w + tid * 4);
    float4 bv = *(const float4*)(ln_b + tid * 4);
    float4 r;
    r.x = (v.x - mu) * inv * wv.x + bv.x;
    r.y = (v.y - mu) * inv * wv.y + bv.y;
    r.z = (v.z - mu) * inv * wv.z + bv.z;
    r.w = (v.w - mu) * inv * wv.w + bv.w;
    *(float4*)(g_mlp + (size_t)bl * MLPH + tid * 4) = r;
}

// ---------------- two-stage mean-pool + head ----------------
__global__ void __launch_bounds__(256) pool1_kernel()
{
    int b = blockIdx.x, seg = blockIdx.y;
    int d = threadIdx.x;
    float s = 0.f;
    int t0 = seg * 128;
#pragma unroll 8
    for (int t = 0; t < 128; t++)
        s += g_h2[((size_t)(b * LSEQ + t0 + t)) * DMODEL + d];
    g_pool[(b * 16 + seg) * DMODEL + d] = s;
}

__global__ void __launch_bounds__(256) pool2_kernel(const float* __restrict__ head_w,
                                                    const float* __restrict__ head_b,
                                                    float* __restrict__ out)
{
    int b = blockIdx.x;
    int d = threadIdx.x;
    float s = 0.f;
#pragma unroll
    for (int seg = 0; seg < 16; seg++)
        s += g_pool[(b * 16 + seg) * DMODEL + d];
    __shared__ float pooled[DMODEL];
    pooled[d] = s * (1.f / LSEQ);
    __syncthreads();
    if (d < 2) {
        float accv = head_b[d];
        for (int j = 0; j < DMODEL; j++) accv += pooled[j] * head_w[d * DMODEL + j];
        out[b * 2 + d] = accv;
    }
}

// ---------------- host launcher ----------------
extern "C" void kernel_launch(void* const* d_in, const int* in_sizes, int n_in,
                              void* d_out, int out_size)
{
    (void)in_sizes; (void)n_in; (void)out_size;
    const float* x         = (const float*)d_in[0];
    const float* context   = (const float*)d_in[1];
    const float* in_proj_w = (const float*)d_in[2];
    const float* conv_w    = (const float*)d_in[3];
    const float* conv_b    = (const float*)d_in[4];
    const float* dt_bias   = (const float*)d_in[5];
    const float* A_log     = (const float*)d_in[6];
    const float* D_param   = (const float*)d_in[7];
    const float* norm_w    = (const float*)d_in[8];
    const float* out_proj_w= (const float*)d_in[9];
    const float* wq        = (const float*)d_in[10];
    const float* wk        = (const float*)d_in[11];
    const float* wv        = (const float*)d_in[12];
    const float* wo        = (const float*)d_in[13];
    const float* wo_b      = (const float*)d_in[14];
    const float* w1        = (const float*)d_in[15];
    const float* b1        = (const float*)d_in[16];
    const float* ln_w      = (const float*)d_in[17];
    const float* ln_b      = (const float*)d_in[18];
    const float* w2        = (const float*)d_in[19];
    const float* b2        = (const float*)d_in[20];
    const float* head_w    = (const float*)d_in[21];
    const float* head_b    = (const float*)d_in[22];
    float* out = (float*)d_out;

    float *p_zx, *p_y, *p_hres, *p_q, *p_k, *p_v, *p_o, *p_ob, *p_mlp, *p_h2;
    cudaGetSymbolAddress((void**)&p_zx,   g_zxbcdt);
    cudaGetSymbolAddress((void**)&p_y,    g_y);
    cudaGetSymbolAddress((void**)&p_hres, g_hres);
    cudaGetSymbolAddress((void**)&p_q,    g_q);
    cudaGetSymbolAddress((void**)&p_k,    g_k);
    cudaGetSymbolAddress((void**)&p_v,    g_v);
    cudaGetSymbolAddress((void**)&p_o,    g_o);
    cudaGetSymbolAddress((void**)&p_ob,   g_ob);
    cudaGetSymbolAddress((void**)&p_mlp,  g_mlp);
    cudaGetSymbolAddress((void**)&p_h2,   g_h2);

    // 1) in_proj (big tile)
    gemm128_kernel<EPI_NONE><<<dim3((DINPROJ + 127) / 128, M4 / 128), 256>>>(
        x, in_proj_w, nullptr, nullptr, p_zx, M4, DINPROJ, DMODEL);
    // 2) conv + dt/dA
    conv_dt_kernel<<<M4 / 16, CONVDIM>>>(conv_w, conv_b, dt_bias, A_log);
    // 3) chunked selective scan (4 p per warp)
    scan_chunk_kernel<<<4 * 8 * 2 * NCHUNK, 128>>>();
    combine_state_kernel<<<256, 256>>>();
    scan_fix_kernel<<<4 * 8 * 2 * (NCHUNK - 1), 128>>>();
    // 4) gate + RMSNorm
    gate_rms_kernel<<<M4, DINNER>>>(D_param, norm_w);
    // 5) out_proj + residual
    gemm_bf16_kernel<EPI_RES><<<dim3(DMODEL / 64, M4 / 64), 128>>>(
        p_y, out_proj_w, nullptr, x, p_hres, M4, DMODEL, DINNER);
    // 6) q, k, v
    gemm_bf16_kernel<EPI_NONE><<<dim3(DMODEL / 64, M4 / 64), 128>>>(
        p_hres, wq, nullptr, nullptr, p_q, M4, DMODEL, DMODEL);
    gemm_bf16_kernel<EPI_NONE><<<dim3(DMODEL / 64, M4 / 64), 128>>>(
        context, wk, nullptr, nullptr, p_k, M4, DMODEL, DMODEL);
    gemm_bf16_kernel<EPI_NONE><<<dim3(DMODEL / 64, M4 / 64), 128>>>(
        context, wv, nullptr, nullptr, p_v, M4, DMODEL, DMODEL);
    // 6b) pack attention operands once
    qk_pack_kernel<<<(M4 * DMODEL / 4) / 256, 256>>>();
    v_pack_kernel<<<(BBATCH * NHEADS * 1024 * 32) / 256, 256>>>();
    // 7) attention
    attn_mma_kernel<<<dim3(LSEQ / 128, NHEADS, BBATCH), 256>>>();
    // 8) attn out proj
    gemm_bf16_kernel<EPI_BIAS><<<dim3(DMODEL / 64, M4 / 64), 128>>>(
        p_o, wo, wo_b, nullptr, p_ob, M4, DMODEL, DMODEL);
    // 9) MLP fc1 + GELU (big tile)
    gemm128_kernel<EPI_BIAS_GELU><<<dim3(MLPH / 128, M4 / 128), 256>>>(
        p_ob, w1, b1, nullptr, p_mlp, M4, MLPH, DMODEL);
    // 10) LayerNorm
    layernorm_kernel<<<M4, 256>>>(ln_w, ln_b);
    // 11) MLP fc2
    gemm_bf16_kernel<EPI_BIAS><<<dim3(DMODEL / 64, M4 / 64), 128>>>(
        p_mlp, w2, b2, nullptr, p_h2, M4, DMODEL, MLPH);
    // 12) two-stage pool + head
    pool1_kernel<<<dim3(BBATCH, 16), 256>>>();
    pool2_kernel<<<BBATCH, 256>>>(head_w, head_b, out);
}

// round 9
// speedup vs baseline: 2.8101x; 1.0036x over previous
#include <cuda_runtime.h>
#include <cuda_bf16.h>
#include <math.h>

// ---------------- problem constants ----------------
#define BBATCH 2
#define LSEQ 2048
#define DMODEL 256
#define DINNER 512
#define DSTATE 128
#define NHEADS 8
#define HEADDIM 64
#define CONVDIM 768          // DINNER + 2*DSTATE
#define DINPROJ 1288         // 2*DINNER + 2*DSTATE + NHEADS
#define AHD 32               // attention head dim
#define MLPH 1024
#define M4 (BBATCH * LSEQ)   // 4096 rows
#define NCHUNK 32
#define CHUNK 64             // LSEQ / NCHUNK

// pre-split weight region offsets (in bf16x2-pair units; region K2 = K/2)
#define WOFF_INPROJ 0          // N=1288 K2=128
#define WOFF_OUTPROJ 164864    // N=256  K2=256
#define WOFF_WQ 230400         // N=256  K2=128
#define WOFF_WK 263168         // N=256  K2=128  (wv follows contiguously)
#define WOFF_WV 295936         // N=256  K2=128
#define WOFF_WO 328704         // N=256  K2=128
#define WOFF_W1 361472         // N=1024 K2=128
#define WOFF_W2 492544         // N=256  K2=512
#define WTOTAL 623616

// ---------------- scratch buffers ----------------
__device__ float g_zxbcdt[(size_t)M4 * DINPROJ];
__device__ float g_xBC[(size_t)M4 * CONVDIM];
__device__ float g_dt[M4 * NHEADS];
__device__ float g_dA[M4 * NHEADS];
__device__ float g_y[(size_t)M4 * DINNER];
__device__ float g_hres[(size_t)M4 * DMODEL];
__device__ float g_v[(size_t)M4 * DMODEL];
__device__ float g_o[(size_t)M4 * DMODEL];
__device__ float g_ob[(size_t)M4 * DMODEL];
__device__ float g_mlp[(size_t)M4 * MLPH];
__device__ float g_h2[(size_t)M4 * DMODEL];
// chunked-scan buffers
__device__ float g_state[(size_t)BBATCH * NHEADS * NCHUNK * HEADDIM * DSTATE];
__device__ float g_H0[(size_t)BBATCH * NHEADS * NCHUNK * HEADDIM * DSTATE];
__device__ float g_P[BBATCH * NHEADS * NCHUNK];
__device__ float g_cumA[BBATCH * NHEADS * LSEQ];
// attention packed operands
__device__ float g_qp[(size_t)M4 * DMODEL];
__device__ float g_kp[(size_t)M4 * DMODEL];
__device__ unsigned g_vhi[(size_t)BBATCH * NHEADS * 1024 * 32];
__device__ unsigned g_vlo[(size_t)BBATCH * NHEADS * 1024 * 32];
// pooling partials
__device__ float g_pool[BBATCH * 16 * DMODEL];
// pre-split weights (bf16x2 hi / lo)
__device__ unsigned g_whi[WTOTAL + 64];
__device__ unsigned g_wlo[WTOTAL + 64];

// ---------------- helpers ----------------
__device__ __forceinline__ float to_tf32(float x) {
    unsigned r;
    asm("cvt.rna.tf32.f32 %0, %1;" : "=r"(r) : "f"(x));
    return __uint_as_float(r);
}

__device__ __forceinline__ void mma_tf32(float c[4], const unsigned a[4],
                                         unsigned b0, unsigned b1) {
    asm volatile(
        "mma.sync.aligned.m16n8k8.row.col.f32.tf32.tf32.f32 "
        "{%0,%1,%2,%3},{%4,%5,%6,%7},{%8,%9},{%0,%1,%2,%3};"
        : "+f"(c[0]), "+f"(c[1]), "+f"(c[2]), "+f"(c[3])
        : "r"(a[0]), "r"(a[1]), "r"(a[2]), "r"(a[3]), "r"(b0), "r"(b1));
}

__device__ __forceinline__ void mma_bf16(float c[4], unsigned a0, unsigned a1,
                                         unsigned a2, unsigned a3,
                                         unsigned b0, unsigned b1) {
    asm volatile(
        "mma.sync.aligned.m16n8k16.row.col.f32.bf16.bf16.f32 "
        "{%0,%1,%2,%3},{%4,%5,%6,%7},{%8,%9},{%0,%1,%2,%3};"
        : "+f"(c[0]), "+f"(c[1]), "+f"(c[2]), "+f"(c[3])
        : "r"(a0), "r"(a1), "r"(a2), "r"(a3), "r"(b0), "r"(b1));
}

// split a pair of floats into bf16x2 hi + lo words
__device__ __forceinline__ void bf16_split2(float x, float y,
                                            unsigned& hi, unsigned& lo) {
    __nv_bfloat16 hx = __float2bfloat16_rn(x);
    __nv_bfloat16 hy = __float2bfloat16_rn(y);
    __nv_bfloat16 lx = __float2bfloat16_rn(x - __bfloat162float(hx));
    __nv_bfloat16 ly = __float2bfloat16_rn(y - __bfloat162float(hy));
    __nv_bfloat162 hh = __halves2bfloat162(hx, hy);
    __nv_bfloat162 ll = __halves2bfloat162(lx, ly);
    hi = *(unsigned*)&hh;
    lo = *(unsigned*)&ll;
}

// fast erf (Abramowitz-Stegun 7.1.26, abs err < 1.5e-7)
__device__ __forceinline__ float fast_erf(float x) {
    float ax = fabsf(x);
    float t = __frcp_rn(1.f + 0.3275911f * ax);
    float p = 1.061405429f;
    p = p * t - 1.453152027f;
    p = p * t + 1.421413741f;
    p = p * t - 0.284496736f;
    p = p * t + 0.254829592f;
    float r = 1.f - p * t * __expf(-ax * ax);
    return copysignf(r, x);
}
__device__ __forceinline__ float gelu(float v) {
    return 0.5f * v * (1.f + fast_erf(v * 0.70710678118f));
}

// ---------------- weight pre-split pack (runs once per launch) --------------
__global__ void __launch_bounds__(256) pack_w_kernel(
    const float* __restrict__ in_proj_w, const float* __restrict__ out_proj_w,
    const float* __restrict__ wq, const float* __restrict__ wk,
    const float* __restrict__ wv, const float* __restrict__ wo,
    const float* __restrict__ w1, const float* __restrict__ w2)
{
    int idx = blockIdx.x * 256 + threadIdx.x;
    if (idx >= WTOTAL) return;
    const float* src;
    int off, K2;
    if (idx < WOFF_OUTPROJ)      { src = in_proj_w;  off = WOFF_INPROJ;  K2 = 128; }
    else if (idx < WOFF_WQ)      { src = out_proj_w; off = WOFF_OUTPROJ; K2 = 256; }
    else if (idx < WOFF_WK)      { src = wq;         off = WOFF_WQ;      K2 = 128; }
    else if (idx < WOFF_WV)      { src = wk;         off = WOFF_WK;      K2 = 128; }
    else if (idx < WOFF_WO)      { src = wv;         off = WOFF_WV;      K2 = 128; }
    else if (idx < WOFF_W1)      { src = wo;         off = WOFF_WO;      K2 = 128; }
    else if (idx < WOFF_W2)      { src = w1;         off = WOFF_W1;      K2 = 128; }
    else                         { src = w2;         off = WOFF_W2;      K2 = 512; }
    int loc = idx - off;
    int n = loc / K2, kp = loc - n * K2;
    float x0 = src[(size_t)n * (K2 * 2) + 2 * kp];
    float x1 = src[(size_t)n * (K2 * 2) + 2 * kp + 1];
    unsigned hi, lo;
    bf16_split2(x0, x1, hi, lo);
    g_whi[idx] = hi;
    g_wlo[idx] = lo;
}

// ---------------- bf16 split GEMM (64x64 tile, double-buffered) -------------
// C = A @ W^T; A split in-loop, W pre-split in global memory.
// 3 MMAs per K16 slab: AhWh + AhWl + AlWh.
enum { EPI_NONE = 0, EPI_BIAS = 1, EPI_BIAS_GELU = 2, EPI_RES = 3,
       EPI_QPACK = 4, EPI_KV = 5 };

template <int EPI>
__global__ void __launch_bounds__(128)
gemm_bf16_kernel(const float* __restrict__ A,
                 const unsigned* __restrict__ Whig, const unsigned* __restrict__ Wlog,
                 const float* __restrict__ bias, const float* __restrict__ res,
                 float* __restrict__ C, float* __restrict__ C2,
                 int M, int N, int K)
{
    __shared__ unsigned Ah[2][64][9], Al[2][64][9];
    __shared__ unsigned Wh[2][64][9], Wl[2][64][9];

    const int K2 = K >> 1;
    const int m0 = blockIdx.y * 64, n0 = blockIdx.x * 64;
    const int tid = threadIdx.x;
    const int w = tid >> 5, lane = tid & 31;
    const int qd = lane & 3, g = lane >> 2;
    const int wm = (w & 1) * 32, wn = (w >> 1) * 32;
    const int lrow = tid >> 2;        // 0..31
    const int lc4 = (tid & 3) * 4;    // K float offsets 0,4,8,12
    const int lp  = lc4 >> 1;         // pair index 0,2,4,6

    float c[2][4][4];
#pragma unroll
    for (int mt = 0; mt < 2; mt++)
#pragma unroll
        for (int nt = 0; nt < 4; nt++)
#pragma unroll
            for (int i = 0; i < 4; i++) c[mt][nt][i] = 0.f;

    const float* Aptr0 = A + (size_t)(m0 + lrow) * K + lc4;
    const float* Aptr1 = A + (size_t)(m0 + lrow + 32) * K + lc4;
    const bool wv0 = (n0 + lrow) < N;
    const bool wv1 = (n0 + lrow + 32) < N;
    const unsigned* Whp0 = Whig + (size_t)(wv0 ? (n0 + lrow) : 0) * K2 + lp;
    const unsigned* Wlp0 = Wlog + (size_t)(wv0 ? (n0 + lrow) : 0) * K2 + lp;
    const unsigned* Whp1 = Whig + (size_t)(wv1 ? (n0 + lrow + 32) : 0) * K2 + lp;
    const unsigned* Wlp1 = Wlog + (size_t)(wv1 ? (n0 + lrow + 32) : 0) * K2 + lp;

    float4 pa0 = *(const float4*)Aptr0;
    float4 pa1 = *(const float4*)Aptr1;
    uint2 ph0 = *(const uint2*)Whp0;
    uint2 pl0 = *(const uint2*)Wlp0;
    uint2 ph1 = *(const uint2*)Whp1;
    uint2 pl1 = *(const uint2*)Wlp1;

    int buf = 0;
    for (int k0 = 0; k0 < K; k0 += 16) {
        unsigned hi, lo;
        bf16_split2(pa0.x, pa0.y, hi, lo); Ah[buf][lrow][lp] = hi; Al[buf][lrow][lp] = lo;
        bf16_split2(pa0.z, pa0.w, hi, lo); Ah[buf][lrow][lp + 1] = hi; Al[buf][lrow][lp + 1] = lo;
        bf16_split2(pa1.x, pa1.y, hi, lo); Ah[buf][lrow + 32][lp] = hi; Al[buf][lrow + 32][lp] = lo;
        bf16_split2(pa1.z, pa1.w, hi, lo); Ah[buf][lrow + 32][lp + 1] = hi; Al[buf][lrow + 32][lp + 1] = lo;
        Wh[buf][lrow][lp] = ph0.x;      Wh[buf][lrow][lp + 1] = ph0.y;
        Wl[buf][lrow][lp] = pl0.x;      Wl[buf][lrow][lp + 1] = pl0.y;
        Wh[buf][lrow + 32][lp] = ph1.x; Wh[buf][lrow + 32][lp + 1] = ph1.y;
        Wl[buf][lrow + 32][lp] = pl1.x; Wl[buf][lrow + 32][lp + 1] = pl1.y;
        __syncthreads();

        if (k0 + 16 < K) {
            int kpn = (k0 + 16) >> 1;
            pa0 = *(const float4*)(Aptr0 + k0 + 16);
            pa1 = *(const float4*)(Aptr1 + k0 + 16);
            ph0 = *(const uint2*)(Whp0 + kpn);
            pl0 = *(const uint2*)(Wlp0 + kpn);
            ph1 = *(const uint2*)(Whp1 + kpn);
            pl1 = *(const uint2*)(Wlp1 + kpn);
        }

        unsigned ah[2][4], al[2][4];
#pragma unroll
        for (int mt = 0; mt < 2; mt++) {
            int r = wm + mt * 16;
            ah[mt][0] = Ah[buf][r + g][qd];     ah[mt][1] = Ah[buf][r + g + 8][qd];
            ah[mt][2] = Ah[buf][r + g][qd + 4]; ah[mt][3] = Ah[buf][r + g + 8][qd + 4];
            al[mt][0] = Al[buf][r + g][qd];     al[mt][1] = Al[buf][r + g + 8][qd];
            al[mt][2] = Al[buf][r + g][qd + 4]; al[mt][3] = Al[buf][r + g + 8][qd + 4];
        }
#pragma unroll
        for (int nt = 0; nt < 4; nt++) {
            int cn = wn + nt * 8 + g;
            unsigned bh0 = Wh[buf][cn][qd], bh1 = Wh[buf][cn][qd + 4];
            unsigned bl0 = Wl[buf][cn][qd], bl1 = Wl[buf][cn][qd + 4];
#pragma unroll
            for (int mt = 0; mt < 2; mt++) {
                mma_bf16(c[mt][nt], ah[mt][0], ah[mt][1], ah[mt][2], ah[mt][3], bh0, bh1);
                mma_bf16(c[mt][nt], ah[mt][0], ah[mt][1], ah[mt][2], ah[mt][3], bl0, bl1);
                mma_bf16(c[mt][nt], al[mt][0], al[mt][1], al[mt][2], al[mt][3], bh0, bh1);
            }
        }
        buf ^= 1;
    }

    const float qs = 0.1767766953f;   // 1/sqrt(32)
#pragma unroll
    for (int mt = 0; mt < 2; mt++) {
#pragma unroll
        for (int nt = 0; nt < 4; nt++) {
            int row = m0 + wm + mt * 16 + g;
            int col = n0 + wn + nt * 8 + 2 * qd;
            if (col >= N) continue;
            float v0 = c[mt][nt][0], v1 = c[mt][nt][1];
            float v2 = c[mt][nt][2], v3 = c[mt][nt][3];
            if (EPI == EPI_BIAS || EPI == EPI_BIAS_GELU) {
                float2 bv = *(const float2*)(bias + col);
                v0 += bv.x; v1 += bv.y; v2 += bv.x; v3 += bv.y;
            }
            if (EPI == EPI_BIAS_GELU) {
                v0 = gelu(v0); v1 = gelu(v1); v2 = gelu(v2); v3 = gelu(v3);
            }
            if (EPI == EPI_RES) {
                float2 r0 = *(const float2*)(res + (size_t)row * N + col);
                float2 r1 = *(const float2*)(res + (size_t)(row + 8) * N + col);
                v0 += r0.x; v1 += r0.y; v2 += r1.x; v3 += r1.y;
            }
            if (EPI == EPI_QPACK) {
                *(float2*)(C + (size_t)row * N + col) =
                    make_float2(to_tf32(v0 * qs), to_tf32(v1 * qs));
                *(float2*)(C + (size_t)(row + 8) * N + col) =
                    make_float2(to_tf32(v2 * qs), to_tf32(v3 * qs));
            } else if (EPI == EPI_KV) {
                if (col < DMODEL) {      // K half -> tf32 to g_kp
                    *(float2*)(C + (size_t)row * DMODEL + col) =
                        make_float2(to_tf32(v0), to_tf32(v1));
                    *(float2*)(C + (size_t)(row + 8) * DMODEL + col) =
                        make_float2(to_tf32(v2), to_tf32(v3));
                } else {                 // V half -> raw fp32 to g_v
                    *(float2*)(C2 + (size_t)row * DMODEL + col - DMODEL) =
                        make_float2(v0, v1);
                    *(float2*)(C2 + (size_t)(row + 8) * DMODEL + col - DMODEL) =
                        make_float2(v2, v3);
                }
            } else {
                *(float2*)(C + (size_t)row * N + col) = make_float2(v0, v1);
                *(float2*)(C + (size_t)(row + 8) * N + col) = make_float2(v2, v3);
            }
        }
    }
}

// ---------------- bf16 split GEMM (128x128 tile, 256 threads) ----------------
template <int EPI>
__global__ void __launch_bounds__(256, 2)
gemm128_kernel(const float* __restrict__ A,
               const unsigned* __restrict__ Whig, const unsigned* __restrict__ Wlog,
               const float* __restrict__ bias, const float* __restrict__ res,
               float* __restrict__ C, int M, int N, int K)
{
    __shared__ unsigned Ah[128][9], Al[128][9];
    __shared__ unsigned Wh[128][9], Wl[128][9];

    const int K2 = K >> 1;
    const int m0 = blockIdx.y * 128, n0 = blockIdx.x * 128;
    const int tid = threadIdx.x;
    const int w = tid >> 5, lane = tid & 31;
    const int qd = lane & 3, g = lane >> 2;
    const int wm = (w & 1) * 64;
    const int wn = (w >> 1) * 32;
    const int lrow = tid >> 1;         // 0..127
    const int lc8 = (tid & 1) * 8;     // 0 or 8 (K floats)
    const int lp  = lc8 >> 1;          // pair index 0 or 4

    float c[4][4][4];
#pragma unroll
    for (int mt = 0; mt < 4; mt++)
#pragma unroll
        for (int nt = 0; nt < 4; nt++)
#pragma unroll
            for (int i = 0; i < 4; i++) c[mt][nt][i] = 0.f;

    const float* Aptr = A + (size_t)(m0 + lrow) * K + lc8;
    const bool wvalid = (n0 + lrow) < N;
    const unsigned* Whp = Whig + (size_t)(wvalid ? (n0 + lrow) : 0) * K2 + lp;
    const unsigned* Wlp = Wlog + (size_t)(wvalid ? (n0 + lrow) : 0) * K2 + lp;

    float4 pa0 = *(const float4*)Aptr;
    float4 pa1 = *(const float4*)(Aptr + 4);
    uint4 ph = *(const uint4*)Whp;
    uint4 pl = *(const uint4*)Wlp;

    for (int k0 = 0; k0 < K; k0 += 16) {
        unsigned hi, lo;
        bf16_split2(pa0.x, pa0.y, hi, lo); Ah[lrow][lp] = hi;     Al[lrow][lp] = lo;
        bf16_split2(pa0.z, pa0.w, hi, lo); Ah[lrow][lp + 1] = hi; Al[lrow][lp + 1] = lo;
        bf16_split2(pa1.x, pa1.y, hi, lo); Ah[lrow][lp + 2] = hi; Al[lrow][lp + 2] = lo;
        bf16_split2(pa1.z, pa1.w, hi, lo); Ah[lrow][lp + 3] = hi; Al[lrow][lp + 3] = lo;
        Wh[lrow][lp] = ph.x; Wh[lrow][lp + 1] = ph.y;
        Wh[lrow][lp + 2] = ph.z; Wh[lrow][lp + 3] = ph.w;
        Wl[lrow][lp] = pl.x; Wl[lrow][lp + 1] = pl.y;
        Wl[lrow][lp + 2] = pl.z; Wl[lrow][lp + 3] = pl.w;
        __syncthreads();

        if (k0 + 16 < K) {
            int kpn = (k0 + 16) >> 1;
            pa0 = *(const float4*)(Aptr + k0 + 16);
            pa1 = *(const float4*)(Aptr + k0 + 20);
            ph = *(const uint4*)(Whp + kpn);
            pl = *(const uint4*)(Wlp + kpn);
        }

        unsigned ah[4][4], al[4][4];
#pragma unroll
        for (int mt = 0; mt < 4; mt++) {
            int r = wm + mt * 16;
            ah[mt][0] = Ah[r + g][qd];     ah[mt][1] = Ah[r + g + 8][qd];
            ah[mt][2] = Ah[r + g][qd + 4]; ah[mt][3] = Ah[r + g + 8][qd + 4];
            al[mt][0] = Al[r + g][qd];     al[mt][1] = Al[r + g + 8][qd];
            al[mt][2] = Al[r + g][qd + 4]; al[mt][3] = Al[r + g + 8][qd + 4];
        }
#pragma unroll
        for (int nt = 0; nt < 4; nt++) {
            int cn = wn + nt * 8 + g;
            unsigned bh0 = Wh[cn][qd], bh1 = Wh[cn][qd + 4];
            unsigned bl0 = Wl[cn][qd], bl1 = Wl[cn][qd + 4];
#pragma unroll
            for (int mt = 0; mt < 4; mt++) {
                mma_bf16(c[mt][nt], ah[mt][0], ah[mt][1], ah[mt][2], ah[mt][3], bh0, bh1);
                mma_bf16(c[mt][nt], ah[mt][0], ah[mt][1], ah[mt][2], ah[mt][3], bl0, bl1);
                mma_bf16(c[mt][nt], al[mt][0], al[mt][1], al[mt][2], al[mt][3], bh0, bh1);
            }
        }
        __syncthreads();
    }

#pragma unroll
    for (int mt = 0; mt < 4; mt++) {
#pragma unroll
        for (int nt = 0; nt < 4; nt++) {
            int row = m0 + wm + mt * 16 + g;
            int col = n0 + wn + nt * 8 + 2 * qd;
            if (col >= N) continue;
            float v0 = c[mt][nt][0], v1 = c[mt][nt][1];
            float v2 = c[mt][nt][2], v3 = c[mt][nt][3];
            if (EPI == EPI_BIAS || EPI == EPI_BIAS_GELU) {
                float2 bv = *(const float2*)(bias + col);
                v0 += bv.x; v1 += bv.y; v2 += bv.x; v3 += bv.y;
            }
            if (EPI == EPI_BIAS_GELU) {
                v0 = gelu(v0); v1 = gelu(v1); v2 = gelu(v2); v3 = gelu(v3);
            }
            if (EPI == EPI_RES) {
                float2 r0 = *(const float2*)(res + (size_t)row * N + col);
                float2 r1 = *(const float2*)(res + (size_t)(row + 8) * N + col);
                v0 += r0.x; v1 += r0.y; v2 += r1.x; v3 += r1.y;
            }
            *(float2*)(C + (size_t)row * N + col) = make_float2(v0, v1);
            *(float2*)(C + (size_t)(row + 8) * N + col) = make_float2(v2, v3);
        }
    }
}

// ---------------- conv1d: 16 timesteps per block, sliding register window ----
__global__ void __launch_bounds__(CONVDIM) conv_dt_kernel(
    const float* __restrict__ conv_w, const float* __restrict__ conv_b,
    const float* __restrict__ dt_bias, const float* __restrict__ A_log)
{
    int blk = blockIdx.x;
    int b = blk >> 7;
    int l0 = (blk & 127) << 4;
    int c = threadIdx.x;

    const float* src = g_zxbcdt + (size_t)b * LSEQ * DINPROJ + DINNER + c;
    float cw0 = conv_w[c * 4 + 0], cw1 = conv_w[c * 4 + 1];
    float cw2 = conv_w[c * 4 + 2], cw3 = conv_w[c * 4 + 3];
    float cb = conv_b[c];

    float x0 = 0.f, x1 = 0.f, x2 = 0.f;
    if (l0 >= 3) {
        x0 = src[(size_t)(l0 - 3) * DINPROJ];
        x1 = src[(size_t)(l0 - 2) * DINPROJ];
        x2 = src[(size_t)(l0 - 1) * DINPROJ];
    }
    float* dst = g_xBC + (size_t)(b * LSEQ + l0) * CONVDIM + c;
#pragma unroll
    for (int tl = 0; tl < 16; tl++) {
        float x3 = src[(size_t)(l0 + tl) * DINPROJ];
        float accv = cb + cw0 * x0 + cw1 * x1 + cw2 * x2 + cw3 * x3;
        dst[(size_t)tl * CONVDIM] = accv / (1.f + __expf(-accv));
        x0 = x1; x1 = x2; x2 = x3;
    }

    if (c < NHEADS) {
        float aexp = __expf(A_log[c]);
        float db = dt_bias[c];
        const float* dsrc = g_zxbcdt + (size_t)(b * LSEQ + l0) * DINPROJ + DINNER + CONVDIM + c;
#pragma unroll
        for (int tl = 0; tl < 16; tl++) {
            float v = dsrc[(size_t)tl * DINPROJ] + db;
            float dt = (v > 20.f) ? v : log1pf(__expf(v));
            int off = (b * LSEQ + l0 + tl) * NHEADS + c;
            g_dt[off] = dt;
            g_dA[off] = __expf(dt * -aexp);
        }
    }
}

// ---------------- chunked selective scan: pass A (4 p per warp) -------------
__global__ void __launch_bounds__(128) scan_chunk_kernel()
{
    int bidx = blockIdx.x;
    int pg = bidx & 3;
    int h  = (bidx >> 2) & 7;
    int b  = (bidx >> 5) & 1;
    int cch = bidx >> 6;
    int warp = threadIdx.x >> 5;
    int lane = threadIdx.x & 31;
    int p0 = pg * 16 + warp * 4;
    int n0 = lane * 4;
    int bh = b * NHEADS + h;
    int t0 = cch * CHUNK;

    float4 hh[4];
#pragma unroll
    for (int j = 0; j < 4; j++) hh[j] = make_float4(0.f, 0.f, 0.f, 0.f);
    float prod = 1.f;

    const float* xbase = g_xBC + (size_t)b * LSEQ * CONVDIM;
    const float* dtb = g_dt + (size_t)b * LSEQ * NHEADS + h;
    const float* dab = g_dA + (size_t)b * LSEQ * NHEADS + h;
    float* yout = g_y + (size_t)b * LSEQ * DINNER + h * HEADDIM + p0;
    const int coff = h * HEADDIM + p0;

    for (int tl = 0; tl < CHUNK; tl++) {
        int t = t0 + tl;
        const float* row = xbase + (size_t)t * CONVDIM;
        float dA = dab[t * NHEADS];
        float dt = dtb[t * NHEADS];
        float4 xv = *(const float4*)(row + coff);
        float4 Bv = *(const float4*)(row + DINNER + n0);
        float4 Cv = *(const float4*)(row + DINNER + DSTATE + n0);
        float dtx[4] = {dt * xv.x, dt * xv.y, dt * xv.z, dt * xv.w};
        float acc[4];
#pragma unroll
        for (int j = 0; j < 4; j++) {
            hh[j].x = hh[j].x * dA + dtx[j] * Bv.x;
            hh[j].y = hh[j].y * dA + dtx[j] * Bv.y;
            hh[j].z = hh[j].z * dA + dtx[j] * Bv.z;
            hh[j].w = hh[j].w * dA + dtx[j] * Bv.w;
            acc[j] = hh[j].x * Cv.x + hh[j].y * Cv.y + hh[j].z * Cv.z + hh[j].w * Cv.w;
        }
        prod *= dA;
#pragma unroll
        for (int o = 16; o; o >>= 1) {
#pragma unroll
            for (int j = 0; j < 4; j++)
                acc[j] += __shfl_xor_sync(0xffffffffu, acc[j], o);
        }
        if (lane == 0) {
#pragma unroll
            for (int j = 0; j < 4; j++)
                yout[(size_t)t * DINNER + j] = acc[j];
        }
        if (threadIdx.x == 0 && pg == 0)
            g_cumA[(size_t)bh * LSEQ + t] = prod;
    }
#pragma unroll
    for (int j = 0; j < 4; j++)
        *(float4*)&g_state[(((size_t)bh * NCHUNK + cch) * HEADDIM + p0 + j) * DSTATE + n0] = hh[j];
    if (threadIdx.x == 0 && pg == 0)
        g_P[bh * NCHUNK + cch] = prod;
}

// ---------------- pass B: sequential combine with batched prefetch ----------
__global__ void __launch_bounds__(256) combine_state_kernel()
{
    int idx = blockIdx.x * blockDim.x + threadIdx.x;
    int nq = idx & 63;
    int p  = (idx >> 6) & 63;
    int bh = idx >> 12;
    float2 H = make_float2(0.f, 0.f);
    const float* Pb = g_P + bh * NCHUNK;
    size_t base = (((size_t)bh * NCHUNK) * HEADDIM + p) * DSTATE + nq * 2;
    const size_t cstride = (size_t)HEADDIM * DSTATE;

    for (int cc0 = 0; cc0 < NCHUNK; cc0 += 8) {
        float2 S[8];
#pragma unroll
        for (int j = 0; j < 8; j++)
            S[j] = *(const float2*)&g_state[base + (size_t)(cc0 + j) * cstride];
#pragma unroll
        for (int j = 0; j < 8; j++) {
            *(float2*)&g_H0[base + (size_t)(cc0 + j) * cstride] = H;
            float P = Pb[cc0 + j];
            H.x = S[j].x + P * H.x;
            H.y = S[j].y + P * H.y;
        }
    }
}

// ---------------- pass C: correction y += cumA * (C · H0), 4 p per warp -----
__global__ void __launch_bounds__(128) scan_fix_kernel()
{
    int bidx = blockIdx.x;
    int pg = bidx & 3;
    int h  = (bidx >> 2) & 7;
    int b  = (bidx >> 5) & 1;
    int cch = (bidx >> 6) + 1;
    int warp = threadIdx.x >> 5;
    int lane = threadIdx.x & 31;
    int p0 = pg * 16 + warp * 4;
    int n0 = lane * 4;
    int bh = b * NHEADS + h;
    int t0 = cch * CHUNK;

    float4 H[4];
#pragma unroll
    for (int j = 0; j < 4; j++)
        H[j] = *(const float4*)&g_H0[(((size_t)bh * NCHUNK + cch) * HEADDIM + p0 + j) * DSTATE + n0];

    const float* cb = g_xBC + (size_t)b * LSEQ * CONVDIM + DINNER + DSTATE + n0;
    const float* cum = g_cumA + (size_t)bh * LSEQ;
    float* yout = g_y + (size_t)b * LSEQ * DINNER + h * HEADDIM + p0;

    for (int tl = 0; tl < CHUNK; tl++) {
        int t = t0 + tl;
        float4 Cv = *(const float4*)(cb + (size_t)t * CONVDIM);
        float acc[4];
#pragma unroll
        for (int j = 0; j < 4; j++)
            acc[j] = H[j].x * Cv.x + H[j].y * Cv.y + H[j].z * Cv.z + H[j].w * Cv.w;
#pragma unroll
        for (int o = 16; o; o >>= 1) {
#pragma unroll
            for (int j = 0; j < 4; j++)
                acc[j] += __shfl_xor_sync(0xffffffffu, acc[j], o);
        }
        if (lane == 0) {
            float cm = cum[t];
#pragma unroll
            for (int j = 0; j < 4; j++)
                yout[(size_t)t * DINNER + j] += cm * acc[j];
        }
    }
}

// ---------------- gate + RMSNorm ----------------
__global__ void __launch_bounds__(512) gate_rms_kernel(const float* __restrict__ D_param,
                                                       const float* __restrict__ norm_w)
{
    int bl = blockIdx.x;
    int d = threadIdx.x;
    float y = g_y[(size_t)bl * DINNER + d] +
              D_param[d >> 6] * g_xBC[(size_t)bl * CONVDIM + d];
    float z = g_zxbcdt[(size_t)bl * DINPROJ + d];
    float g = y * (z / (1.f + __expf(-z)));

    __shared__ float sh[16];
    float s = g * g;
    int lane = d & 31, w = d >> 5;
#pragma unroll
    for (int o = 16; o; o >>= 1) s += __shfl_xor_sync(0xffffffffu, s, o);
    if (lane == 0) sh[w] = s;
    __syncthreads();
    if (w == 0) {
        float v = (lane < 16) ? sh[lane] : 0.f;
#pragma unroll
        for (int o = 16; o; o >>= 1) v += __shfl_xor_sync(0xffffffffu, v, o);
        if (lane == 0) sh[0] = v;
    }
    __syncthreads();
    float scale = rsqrtf(sh[0] * (1.f / DINNER) + 1e-5f);
    g_y[(size_t)bl * DINNER + d] = g * scale * norm_w[d];
}

// ---------------- V packing (split bf16 hi/lo, key-paired) ----------------
__global__ void __launch_bounds__(256) v_pack_kernel()
{
    int idx = blockIdx.x * blockDim.x + threadIdx.x;
    int d  = idx & 31;
    int kp = (idx >> 5) & 1023;
    int h  = (idx >> 15) & 7;
    int b  = idx >> 18;
    size_t src = ((size_t)(b * LSEQ + 2 * kp)) * DMODEL + h * AHD + d;
    float v0 = g_v[src];
    float v1 = g_v[src + DMODEL];
    unsigned hi, lo;
    bf16_split2(v0, v1, hi, lo);
    g_vhi[idx] = hi;
    g_vlo[idx] = lo;
}

// ---------------- flash attention: 128 queries/block, split-bf16 V ----------
__global__ void __launch_bounds__(256) attn_mma_kernel()
{
    __shared__ float Qs[128][40];
    __shared__ float Ks[64][40];
    __shared__ unsigned Vh[32][40];
    __shared__ unsigned Vl[32][40];

    const int q0 = blockIdx.x * 128;
    const int h = blockIdx.y;
    const int b = blockIdx.z;
    const int tid = threadIdx.x;
    const int w = tid >> 5, lane = tid & 31;
    const int qd = lane & 3, g = lane >> 2;

    const size_t base = (size_t)b * LSEQ * DMODEL + h * AHD;
    const unsigned* vhib = g_vhi + ((size_t)(b * NHEADS + h)) * 1024 * 32;
    const unsigned* vlob = g_vlo + ((size_t)(b * NHEADS + h)) * 1024 * 32;

#pragma unroll
    for (int i = 0; i < 4; i++) {
        int e = tid + i * 256;
        int row = e >> 3, c4 = (e & 7) * 4;
        *(float4*)&Qs[row][c4] =
            *(const float4*)(g_qp + base + (size_t)(q0 + row) * DMODEL + c4);
    }
    __syncthreads();

    unsigned qa[4][4];
#pragma unroll
    for (int ks = 0; ks < 4; ks++) {
        int r = w * 16;
        qa[ks][0] = __float_as_uint(Qs[r + g][8 * ks + qd]);
        qa[ks][1] = __float_as_uint(Qs[r + g + 8][8 * ks + qd]);
        qa[ks][2] = __float_as_uint(Qs[r + g][8 * ks + qd + 4]);
        qa[ks][3] = __float_as_uint(Qs[r + g + 8][8 * ks + qd + 4]);
    }

    float m0 = -1e30f, m1 = -1e30f, l0 = 0.f, l1 = 0.f;
    float o[4][4];
#pragma unroll
    for (int nt = 0; nt < 4; nt++)
#pragma unroll
        for (int i = 0; i < 4; i++) o[nt][i] = 0.f;

    for (int kt = 0; kt < LSEQ / 64; kt++) {
        __syncthreads();
#pragma unroll
        for (int i = 0; i < 2; i++) {
            int e = tid + i * 256;
            int row = e >> 3, c4 = (e & 7) * 4;
            *(float4*)&Ks[row][c4] =
                *(const float4*)(g_kp + base + (size_t)(kt * 64 + row) * DMODEL + c4);
        }
        {
            int kp = tid >> 3, q4 = (tid & 7) * 4;
            size_t gsrc = (size_t)(kt * 32 + kp) * 32 + q4;
            *(uint4*)&Vh[kp][q4] = *(const uint4*)(vhib + gsrc);
            *(uint4*)&Vl[kp][q4] = *(const uint4*)(vlob + gsrc);
        }
        __syncthreads();

        float s[8][4];
#pragma unroll
        for (int nt = 0; nt < 8; nt++)
#pragma unroll
            for (int i = 0; i < 4; i++) s[nt][i] = 0.f;
#pragma unroll
        for (int ks = 0; ks < 4; ks++) {
#pragma unroll
            for (int nt = 0; nt < 8; nt++) {
                unsigned b0 = __float_as_uint(Ks[nt * 8 + g][8 * ks + qd]);
                unsigned b1 = __float_as_uint(Ks[nt * 8 + g][8 * ks + qd + 4]);
                mma_tf32(s[nt], qa[ks], b0, b1);
            }
        }

        float r0 = -1e30f, r1 = -1e30f;
#pragma unroll
        for (int nt = 0; nt < 8; nt++) {
            r0 = fmaxf(r0, fmaxf(s[nt][0], s[nt][1]));
            r1 = fmaxf(r1, fmaxf(s[nt][2], s[nt][3]));
        }
        r0 = fmaxf(r0, __shfl_xor_sync(0xffffffffu, r0, 1));
        r0 = fmaxf(r0, __shfl_xor_sync(0xffffffffu, r0, 2));
        r1 = fmaxf(r1, __shfl_xor_sync(0xffffffffu, r1, 1));
        r1 = fmaxf(r1, __shfl_xor_sync(0xffffffffu, r1, 2));
        float nm0 = fmaxf(m0, r0), nm1 = fmaxf(m1, r1);
        float cf0 = __expf(m0 - nm0), cf1 = __expf(m1 - nm1);
        m0 = nm0; m1 = nm1;
        l0 *= cf0; l1 *= cf1;
#pragma unroll
        for (int nt = 0; nt < 4; nt++) {
            o[nt][0] *= cf0; o[nt][1] *= cf0;
            o[nt][2] *= cf1; o[nt][3] *= cf1;
        }

        unsigned plo[8], phi[8];
#pragma unroll
        for (int nt = 0; nt < 8; nt++) {
            float p0 = __expf(s[nt][0] - m0);
            float p1 = __expf(s[nt][1] - m0);
            float p2 = __expf(s[nt][2] - m1);
            float p3 = __expf(s[nt][3] - m1);
            l0 += p0 + p1;
            l1 += p2 + p3;
            __nv_bfloat162 lo = __floats2bfloat162_rn(p0, p1);
            __nv_bfloat162 hi = __floats2bfloat162_rn(p2, p3);
            plo[nt] = *(unsigned*)&lo;
            phi[nt] = *(unsigned*)&hi;
        }

#pragma unroll
        for (int kk = 0; kk < 4; kk++) {
            unsigned a0 = plo[2 * kk], a1 = phi[2 * kk];
            unsigned a2 = plo[2 * kk + 1], a3 = phi[2 * kk + 1];
#pragma unroll
            for (int nt = 0; nt < 4; nt++) {
                unsigned bh0 = Vh[kk * 8 + qd][nt * 8 + g];
                unsigned bh1 = Vh[kk * 8 + qd + 4][nt * 8 + g];
                mma_bf16(o[nt], a0, a1, a2, a3, bh0, bh1);
                unsigned bl0 = Vl[kk * 8 + qd][nt * 8 + g];
                unsigned bl1 = Vl[kk * 8 + qd + 4][nt * 8 + g];
                mma_bf16(o[nt], a0, a1, a2, a3, bl0, bl1);
            }
        }
    }

    l0 += __shfl_xor_sync(0xffffffffu, l0, 1);
    l0 += __shfl_xor_sync(0xffffffffu, l0, 2);
    l1 += __shfl_xor_sync(0xffffffffu, l1, 1);
    l1 += __shfl_xor_sync(0xffffffffu, l1, 2);

    float inv0 = 1.f / l0, inv1 = 1.f / l1;
    int row = q0 + w * 16 + g;
#pragma unroll
    for (int nt = 0; nt < 4; nt++) {
        int col = h * AHD + nt * 8 + 2 * qd;
        *(float2*)(g_o + (size_t)(b * LSEQ + row) * DMODEL + col) =
            make_float2(o[nt][0] * inv0, o[nt][1] * inv0);
        *(float2*)(g_o + (size_t)(b * LSEQ + row + 8) * DMODEL + col) =
            make_float2(o[nt][2] * inv1, o[nt][3] * inv1);
    }
}

// ---------------- LayerNorm over 1024 ----------------
__global__ void __launch_bounds__(256) layernorm_kernel(const float* __restrict__ ln_w,
                                                        const float* __restrict__ ln_b)
{
    int bl = blockIdx.x, tid = threadIdx.x;
    float4 v = *(const float4*)(g_mlp + (size_t)bl * MLPH + tid * 4);
    float s = v.x + v.y + v.z + v.w;
    float s2 = v.x * v.x + v.y * v.y + v.z * v.z + v.w * v.w;

    __shared__ float shs[8], shs2[8];
    int lane = tid & 31, w = tid >> 5;
#pragma unroll
    for (int o = 16; o; o >>= 1) {
        s += __shfl_xor_sync(0xffffffffu, s, o);
        s2 += __shfl_xor_sync(0xffffffffu, s2, o);
    }
    if (lane == 0) { shs[w] = s; shs2[w] = s2; }
    __syncthreads();
    if (w == 0) {
        float a = (lane < 8) ? shs[lane] : 0.f;
        float b2 = (lane < 8) ? shs2[lane] : 0.f;
#pragma unroll
        for (int o = 4; o; o >>= 1) {
            a += __shfl_xor_sync(0xffffffffu, a, o);
            b2 += __shfl_xor_sync(0xffffffffu, b2, o);
        }
        if (lane == 0) { shs[0] = a; shs2[0] = b2; }
    }
    __syncthreads();
    float mu = shs[0] * (1.f / MLPH);
    float var = shs2[0] * (1.f / MLPH) - mu * mu;
    float inv = rsqrtf(var + 1e-5f);

    float4 wv = *(const float4*)(ln_w + tid * 4);
    float4 bv = *(const float4*)(ln_b + tid * 4);
    float4 r;
    r.x = (v.x - mu) * inv * wv.x + bv.x;
    r.y = (v.y - mu) * inv * wv.y + bv.y;
    r.z = (v.z - mu) * inv * wv.z + bv.z;
    r.w = (v.w - mu) * inv * wv.w + bv.w;
    *(float4*)(g_mlp + (size_t)bl * MLPH + tid * 4) = r;
}

// ---------------- two-stage mean-pool + head ----------------
__global__ void __launch_bounds__(256) pool1_kernel()
{
    int b = blockIdx.x, seg = blockIdx.y;
    int d = threadIdx.x;
    float s = 0.f;
    int t0 = seg * 128;
#pragma unroll 8
    for (int t = 0; t < 128; t++)
        s += g_h2[((size_t)(b * LSEQ + t0 + t)) * DMODEL + d];
    g_pool[(b * 16 + seg) * DMODEL + d] = s;
}

__global__ void __launch_bounds__(256) pool2_kernel(const float* __restrict__ head_w,
                                                    const float* __restrict__ head_b,
                                                    float* __restrict__ out)
{
    int b = blockIdx.x;
    int d = threadIdx.x;
    float s = 0.f;
#pragma unroll
    for (int seg = 0; seg < 16; seg++)
        s += g_pool[(b * 16 + seg) * DMODEL + d];
    __shared__ float pooled[DMODEL];
    pooled[d] = s * (1.f / LSEQ);
    __syncthreads();
    if (d < 2) {
        float accv = head_b[d];
        for (int j = 0; j < DMODEL; j++) accv += pooled[j] * head_w[d * DMODEL + j];
        out[b * 2 + d] = accv;
    }
}

// ---------------- host launcher ----------------
extern "C" void kernel_launch(void* const* d_in, const int* in_sizes, int n_in,
                              void* d_out, int out_size)
{
    (void)in_sizes; (void)n_in; (void)out_size;
    const float* x         = (const float*)d_in[0];
    const float* context   = (const float*)d_in[1];
    const float* in_proj_w = (const float*)d_in[2];
    const float* conv_w    = (const float*)d_in[3];
    const float* conv_b    = (const float*)d_in[4];
    const float* dt_bias   = (const float*)d_in[5];
    const float* A_log     = (const float*)d_in[6];
    const float* D_param   = (const float*)d_in[7];
    const float* norm_w    = (const float*)d_in[8];
    const float* out_proj_w= (const float*)d_in[9];
    const float* wq        = (const float*)d_in[10];
    const float* wk        = (const float*)d_in[11];
    const float* wv        = (const float*)d_in[12];
    const float* wo        = (const float*)d_in[13];
    const float* wo_b      = (const float*)d_in[14];
    const float* w1        = (const float*)d_in[15];
    const float* b1        = (const float*)d_in[16];
    const float* ln_w      = (const float*)d_in[17];
    const float* ln_b      = (const float*)d_in[18];
    const float* w2        = (const float*)d_in[19];
    const float* b2        = (const float*)d_in[20];
    const float* head_w    = (const float*)d_in[21];
    const float* head_b    = (const float*)d_in[22];
    float* out = (float*)d_out;

    float *p_zx, *p_y, *p_hres, *p_v, *p_o, *p_ob, *p_mlp, *p_h2, *p_qp, *p_kp;
    unsigned *p_whi, *p_wlo;
    cudaGetSymbolAddress((void**)&p_zx,   g_zxbcdt);
    cudaGetSymbolAddress((void**)&p_y,    g_y);
    cudaGetSymbolAddress((void**)&p_hres, g_hres);
    cudaGetSymbolAddress((void**)&p_v,    g_v);
    cudaGetSymbolAddress((void**)&p_o,    g_o);
    cudaGetSymbolAddress((void**)&p_ob,   g_ob);
    cudaGetSymbolAddress((void**)&p_mlp,  g_mlp);
    cudaGetSymbolAddress((void**)&p_h2,   g_h2);
    cudaGetSymbolAddress((void**)&p_qp,   g_qp);
    cudaGetSymbolAddress((void**)&p_kp,   g_kp);
    cudaGetSymbolAddress((void**)&p_whi,  g_whi);
    cudaGetSymbolAddress((void**)&p_wlo,  g_wlo);

    // 0) pre-split all weights into bf16 hi/lo
    pack_w_kernel<<<(WTOTAL + 255) / 256, 256>>>(
        in_proj_w, out_proj_w, wq, wk, wv, wo, w1, w2);
    // 1) in_proj (big tile)
    gemm128_kernel<EPI_NONE><<<dim3((DINPROJ + 127) / 128, M4 / 128), 256>>>(
        x, p_whi + WOFF_INPROJ, p_wlo + WOFF_INPROJ, nullptr, nullptr,
        p_zx, M4, DINPROJ, DMODEL);
    // 2) conv + dt/dA
    conv_dt_kernel<<<M4 / 16, CONVDIM>>>(conv_w, conv_b, dt_bias, A_log);
    // 3) chunked selective scan
    scan_chunk_kernel<<<4 * 8 * 2 * NCHUNK, 128>>>();
    combine_state_kernel<<<256, 256>>>();
    scan_fix_kernel<<<4 * 8 * 2 * (NCHUNK - 1), 128>>>();
    // 4) gate + RMSNorm
    gate_rms_kernel<<<M4, DINNER>>>(D_param, norm_w);
    // 5) out_proj + residual
    gemm_bf16_kernel<EPI_RES><<<dim3(DMODEL / 64, M4 / 64), 128>>>(
        p_y, p_whi + WOFF_OUTPROJ, p_wlo + WOFF_OUTPROJ, nullptr, x,
        p_hres, nullptr, M4, DMODEL, DINNER);
    // 6) Q projection (epilogue emits tf32-scaled g_qp)
    gemm_bf16_kernel<EPI_QPACK><<<dim3(DMODEL / 64, M4 / 64), 128>>>(
        p_hres, p_whi + WOFF_WQ, p_wlo + WOFF_WQ, nullptr, nullptr,
        p_qp, nullptr, M4, DMODEL, DMODEL);
    // 6b) fused K+V projection (N=512; K half -> tf32 g_kp, V half -> g_v)
    gemm_bf16_kernel<EPI_KV><<<dim3(512 / 64, M4 / 64), 128>>>(
        context, p_whi + WOFF_WK, p_wlo + WOFF_WK, nullptr, nullptr,
        p_kp, p_v, M4, 512, DMODEL);
    // 6c) V pack (split bf16 hi/lo, key-paired)
    v_pack_kernel<<<(BBATCH * NHEADS * 1024 * 32) / 256, 256>>>();
    // 7) attention
    attn_mma_kernel<<<dim3(LSEQ / 128, NHEADS, BBATCH), 256>>>();
    // 8) attn out proj
    gemm_bf16_kernel<EPI_BIAS><<<dim3(DMODEL / 64, M4 / 64), 128>>>(
        p_o, p_whi + WOFF_WO, p_wlo + WOFF_WO, wo_b, nullptr,
        p_ob, nullptr, M4, DMODEL, DMODEL);
    // 9) MLP fc1 + GELU (big tile)
    gemm128_kernel<EPI_BIAS_GELU><<<dim3(MLPH / 128, M4 / 128), 256>>>(
        p_ob, p_whi + WOFF_W1, p_wlo + WOFF_W1, b1, nullptr,
        p_mlp, M4, MLPH, DMODEL);
    // 10) LayerNorm
    layernorm_kernel<<<M4, 256>>>(ln_w, ln_b);
    // 11) MLP fc2
    gemm_bf16_kernel<EPI_BIAS><<<dim3(DMODEL / 64, M4 / 64), 128>>>(
        p_mlp, p_whi + WOFF_W2, p_wlo + WOFF_W2, b2, nullptr,
        p_h2, nullptr, M4, DMODEL, MLPH);
    // 12) two-stage pool + head
    pool1_kernel<<<dim3(BBATCH, 16), 256>>>();
    pool2_kernel<<<BBATCH, 256>>>(head_w, head_b, out);
}

// round 10
// speedup vs baseline: 3.4295x; 1.2204x over previous
#include <cuda_runtime.h>
#include <cuda_bf16.h>
#include <math.h>

// ---------------- problem constants ----------------
#define BBATCH 2
#define LSEQ 2048
#define DMODEL 256
#define DINNER 512
#define DSTATE 128
#define NHEADS 8
#define HEADDIM 64
#define CONVDIM 768          // DINNER + 2*DSTATE
#define DINPROJ 1288         // 2*DINNER + 2*DSTATE + NHEADS
#define AHD 32               // attention head dim
#define MLPH 1024
#define M4 (BBATCH * LSEQ)   // 4096 rows
#define NCHUNK 32
#define CHUNK 64             // LSEQ / NCHUNK

// pre-split weight region offsets (in bf16x2-pair units; region K2 = K/2)
#define WOFF_INPROJ 0          // N=1288 K2=128
#define WOFF_OUTPROJ 164864    // N=256  K2=256
#define WOFF_WQ 230400         // N=256  K2=128
#define WOFF_WK 263168         // N=256  K2=128  (wv follows contiguously)
#define WOFF_WV 295936         // N=256  K2=128
#define WOFF_WO 328704         // N=256  K2=128
#define WOFF_W1 361472         // N=1024 K2=128
#define WOFF_W2 492544         // N=256  K2=512
#define WTOTAL 623616

// ---------------- scratch buffers ----------------
__device__ float g_zxbcdt[(size_t)M4 * DINPROJ];
__device__ float g_xBC[(size_t)M4 * CONVDIM];
__device__ float g_dt[M4 * NHEADS];
__device__ float g_dA[M4 * NHEADS];
__device__ float g_y[(size_t)M4 * DINNER];
__device__ float g_hres[(size_t)M4 * DMODEL];
__device__ float g_v[(size_t)M4 * DMODEL];
__device__ float g_o[(size_t)M4 * DMODEL];
__device__ float g_ob[(size_t)M4 * DMODEL];
__device__ float g_mlp[(size_t)M4 * MLPH];
__device__ float g_h2[(size_t)M4 * DMODEL];
// chunked-scan buffers
__device__ float g_state[(size_t)BBATCH * NHEADS * NCHUNK * HEADDIM * DSTATE];
__device__ float g_H0[(size_t)BBATCH * NHEADS * NCHUNK * HEADDIM * DSTATE];
__device__ float g_P[BBATCH * NHEADS * NCHUNK];
__device__ float g_la[BBATCH * NHEADS * LSEQ];            // log-decay prefix (within chunk)
__device__ float g_G[(size_t)BBATCH * NCHUNK * CHUNK * CHUNK];   // C@B^T per (b,chunk)
// attention packed operands
__device__ float g_qp[(size_t)M4 * DMODEL];
__device__ float g_kp[(size_t)M4 * DMODEL];
__device__ unsigned g_vhi[(size_t)BBATCH * NHEADS * 1024 * 32];
__device__ unsigned g_vlo[(size_t)BBATCH * NHEADS * 1024 * 32];
// pooling partials
__device__ float g_pool[BBATCH * 16 * DMODEL];
// pre-split weights (bf16x2 hi / lo)
__device__ unsigned g_whi[WTOTAL + 64];
__device__ unsigned g_wlo[WTOTAL + 64];

// ---------------- helpers ----------------
__device__ __forceinline__ float to_tf32(float x) {
    unsigned r;
    asm("cvt.rna.tf32.f32 %0, %1;" : "=r"(r) : "f"(x));
    return __uint_as_float(r);
}

__device__ __forceinline__ void mma_tf32(float c[4], const unsigned a[4],
                                         unsigned b0, unsigned b1) {
    asm volatile(
        "mma.sync.aligned.m16n8k8.row.col.f32.tf32.tf32.f32 "
        "{%0,%1,%2,%3},{%4,%5,%6,%7},{%8,%9},{%0,%1,%2,%3};"
        : "+f"(c[0]), "+f"(c[1]), "+f"(c[2]), "+f"(c[3])
        : "r"(a[0]), "r"(a[1]), "r"(a[2]), "r"(a[3]), "r"(b0), "r"(b1));
}

__device__ __forceinline__ void mma_bf16(float c[4], unsigned a0, unsigned a1,
                                         unsigned a2, unsigned a3,
                                         unsigned b0, unsigned b1) {
    asm volatile(
        "mma.sync.aligned.m16n8k16.row.col.f32.bf16.bf16.f32 "
        "{%0,%1,%2,%3},{%4,%5,%6,%7},{%8,%9},{%0,%1,%2,%3};"
        : "+f"(c[0]), "+f"(c[1]), "+f"(c[2]), "+f"(c[3])
        : "r"(a0), "r"(a1), "r"(a2), "r"(a3), "r"(b0), "r"(b1));
}

// split a pair of floats into bf16x2 hi + lo words
__device__ __forceinline__ void bf16_split2(float x, float y,
                                            unsigned& hi, unsigned& lo) {
    __nv_bfloat16 hx = __float2bfloat16_rn(x);
    __nv_bfloat16 hy = __float2bfloat16_rn(y);
    __nv_bfloat16 lx = __float2bfloat16_rn(x - __bfloat162float(hx));
    __nv_bfloat16 ly = __float2bfloat16_rn(y - __bfloat162float(hy));
    __nv_bfloat162 hh = __halves2bfloat162(hx, hy);
    __nv_bfloat162 ll = __halves2bfloat162(lx, ly);
    hi = *(unsigned*)&hh;
    lo = *(unsigned*)&ll;
}

// fast erf (Abramowitz-Stegun 7.1.26, abs err < 1.5e-7)
__device__ __forceinline__ float fast_erf(float x) {
    float ax = fabsf(x);
    float t = __frcp_rn(1.f + 0.3275911f * ax);
    float p = 1.061405429f;
    p = p * t - 1.453152027f;
    p = p * t + 1.421413741f;
    p = p * t - 0.284496736f;
    p = p * t + 0.254829592f;
    float r = 1.f - p * t * __expf(-ax * ax);
    return copysignf(r, x);
}
__device__ __forceinline__ float gelu(float v) {
    return 0.5f * v * (1.f + fast_erf(v * 0.70710678118f));
}

// ---------------- weight pre-split pack ----------------
__global__ void __launch_bounds__(256) pack_w_kernel(
    const float* __restrict__ in_proj_w, const float* __restrict__ out_proj_w,
    const float* __restrict__ wq, const float* __restrict__ wk,
    const float* __restrict__ wv, const float* __restrict__ wo,
    const float* __restrict__ w1, const float* __restrict__ w2)
{
    int idx = blockIdx.x * 256 + threadIdx.x;
    if (idx >= WTOTAL) return;
    const float* src;
    int off, K2;
    if (idx < WOFF_OUTPROJ)      { src = in_proj_w;  off = WOFF_INPROJ;  K2 = 128; }
    else if (idx < WOFF_WQ)      { src = out_proj_w; off = WOFF_OUTPROJ; K2 = 256; }
    else if (idx < WOFF_WK)      { src = wq;         off = WOFF_WQ;      K2 = 128; }
    else if (idx < WOFF_WV)      { src = wk;         off = WOFF_WK;      K2 = 128; }
    else if (idx < WOFF_WO)      { src = wv;         off = WOFF_WV;      K2 = 128; }
    else if (idx < WOFF_W1)      { src = wo;         off = WOFF_WO;      K2 = 128; }
    else if (idx < WOFF_W2)      { src = w1;         off = WOFF_W1;      K2 = 128; }
    else                         { src = w2;         off = WOFF_W2;      K2 = 512; }
    int loc = idx - off;
    int n = loc / K2, kp = loc - n * K2;
    float x0 = src[(size_t)n * (K2 * 2) + 2 * kp];
    float x1 = src[(size_t)n * (K2 * 2) + 2 * kp + 1];
    unsigned hi, lo;
    bf16_split2(x0, x1, hi, lo);
    g_whi[idx] = hi;
    g_wlo[idx] = lo;
}

// ---------------- bf16 split GEMM (64x64 tile, double-buffered) -------------
enum { EPI_NONE = 0, EPI_BIAS = 1, EPI_BIAS_GELU = 2, EPI_RES = 3,
       EPI_QPACK = 4, EPI_KV = 5 };

template <int EPI>
__global__ void __launch_bounds__(128)
gemm_bf16_kernel(const float* __restrict__ A,
                 const unsigned* __restrict__ Whig, const unsigned* __restrict__ Wlog,
                 const float* __restrict__ bias, const float* __restrict__ res,
                 float* __restrict__ C, float* __restrict__ C2,
                 int M, int N, int K)
{
    __shared__ unsigned Ah[2][64][9], Al[2][64][9];
    __shared__ unsigned Wh[2][64][9], Wl[2][64][9];

    const int K2 = K >> 1;
    const int m0 = blockIdx.y * 64, n0 = blockIdx.x * 64;
    const int tid = threadIdx.x;
    const int w = tid >> 5, lane = tid & 31;
    const int qd = lane & 3, g = lane >> 2;
    const int wm = (w & 1) * 32, wn = (w >> 1) * 32;
    const int lrow = tid >> 2;        // 0..31
    const int lc4 = (tid & 3) * 4;    // K float offsets 0,4,8,12
    const int lp  = lc4 >> 1;         // pair index 0,2,4,6

    float c[2][4][4];
#pragma unroll
    for (int mt = 0; mt < 2; mt++)
#pragma unroll
        for (int nt = 0; nt < 4; nt++)
#pragma unroll
            for (int i = 0; i < 4; i++) c[mt][nt][i] = 0.f;

    const float* Aptr0 = A + (size_t)(m0 + lrow) * K + lc4;
    const float* Aptr1 = A + (size_t)(m0 + lrow + 32) * K + lc4;
    const bool wv0 = (n0 + lrow) < N;
    const bool wv1 = (n0 + lrow + 32) < N;
    const unsigned* Whp0 = Whig + (size_t)(wv0 ? (n0 + lrow) : 0) * K2 + lp;
    const unsigned* Wlp0 = Wlog + (size_t)(wv0 ? (n0 + lrow) : 0) * K2 + lp;
    const unsigned* Whp1 = Whig + (size_t)(wv1 ? (n0 + lrow + 32) : 0) * K2 + lp;
    const unsigned* Wlp1 = Wlog + (size_t)(wv1 ? (n0 + lrow + 32) : 0) * K2 + lp;

    float4 pa0 = *(const float4*)Aptr0;
    float4 pa1 = *(const float4*)Aptr1;
    uint2 ph0 = *(const uint2*)Whp0;
    uint2 pl0 = *(const uint2*)Wlp0;
    uint2 ph1 = *(const uint2*)Whp1;
    uint2 pl1 = *(const uint2*)Wlp1;

    int buf = 0;
    for (int k0 = 0; k0 < K; k0 += 16) {
        unsigned hi, lo;
        bf16_split2(pa0.x, pa0.y, hi, lo); Ah[buf][lrow][lp] = hi; Al[buf][lrow][lp] = lo;
        bf16_split2(pa0.z, pa0.w, hi, lo); Ah[buf][lrow][lp + 1] = hi; Al[buf][lrow][lp + 1] = lo;
        bf16_split2(pa1.x, pa1.y, hi, lo); Ah[buf][lrow + 32][lp] = hi; Al[buf][lrow + 32][lp] = lo;
        bf16_split2(pa1.z, pa1.w, hi, lo); Ah[buf][lrow + 32][lp + 1] = hi; Al[buf][lrow + 32][lp + 1] = lo;
        Wh[buf][lrow][lp] = ph0.x;      Wh[buf][lrow][lp + 1] = ph0.y;
        Wl[buf][lrow][lp] = pl0.x;      Wl[buf][lrow][lp + 1] = pl0.y;
        Wh[buf][lrow + 32][lp] = ph1.x; Wh[buf][lrow + 32][lp + 1] = ph1.y;
        Wl[buf][lrow + 32][lp] = pl1.x; Wl[buf][lrow + 32][lp + 1] = pl1.y;
        __syncthreads();

        if (k0 + 16 < K) {
            int kpn = (k0 + 16) >> 1;
            pa0 = *(const float4*)(Aptr0 + k0 + 16);
            pa1 = *(const float4*)(Aptr1 + k0 + 16);
            ph0 = *(const uint2*)(Whp0 + kpn);
            pl0 = *(const uint2*)(Wlp0 + kpn);
            ph1 = *(const uint2*)(Whp1 + kpn);
            pl1 = *(const uint2*)(Wlp1 + kpn);
        }

        unsigned ah[2][4], al[2][4];
#pragma unroll
        for (int mt = 0; mt < 2; mt++) {
            int r = wm + mt * 16;
            ah[mt][0] = Ah[buf][r + g][qd];     ah[mt][1] = Ah[buf][r + g + 8][qd];
            ah[mt][2] = Ah[buf][r + g][qd + 4]; ah[mt][3] = Ah[buf][r + g + 8][qd + 4];
            al[mt][0] = Al[buf][r + g][qd];     al[mt][1] = Al[buf][r + g + 8][qd];
            al[mt][2] = Al[buf][r + g][qd + 4]; al[mt][3] = Al[buf][r + g + 8][qd + 4];
        }
#pragma unroll
        for (int nt = 0; nt < 4; nt++) {
            int cn = wn + nt * 8 + g;
            unsigned bh0 = Wh[buf][cn][qd], bh1 = Wh[buf][cn][qd + 4];
            unsigned bl0 = Wl[buf][cn][qd], bl1 = Wl[buf][cn][qd + 4];
#pragma unroll
            for (int mt = 0; mt < 2; mt++) {
                mma_bf16(c[mt][nt], ah[mt][0], ah[mt][1], ah[mt][2], ah[mt][3], bh0, bh1);
                mma_bf16(c[mt][nt], ah[mt][0], ah[mt][1], ah[mt][2], ah[mt][3], bl0, bl1);
                mma_bf16(c[mt][nt], al[mt][0], al[mt][1], al[mt][2], al[mt][3], bh0, bh1);
            }
        }
        buf ^= 1;
    }

    const float qs = 0.1767766953f;   // 1/sqrt(32)
#pragma unroll
    for (int mt = 0; mt < 2; mt++) {
#pragma unroll
        for (int nt = 0; nt < 4; nt++) {
            int row = m0 + wm + mt * 16 + g;
            int col = n0 + wn + nt * 8 + 2 * qd;
            if (col >= N) continue;
            float v0 = c[mt][nt][0], v1 = c[mt][nt][1];
            float v2 = c[mt][nt][2], v3 = c[mt][nt][3];
            if (EPI == EPI_BIAS || EPI == EPI_BIAS_GELU) {
                float2 bv = *(const float2*)(bias + col);
                v0 += bv.x; v1 += bv.y; v2 += bv.x; v3 += bv.y;
            }
            if (EPI == EPI_BIAS_GELU) {
                v0 = gelu(v0); v1 = gelu(v1); v2 = gelu(v2); v3 = gelu(v3);
            }
            if (EPI == EPI_RES) {
                float2 r0 = *(const float2*)(res + (size_t)row * N + col);
                float2 r1 = *(const float2*)(res + (size_t)(row + 8) * N + col);
                v0 += r0.x; v1 += r0.y; v2 += r1.x; v3 += r1.y;
            }
            if (EPI == EPI_QPACK) {
                *(float2*)(C + (size_t)row * N + col) =
                    make_float2(to_tf32(v0 * qs), to_tf32(v1 * qs));
                *(float2*)(C + (size_t)(row + 8) * N + col) =
                    make_float2(to_tf32(v2 * qs), to_tf32(v3 * qs));
            } else if (EPI == EPI_KV) {
                if (col < DMODEL) {
                    *(float2*)(C + (size_t)row * DMODEL + col) =
                        make_float2(to_tf32(v0), to_tf32(v1));
                    *(float2*)(C + (size_t)(row + 8) * DMODEL + col) =
                        make_float2(to_tf32(v2), to_tf32(v3));
                } else {
                    *(float2*)(C2 + (size_t)row * DMODEL + col - DMODEL) =
                        make_float2(v0, v1);
                    *(float2*)(C2 + (size_t)(row + 8) * DMODEL + col - DMODEL) =
                        make_float2(v2, v3);
                }
            } else {
                *(float2*)(C + (size_t)row * N + col) = make_float2(v0, v1);
                *(float2*)(C + (size_t)(row + 8) * N + col) = make_float2(v2, v3);
            }
        }
    }
}

// ---------------- bf16 split GEMM (128x128 tile, 256 threads) ----------------
template <int EPI>
__global__ void __launch_bounds__(256, 2)
gemm128_kernel(const float* __restrict__ A,
               const unsigned* __restrict__ Whig, const unsigned* __restrict__ Wlog,
               const float* __restrict__ bias, const float* __restrict__ res,
               float* __restrict__ C, int M, int N, int K)
{
    __shared__ unsigned Ah[128][9], Al[128][9];
    __shared__ unsigned Wh[128][9], Wl[128][9];

    const int K2 = K >> 1;
    const int m0 = blockIdx.y * 128, n0 = blockIdx.x * 128;
    const int tid = threadIdx.x;
    const int w = tid >> 5, lane = tid & 31;
    const int qd = lane & 3, g = lane >> 2;
    const int wm = (w & 1) * 64;
    const int wn = (w >> 1) * 32;
    const int lrow = tid >> 1;
    const int lc8 = (tid & 1) * 8;
    const int lp  = lc8 >> 1;

    float c[4][4][4];
#pragma unroll
    for (int mt = 0; mt < 4; mt++)
#pragma unroll
        for (int nt = 0; nt < 4; nt++)
#pragma unroll
            for (int i = 0; i < 4; i++) c[mt][nt][i] = 0.f;

    const float* Aptr = A + (size_t)(m0 + lrow) * K + lc8;
    const bool wvalid = (n0 + lrow) < N;
    const unsigned* Whp = Whig + (size_t)(wvalid ? (n0 + lrow) : 0) * K2 + lp;
    const unsigned* Wlp = Wlog + (size_t)(wvalid ? (n0 + lrow) : 0) * K2 + lp;

    float4 pa0 = *(const float4*)Aptr;
    float4 pa1 = *(const float4*)(Aptr + 4);
    uint4 ph = *(const uint4*)Whp;
    uint4 pl = *(const uint4*)Wlp;

    for (int k0 = 0; k0 < K; k0 += 16) {
        unsigned hi, lo;
        bf16_split2(pa0.x, pa0.y, hi, lo); Ah[lrow][lp] = hi;     Al[lrow][lp] = lo;
        bf16_split2(pa0.z, pa0.w, hi, lo); Ah[lrow][lp + 1] = hi; Al[lrow][lp + 1] = lo;
        bf16_split2(pa1.x, pa1.y, hi, lo); Ah[lrow][lp + 2] = hi; Al[lrow][lp + 2] = lo;
        bf16_split2(pa1.z, pa1.w, hi, lo); Ah[lrow][lp + 3] = hi; Al[lrow][lp + 3] = lo;
        Wh[lrow][lp] = ph.x; Wh[lrow][lp + 1] = ph.y;
        Wh[lrow][lp + 2] = ph.z; Wh[lrow][lp + 3] = ph.w;
        Wl[lrow][lp] = pl.x; Wl[lrow][lp + 1] = pl.y;
        Wl[lrow][lp + 2] = pl.z; Wl[lrow][lp + 3] = pl.w;
        __syncthreads();

        if (k0 + 16 < K) {
            int kpn = (k0 + 16) >> 1;
            pa0 = *(const float4*)(Aptr + k0 + 16);
            pa1 = *(const float4*)(Aptr + k0 + 20);
            ph = *(const uint4*)(Whp + kpn);
            pl = *(const uint4*)(Wlp + kpn);
        }

        unsigned ah[4][4], al[4][4];
#pragma unroll
        for (int mt = 0; mt < 4; mt++) {
            int r = wm + mt * 16;
            ah[mt][0] = Ah[r + g][qd];     ah[mt][1] = Ah[r + g + 8][qd];
            ah[mt][2] = Ah[r + g][qd + 4]; ah[mt][3] = Ah[r + g + 8][qd + 4];
            al[mt][0] = Al[r + g][qd];     al[mt][1] = Al[r + g + 8][qd];
            al[mt][2] = Al[r + g][qd + 4]; al[mt][3] = Al[r + g + 8][qd + 4];
        }
#pragma unroll
        for (int nt = 0; nt < 4; nt++) {
            int cn = wn + nt * 8 + g;
            unsigned bh0 = Wh[cn][qd], bh1 = Wh[cn][qd + 4];
            unsigned bl0 = Wl[cn][qd], bl1 = Wl[cn][qd + 4];
#pragma unroll
            for (int mt = 0; mt < 4; mt++) {
                mma_bf16(c[mt][nt], ah[mt][0], ah[mt][1], ah[mt][2], ah[mt][3], bh0, bh1);
                mma_bf16(c[mt][nt], ah[mt][0], ah[mt][1], ah[mt][2], ah[mt][3], bl0, bl1);
                mma_bf16(c[mt][nt], al[mt][0], al[mt][1], al[mt][2], al[mt][3], bh0, bh1);
            }
        }
        __syncthreads();
    }

#pragma unroll
    for (int mt = 0; mt < 4; mt++) {
#pragma unroll
        for (int nt = 0; nt < 4; nt++) {
            int row = m0 + wm + mt * 16 + g;
            int col = n0 + wn + nt * 8 + 2 * qd;
            if (col >= N) continue;
            float v0 = c[mt][nt][0], v1 = c[mt][nt][1];
            float v2 = c[mt][nt][2], v3 = c[mt][nt][3];
            if (EPI == EPI_BIAS || EPI == EPI_BIAS_GELU) {
                float2 bv = *(const float2*)(bias + col);
                v0 += bv.x; v1 += bv.y; v2 += bv.x; v3 += bv.y;
            }
            if (EPI == EPI_BIAS_GELU) {
                v0 = gelu(v0); v1 = gelu(v1); v2 = gelu(v2); v3 = gelu(v3);
            }
            if (EPI == EPI_RES) {
                float2 r0 = *(const float2*)(res + (size_t)row * N + col);
                float2 r1 = *(const float2*)(res + (size_t)(row + 8) * N + col);
                v0 += r0.x; v1 += r0.y; v2 += r1.x; v3 += r1.y;
            }
            *(float2*)(C + (size_t)row * N + col) = make_float2(v0, v1);
            *(float2*)(C + (size_t)(row + 8) * N + col) = make_float2(v2, v3);
        }
    }
}

// ---------------- conv1d: 16 timesteps per block ----------------
__global__ void __launch_bounds__(CONVDIM) conv_dt_kernel(
    const float* __restrict__ conv_w, const float* __restrict__ conv_b,
    const float* __restrict__ dt_bias, const float* __restrict__ A_log)
{
    int blk = blockIdx.x;
    int b = blk >> 7;
    int l0 = (blk & 127) << 4;
    int c = threadIdx.x;

    const float* src = g_zxbcdt + (size_t)b * LSEQ * DINPROJ + DINNER + c;
    float cw0 = conv_w[c * 4 + 0], cw1 = conv_w[c * 4 + 1];
    float cw2 = conv_w[c * 4 + 2], cw3 = conv_w[c * 4 + 3];
    float cb = conv_b[c];

    float x0 = 0.f, x1 = 0.f, x2 = 0.f;
    if (l0 >= 3) {
        x0 = src[(size_t)(l0 - 3) * DINPROJ];
        x1 = src[(size_t)(l0 - 2) * DINPROJ];
        x2 = src[(size_t)(l0 - 1) * DINPROJ];
    }
    float* dst = g_xBC + (size_t)(b * LSEQ + l0) * CONVDIM + c;
#pragma unroll
    for (int tl = 0; tl < 16; tl++) {
        float x3 = src[(size_t)(l0 + tl) * DINPROJ];
        float accv = cb + cw0 * x0 + cw1 * x1 + cw2 * x2 + cw3 * x3;
        dst[(size_t)tl * CONVDIM] = accv / (1.f + __expf(-accv));
        x0 = x1; x1 = x2; x2 = x3;
    }

    if (c < NHEADS) {
        float aexp = __expf(A_log[c]);
        float db = dt_bias[c];
        const float* dsrc = g_zxbcdt + (size_t)(b * LSEQ + l0) * DINPROJ + DINNER + CONVDIM + c;
#pragma unroll
        for (int tl = 0; tl < 16; tl++) {
            float v = dsrc[(size_t)tl * DINPROJ] + db;
            float dt = (v > 20.f) ? v : log1pf(__expf(v));
            int off = (b * LSEQ + l0 + tl) * NHEADS + c;
            g_dt[off] = dt;
            g_dA[off] = __expf(dt * -aexp);
        }
    }
}

// ---------------- scan pass A: state recurrence only (no y!) ----------------
__global__ void __launch_bounds__(128) scan_chunk_kernel(const float* __restrict__ A_log)
{
    int bidx = blockIdx.x;
    int pg = bidx & 3;
    int h  = (bidx >> 2) & 7;
    int b  = (bidx >> 5) & 1;
    int cch = bidx >> 6;
    int warp = threadIdx.x >> 5;
    int lane = threadIdx.x & 31;
    int p0 = pg * 16 + warp * 4;
    int n0 = lane * 4;
    int bh = b * NHEADS + h;
    int t0 = cch * CHUNK;

    float4 hh[4];
#pragma unroll
    for (int j = 0; j < 4; j++) hh[j] = make_float4(0.f, 0.f, 0.f, 0.f);
    float aexp = __expf(A_log[h]);
    float lasum = 0.f;

    const float* xbase = g_xBC + (size_t)b * LSEQ * CONVDIM;
    const float* dtb = g_dt + (size_t)b * LSEQ * NHEADS + h;
    const float* dab = g_dA + (size_t)b * LSEQ * NHEADS + h;
    const int coff = h * HEADDIM + p0;

    for (int tl = 0; tl < CHUNK; tl++) {
        int t = t0 + tl;
        const float* row = xbase + (size_t)t * CONVDIM;
        float dA = dab[t * NHEADS];
        float dt = dtb[t * NHEADS];
        float4 xv = *(const float4*)(row + coff);
        float4 Bv = *(const float4*)(row + DINNER + n0);
        float dtx[4] = {dt * xv.x, dt * xv.y, dt * xv.z, dt * xv.w};
#pragma unroll
        for (int j = 0; j < 4; j++) {
            hh[j].x = hh[j].x * dA + dtx[j] * Bv.x;
            hh[j].y = hh[j].y * dA + dtx[j] * Bv.y;
            hh[j].z = hh[j].z * dA + dtx[j] * Bv.z;
            hh[j].w = hh[j].w * dA + dtx[j] * Bv.w;
        }
        lasum -= aexp * dt;
        if (threadIdx.x == 0 && pg == 0)
            g_la[(size_t)bh * LSEQ + t] = lasum;
    }
#pragma unroll
    for (int j = 0; j < 4; j++)
        *(float4*)&g_state[(((size_t)bh * NCHUNK + cch) * HEADDIM + p0 + j) * DSTATE + n0] = hh[j];
    if (threadIdx.x == 0 && pg == 0)
        g_P[bh * NCHUNK + cch] = __expf(lasum);
}

// ---------------- scan G kernel: G = C @ B^T per (b, chunk) -----------------
__global__ void __launch_bounds__(128) scan_g_kernel()
{
    __shared__ unsigned Ah[2][64][9], Al[2][64][9];
    __shared__ unsigned Wh[2][64][9], Wl[2][64][9];

    const int cch = blockIdx.x & 31, b = blockIdx.x >> 5;
    const int t0 = cch * CHUNK;
    const int tid = threadIdx.x;
    const int w = tid >> 5, lane = tid & 31;
    const int qd = lane & 3, g = lane >> 2;
    const int wm = (w & 1) * 32, wn = (w >> 1) * 32;
    const int lrow = tid >> 2;
    const int lc4 = (tid & 3) * 4;
    const int lp  = lc4 >> 1;

    float c[2][4][4];
#pragma unroll
    for (int mt = 0; mt < 2; mt++)
#pragma unroll
        for (int nt = 0; nt < 4; nt++)
#pragma unroll
            for (int i = 0; i < 4; i++) c[mt][nt][i] = 0.f;

    const float* Aptr0 = g_xBC + (size_t)(b * LSEQ + t0 + lrow) * CONVDIM + DINNER + DSTATE + lc4;
    const float* Aptr1 = Aptr0 + (size_t)32 * CONVDIM;
    const float* Wptr0 = g_xBC + (size_t)(b * LSEQ + t0 + lrow) * CONVDIM + DINNER + lc4;
    const float* Wptr1 = Wptr0 + (size_t)32 * CONVDIM;

    float4 pa0 = *(const float4*)Aptr0;
    float4 pa1 = *(const float4*)Aptr1;
    float4 pw0 = *(const float4*)Wptr0;
    float4 pw1 = *(const float4*)Wptr1;

    int buf = 0;
    for (int k0 = 0; k0 < DSTATE; k0 += 16) {
        unsigned hi, lo;
        bf16_split2(pa0.x, pa0.y, hi, lo); Ah[buf][lrow][lp] = hi; Al[buf][lrow][lp] = lo;
        bf16_split2(pa0.z, pa0.w, hi, lo); Ah[buf][lrow][lp + 1] = hi; Al[buf][lrow][lp + 1] = lo;
        bf16_split2(pa1.x, pa1.y, hi, lo); Ah[buf][lrow + 32][lp] = hi; Al[buf][lrow + 32][lp] = lo;
        bf16_split2(pa1.z, pa1.w, hi, lo); Ah[buf][lrow + 32][lp + 1] = hi; Al[buf][lrow + 32][lp + 1] = lo;
        bf16_split2(pw0.x, pw0.y, hi, lo); Wh[buf][lrow][lp] = hi; Wl[buf][lrow][lp] = lo;
        bf16_split2(pw0.z, pw0.w, hi, lo); Wh[buf][lrow][lp + 1] = hi; Wl[buf][lrow][lp + 1] = lo;
        bf16_split2(pw1.x, pw1.y, hi, lo); Wh[buf][lrow + 32][lp] = hi; Wl[buf][lrow + 32][lp] = lo;
        bf16_split2(pw1.z, pw1.w, hi, lo); Wh[buf][lrow + 32][lp + 1] = hi; Wl[buf][lrow + 32][lp + 1] = lo;
        __syncthreads();

        if (k0 + 16 < DSTATE) {
            pa0 = *(const float4*)(Aptr0 + k0 + 16);
            pa1 = *(const float4*)(Aptr1 + k0 + 16);
            pw0 = *(const float4*)(Wptr0 + k0 + 16);
            pw1 = *(const float4*)(Wptr1 + k0 + 16);
        }

        unsigned ah[2][4], al[2][4];
#pragma unroll
        for (int mt = 0; mt < 2; mt++) {
            int r = wm + mt * 16;
            ah[mt][0] = Ah[buf][r + g][qd];     ah[mt][1] = Ah[buf][r + g + 8][qd];
            ah[mt][2] = Ah[buf][r + g][qd + 4]; ah[mt][3] = Ah[buf][r + g + 8][qd + 4];
            al[mt][0] = Al[buf][r + g][qd];     al[mt][1] = Al[buf][r + g + 8][qd];
            al[mt][2] = Al[buf][r + g][qd + 4]; al[mt][3] = Al[buf][r + g + 8][qd + 4];
        }
#pragma unroll
        for (int nt = 0; nt < 4; nt++) {
            int cn = wn + nt * 8 + g;
            unsigned bh0 = Wh[buf][cn][qd], bh1 = Wh[buf][cn][qd + 4];
            unsigned bl0 = Wl[buf][cn][qd], bl1 = Wl[buf][cn][qd + 4];
#pragma unroll
            for (int mt = 0; mt < 2; mt++) {
                mma_bf16(c[mt][nt], ah[mt][0], ah[mt][1], ah[mt][2], ah[mt][3], bh0, bh1);
                mma_bf16(c[mt][nt], ah[mt][0], ah[mt][1], ah[mt][2], ah[mt][3], bl0, bl1);
                mma_bf16(c[mt][nt], al[mt][0], al[mt][1], al[mt][2], al[mt][3], bh0, bh1);
            }
        }
        buf ^= 1;
    }

    float* Gout = g_G + (size_t)(b * NCHUNK + cch) * (CHUNK * CHUNK);
#pragma unroll
    for (int mt = 0; mt < 2; mt++) {
#pragma unroll
        for (int nt = 0; nt < 4; nt++) {
            int row = wm + mt * 16 + g;
            int col = wn + nt * 8 + 2 * qd;
            *(float2*)(Gout + (size_t)row * CHUNK + col) =
                make_float2(c[mt][nt][0], c[mt][nt][1]);
            *(float2*)(Gout + (size_t)(row + 8) * CHUNK + col) =
                make_float2(c[mt][nt][2], c[mt][nt][3]);
        }
    }
}

// ---------------- pass B: sequential combine with batched prefetch ----------
__global__ void __launch_bounds__(256) combine_state_kernel()
{
    int idx = blockIdx.x * blockDim.x + threadIdx.x;
    int nq = idx & 63;
    int p  = (idx >> 6) & 63;
    int bh = idx >> 12;
    float2 H = make_float2(0.f, 0.f);
    const float* Pb = g_P + bh * NCHUNK;
    size_t base = (((size_t)bh * NCHUNK) * HEADDIM + p) * DSTATE + nq * 2;
    const size_t cstride = (size_t)HEADDIM * DSTATE;

    for (int cc0 = 0; cc0 < NCHUNK; cc0 += 8) {
        float2 S[8];
#pragma unroll
        for (int j = 0; j < 8; j++)
            S[j] = *(const float2*)&g_state[base + (size_t)(cc0 + j) * cstride];
#pragma unroll
        for (int j = 0; j < 8; j++) {
            *(float2*)&g_H0[base + (size_t)(cc0 + j) * cstride] = H;
            float P = Pb[cc0 + j];
            H.x = S[j].x + P * H.x;
            H.y = S[j].y + P * H.y;
        }
    }
}

// ---------------- scan Y kernel: y = M@X + (a_t C)@H0^T (tensor cores) ------
__global__ void __launch_bounds__(128) scan_y_kernel()
{
    __shared__ unsigned U0[64][33], U1[64][33], U2[64][33], U3[64][33];
    __shared__ float sla[64], sdt[64];

    const int cch = blockIdx.x & 31;
    const int h = (blockIdx.x >> 5) & 7;
    const int b = blockIdx.x >> 8;
    const int bh = b * NHEADS + h;
    const int t0 = cch * CHUNK;
    const int tid = threadIdx.x;
    const int w = tid >> 5, lane = tid & 31;
    const int qd = lane & 3, g = lane >> 2;
    const int wm = (w & 1) * 32, wn = (w >> 1) * 32;

    if (tid < 64) {
        sla[tid] = g_la[(size_t)bh * LSEQ + t0 + tid];
        sdt[tid] = g_dt[(size_t)(b * LSEQ + t0 + tid) * NHEADS + h];
    }
    __syncthreads();

    // build M = G * L * dt (masked, split bf16, pairs along s)
    const float* Gp = g_G + (size_t)(b * NCHUNK + cch) * (CHUNK * CHUNK);
#pragma unroll
    for (int i = 0; i < 16; i++) {
        int idx = tid + i * 128;
        int t = idx >> 5, sp = idx & 31;
        int s0 = 2 * sp, s1 = s0 + 1;
        float m0 = (s0 <= t) ? Gp[t * 64 + s0] * __expf(sla[t] - sla[s0]) * sdt[s0] : 0.f;
        float m1 = (s1 <= t) ? Gp[t * 64 + s1] * __expf(sla[t] - sla[s1]) * sdt[s1] : 0.f;
        unsigned hi, lo; bf16_split2(m0, m1, hi, lo);
        U0[t][sp] = hi; U1[t][sp] = lo;
    }
    // build X^T (p rows, pairs along s)
    const float* xb = g_xBC + (size_t)(b * LSEQ + t0) * CONVDIM + h * HEADDIM;
#pragma unroll
    for (int i = 0; i < 16; i++) {
        int idx = tid + i * 128;
        int p = idx >> 5, sp = idx & 31;
        float v0 = xb[(size_t)(2 * sp) * CONVDIM + p];
        float v1 = xb[(size_t)(2 * sp + 1) * CONVDIM + p];
        unsigned hi, lo; bf16_split2(v0, v1, hi, lo);
        U2[p][sp] = hi; U3[p][sp] = lo;
    }
    __syncthreads();

    float c[2][4][4];
#pragma unroll
    for (int mt = 0; mt < 2; mt++)
#pragma unroll
        for (int nt = 0; nt < 4; nt++)
#pragma unroll
            for (int i = 0; i < 4; i++) c[mt][nt][i] = 0.f;

    // phase 1: Y += M @ X  (K = 64 s values = 4 slabs)
#pragma unroll
    for (int ks = 0; ks < 4; ks++) {
        unsigned ah[2][4], al[2][4];
#pragma unroll
        for (int mt = 0; mt < 2; mt++) {
            int r = wm + mt * 16;
            ah[mt][0] = U0[r + g][8 * ks + qd];     ah[mt][1] = U0[r + g + 8][8 * ks + qd];
            ah[mt][2] = U0[r + g][8 * ks + qd + 4]; ah[mt][3] = U0[r + g + 8][8 * ks + qd + 4];
            al[mt][0] = U1[r + g][8 * ks + qd];     al[mt][1] = U1[r + g + 8][8 * ks + qd];
            al[mt][2] = U1[r + g][8 * ks + qd + 4]; al[mt][3] = U1[r + g + 8][8 * ks + qd + 4];
        }
#pragma unroll
        for (int nt = 0; nt < 4; nt++) {
            int cn = wn + nt * 8 + g;
            unsigned bh0 = U2[cn][8 * ks + qd], bh1 = U2[cn][8 * ks + qd + 4];
            unsigned bl0 = U3[cn][8 * ks + qd], bl1 = U3[cn][8 * ks + qd + 4];
#pragma unroll
            for (int mt = 0; mt < 2; mt++) {
                mma_bf16(c[mt][nt], ah[mt][0], ah[mt][1], ah[mt][2], ah[mt][3], bh0, bh1);
                mma_bf16(c[mt][nt], ah[mt][0], ah[mt][1], ah[mt][2], ah[mt][3], bl0, bl1);
                mma_bf16(c[mt][nt], al[mt][0], al[mt][1], al[mt][2], al[mt][3], bh0, bh1);
            }
        }
    }
    __syncthreads();

    // phase 2: Y += (a_t * C) @ H0^T  (K = 128 n, two halves of 64)
    const float* cb = g_xBC + (size_t)(b * LSEQ + t0) * CONVDIM + DINNER + DSTATE;
    const float* h0b = g_H0 + (((size_t)bh * NCHUNK + cch) * HEADDIM) * DSTATE;
    for (int nh = 0; nh < 2; nh++) {
#pragma unroll
        for (int i = 0; i < 16; i++) {
            int idx = tid + i * 128;
            int t = idx >> 5, np = idx & 31;
            float at = __expf(sla[t]);
            int nn = nh * 64 + 2 * np;
            float c0 = at * cb[(size_t)t * CONVDIM + nn];
            float c1 = at * cb[(size_t)t * CONVDIM + nn + 1];
            unsigned hi, lo; bf16_split2(c0, c1, hi, lo);
            U0[t][np] = hi; U1[t][np] = lo;
        }
#pragma unroll
        for (int i = 0; i < 16; i++) {
            int idx = tid + i * 128;
            int p = idx >> 5, np = idx & 31;
            int nn = nh * 64 + 2 * np;
            float v0 = h0b[(size_t)p * DSTATE + nn];
            float v1 = h0b[(size_t)p * DSTATE + nn + 1];
            unsigned hi, lo; bf16_split2(v0, v1, hi, lo);
            U2[p][np] = hi; U3[p][np] = lo;
        }
        __syncthreads();
#pragma unroll
        for (int ks = 0; ks < 4; ks++) {
            unsigned ah[2][4], al[2][4];
#pragma unroll
            for (int mt = 0; mt < 2; mt++) {
                int r = wm + mt * 16;
                ah[mt][0] = U0[r + g][8 * ks + qd];     ah[mt][1] = U0[r + g + 8][8 * ks + qd];
                ah[mt][2] = U0[r + g][8 * ks + qd + 4]; ah[mt][3] = U0[r + g + 8][8 * ks + qd + 4];
                al[mt][0] = U1[r + g][8 * ks + qd];     al[mt][1] = U1[r + g + 8][8 * ks + qd];
                al[mt][2] = U1[r + g][8 * ks + qd + 4]; al[mt][3] = U1[r + g + 8][8 * ks + qd + 4];
            }
#pragma unroll
            for (int nt = 0; nt < 4; nt++) {
                int cn = wn + nt * 8 + g;
                unsigned bh0 = U2[cn][8 * ks + qd], bh1 = U2[cn][8 * ks + qd + 4];
                unsigned bl0 = U3[cn][8 * ks + qd], bl1 = U3[cn][8 * ks + qd + 4];
#pragma unroll
                for (int mt = 0; mt < 2; mt++) {
                    mma_bf16(c[mt][nt], ah[mt][0], ah[mt][1], ah[mt][2], ah[mt][3], bh0, bh1);
                    mma_bf16(c[mt][nt], ah[mt][0], ah[mt][1], ah[mt][2], ah[mt][3], bl0, bl1);
                    mma_bf16(c[mt][nt], al[mt][0], al[mt][1], al[mt][2], al[mt][3], bh0, bh1);
                }
            }
        }
        __syncthreads();
    }

    // epilogue: write y
#pragma unroll
    for (int mt = 0; mt < 2; mt++) {
#pragma unroll
        for (int nt = 0; nt < 4; nt++) {
            int trow = wm + mt * 16 + g;
            int col = wn + nt * 8 + 2 * qd;
            *(float2*)(g_y + (size_t)(b * LSEQ + t0 + trow) * DINNER + h * HEADDIM + col) =
                make_float2(c[mt][nt][0], c[mt][nt][1]);
            *(float2*)(g_y + (size_t)(b * LSEQ + t0 + trow + 8) * DINNER + h * HEADDIM + col) =
                make_float2(c[mt][nt][2], c[mt][nt][3]);
        }
    }
}

// ---------------- gate + RMSNorm ----------------
__global__ void __launch_bounds__(512) gate_rms_kernel(const float* __restrict__ D_param,
                                                       const float* __restrict__ norm_w)
{
    int bl = blockIdx.x;
    int d = threadIdx.x;
    float y = g_y[(size_t)bl * DINNER + d] +
              D_param[d >> 6] * g_xBC[(size_t)bl * CONVDIM + d];
    float z = g_zxbcdt[(size_t)bl * DINPROJ + d];
    float g = y * (z / (1.f + __expf(-z)));

    __shared__ float sh[16];
    float s = g * g;
    int lane = d & 31, w = d >> 5;
#pragma unroll
    for (int o = 16; o; o >>= 1) s += __shfl_xor_sync(0xffffffffu, s, o);
    if (lane == 0) sh[w] = s;
    __syncthreads();
    if (w == 0) {
        float v = (lane < 16) ? sh[lane] : 0.f;
#pragma unroll
        for (int o = 16; o; o >>= 1) v += __shfl_xor_sync(0xffffffffu, v, o);
        if (lane == 0) sh[0] = v;
    }
    __syncthreads();
    float scale = rsqrtf(sh[0] * (1.f / DINNER) + 1e-5f);
    g_y[(size_t)bl * DINNER + d] = g * scale * norm_w[d];
}

// ---------------- V packing (split bf16 hi/lo, key-paired) ----------------
__global__ void __launch_bounds__(256) v_pack_kernel()
{
    int idx = blockIdx.x * blockDim.x + threadIdx.x;
    int d  = idx & 31;
    int kp = (idx >> 5) & 1023;
    int h  = (idx >> 15) & 7;
    int b  = idx >> 18;
    size_t src = ((size_t)(b * LSEQ + 2 * kp)) * DMODEL + h * AHD + d;
    float v0 = g_v[src];
    float v1 = g_v[src + DMODEL];
    unsigned hi, lo;
    bf16_split2(v0, v1, hi, lo);
    g_vhi[idx] = hi;
    g_vlo[idx] = lo;
}

// ---------------- flash attention: 128 queries/block, split-bf16 V ----------
__global__ void __launch_bounds__(256) attn_mma_kernel()
{
    __shared__ float Qs[128][40];
    __shared__ float Ks[64][40];
    __shared__ unsigned Vh[32][40];
    __shared__ unsigned Vl[32][40];

    const int q0 = blockIdx.x * 128;
    const int h = blockIdx.y;
    const int b = blockIdx.z;
    const int tid = threadIdx.x;
    const int w = tid >> 5, lane = tid & 31;
    const int qd = lane & 3, g = lane >> 2;

    const size_t base = (size_t)b * LSEQ * DMODEL + h * AHD;
    const unsigned* vhib = g_vhi + ((size_t)(b * NHEADS + h)) * 1024 * 32;
    const unsigned* vlob = g_vlo + ((size_t)(b * NHEADS + h)) * 1024 * 32;

#pragma unroll
    for (int i = 0; i < 4; i++) {
        int e = tid + i * 256;
        int row = e >> 3, c4 = (e & 7) * 4;
        *(float4*)&Qs[row][c4] =
            *(const float4*)(g_qp + base + (size_t)(q0 + row) * DMODEL + c4);
    }
    __syncthreads();

    unsigned qa[4][4];
#pragma unroll
    for (int ks = 0; ks < 4; ks++) {
        int r = w * 16;
        qa[ks][0] = __float_as_uint(Qs[r + g][8 * ks + qd]);
        qa[ks][1] = __float_as_uint(Qs[r + g + 8][8 * ks + qd]);
        qa[ks][2] = __float_as_uint(Qs[r + g][8 * ks + qd + 4]);
        qa[ks][3] = __float_as_uint(Qs[r + g + 8][8 * ks + qd + 4]);
    }

    float m0 = -1e30f, m1 = -1e30f, l0 = 0.f, l1 = 0.f;
    float o[4][4];
#pragma unroll
    for (int nt = 0; nt < 4; nt++)
#pragma unroll
        for (int i = 0; i < 4; i++) o[nt][i] = 0.f;

    for (int kt = 0; kt < LSEQ / 64; kt++) {
        __syncthreads();
#pragma unroll
        for (int i = 0; i < 2; i++) {
            int e = tid + i * 256;
            int row = e >> 3, c4 = (e & 7) * 4;
            *(float4*)&Ks[row][c4] =
                *(const float4*)(g_kp + base + (size_t)(kt * 64 + row) * DMODEL + c4);
        }
        {
            int kp = tid >> 3, q4 = (tid & 7) * 4;
            size_t gsrc = (size_t)(kt * 32 + kp) * 32 + q4;
            *(uint4*)&Vh[kp][q4] = *(const uint4*)(vhib + gsrc);
            *(uint4*)&Vl[kp][q4] = *(const uint4*)(vlob + gsrc);
        }
        __syncthreads();

        float s[8][4];
#pragma unroll
        for (int nt = 0; nt < 8; nt++)
#pragma unroll
            for (int i = 0; i < 4; i++) s[nt][i] = 0.f;
#pragma unroll
        for (int ks = 0; ks < 4; ks++) {
#pragma unroll
            for (int nt = 0; nt < 8; nt++) {
                unsigned b0 = __float_as_uint(Ks[nt * 8 + g][8 * ks + qd]);
                unsigned b1 = __float_as_uint(Ks[nt * 8 + g][8 * ks + qd + 4]);
                mma_tf32(s[nt], qa[ks], b0, b1);
            }
        }

        float r0 = -1e30f, r1 = -1e30f;
#pragma unroll
        for (int nt = 0; nt < 8; nt++) {
            r0 = fmaxf(r0, fmaxf(s[nt][0], s[nt][1]));
            r1 = fmaxf(r1, fmaxf(s[nt][2], s[nt][3]));
        }
        r0 = fmaxf(r0, __shfl_xor_sync(0xffffffffu, r0, 1));
        r0 = fmaxf(r0, __shfl_xor_sync(0xffffffffu, r0, 2));
        r1 = fmaxf(r1, __shfl_xor_sync(0xffffffffu, r1, 1));
        r1 = fmaxf(r1, __shfl_xor_sync(0xffffffffu, r1, 2));
        float nm0 = fmaxf(m0, r0), nm1 = fmaxf(m1, r1);
        float cf0 = __expf(m0 - nm0), cf1 = __expf(m1 - nm1);
        m0 = nm0; m1 = nm1;
        l0 *= cf0; l1 *= cf1;
#pragma unroll
        for (int nt = 0; nt < 4; nt++) {
            o[nt][0] *= cf0; o[nt][1] *= cf0;
            o[nt][2] *= cf1; o[nt][3] *= cf1;
        }

        unsigned plo[8], phi[8];
#pragma unroll
        for (int nt = 0; nt < 8; nt++) {
            float p0 = __expf(s[nt][0] - m0);
            float p1 = __expf(s[nt][1] - m0);
            float p2 = __expf(s[nt][2] - m1);
            float p3 = __expf(s[nt][3] - m1);
            l0 += p0 + p1;
            l1 += p2 + p3;
            __nv_bfloat162 lo = __floats2bfloat162_rn(p0, p1);
            __nv_bfloat162 hi = __floats2bfloat162_rn(p2, p3);
            plo[nt] = *(unsigned*)&lo;
            phi[nt] = *(unsigned*)&hi;
        }

#pragma unroll
        for (int kk = 0; kk < 4; kk++) {
            unsigned a0 = plo[2 * kk], a1 = phi[2 * kk];
            unsigned a2 = plo[2 * kk + 1], a3 = phi[2 * kk + 1];
#pragma unroll
            for (int nt = 0; nt < 4; nt++) {
                unsigned bh0 = Vh[kk * 8 + qd][nt * 8 + g];
                unsigned bh1 = Vh[kk * 8 + qd + 4][nt * 8 + g];
                mma_bf16(o[nt], a0, a1, a2, a3, bh0, bh1);
                unsigned bl0 = Vl[kk * 8 + qd][nt * 8 + g];
                unsigned bl1 = Vl[kk * 8 + qd + 4][nt * 8 + g];
                mma_bf16(o[nt], a0, a1, a2, a3, bl0, bl1);
            }
        }
    }

    l0 += __shfl_xor_sync(0xffffffffu, l0, 1);
    l0 += __shfl_xor_sync(0xffffffffu, l0, 2);
    l1 += __shfl_xor_sync(0xffffffffu, l1, 1);
    l1 += __shfl_xor_sync(0xffffffffu, l1, 2);

    float inv0 = 1.f / l0, inv1 = 1.f / l1;
    int row = q0 + w * 16 + g;
#pragma unroll
    for (int nt = 0; nt < 4; nt++) {
        int col = h * AHD + nt * 8 + 2 * qd;
        *(float2*)(g_o + (size_t)(b * LSEQ + row) * DMODEL + col) =
            make_float2(o[nt][0] * inv0, o[nt][1] * inv0);
        *(float2*)(g_o + (size_t)(b * LSEQ + row + 8) * DMODEL + col) =
            make_float2(o[nt][2] * inv1, o[nt][3] * inv1);
    }
}

// ---------------- LayerNorm over 1024 ----------------
__global__ void __launch_bounds__(256) layernorm_kernel(const float* __restrict__ ln_w,
                                                        const float* __restrict__ ln_b)
{
    int bl = blockIdx.x, tid = threadIdx.x;
    float4 v = *(const float4*)(g_mlp + (size_t)bl * MLPH + tid * 4);
    float s = v.x + v.y + v.z + v.w;
    float s2 = v.x * v.x + v.y * v.y + v.z * v.z + v.w * v.w;

    __shared__ float shs[8], shs2[8];
    int lane = tid & 31, w = tid >> 5;
#pragma unroll
    for (int o = 16; o; o >>= 1) {
        s += __shfl_xor_sync(0xffffffffu, s, o);
        s2 += __shfl_xor_sync(0xffffffffu, s2, o);
    }
    if (lane == 0) { shs[w] = s; shs2[w] = s2; }
    __syncthreads();
    if (w == 0) {
        float a = (lane < 8) ? shs[lane] : 0.f;
        float b2 = (lane < 8) ? shs2[lane] : 0.f;
#pragma unroll
        for (int o = 4; o; o >>= 1) {
            a += __shfl_xor_sync(0xffffffffu, a, o);
            b2 += __shfl_xor_sync(0xffffffffu, b2, o);
        }
        if (lane == 0) { shs[0] = a; shs2[0] = b2; }
    }
    __syncthreads();
    float mu = shs[0] * (1.f / MLPH);
    float var = shs2[0] * (1.f / MLPH) - mu * mu;
    float inv = rsqrtf(var + 1e-5f);

    float4 wv = *(const float4*)(ln_w + tid * 4);
    float4 bv = *(const float4*)(ln_b + tid * 4);
    float4 r;
    r.x = (v.x - mu) * inv * wv.x + bv.x;
    r.y = (v.y - mu) * inv * wv.y + bv.y;
    r.z = (v.z - mu) * inv * wv.z + bv.z;
    r.w = (v.w - mu) * inv * wv.w + bv.w;
    *(float4*)(g_mlp + (size_t)bl * MLPH + tid * 4) = r;
}

// ---------------- two-stage mean-pool + head ----------------
__global__ void __launch_bounds__(256) pool1_kernel()
{
    int b = blockIdx.x, seg = blockIdx.y;
    int d = threadIdx.x;
    float s = 0.f;
    int t0 = seg * 128;
#pragma unroll 8
    for (int t = 0; t < 128; t++)
        s += g_h2[((size_t)(b * LSEQ + t0 + t)) * DMODEL + d];
    g_pool[(b * 16 + seg) * DMODEL + d] = s;
}

__global__ void __launch_bounds__(256) pool2_kernel(const float* __restrict__ head_w,
                                                    const float* __restrict__ head_b,
                                                    float* __restrict__ out)
{
    int b = blockIdx.x;
    int d = threadIdx.x;
    float s = 0.f;
#pragma unroll
    for (int seg = 0; seg < 16; seg++)
        s += g_pool[(b * 16 + seg) * DMODEL + d];
    __shared__ float pooled[DMODEL];
    pooled[d] = s * (1.f / LSEQ);
    __syncthreads();
    if (d < 2) {
        float accv = head_b[d];
        for (int j = 0; j < DMODEL; j++) accv += pooled[j] * head_w[d * DMODEL + j];
        out[b * 2 + d] = accv;
    }
}

// ---------------- host launcher ----------------
extern "C" void kernel_launch(void* const* d_in, const int* in_sizes, int n_in,
                              void* d_out, int out_size)
{
    (void)in_sizes; (void)n_in; (void)out_size;
    const float* x         = (const float*)d_in[0];
    const float* context   = (const float*)d_in[1];
    const float* in_proj_w = (const float*)d_in[2];
    const float* conv_w    = (const float*)d_in[3];
    const float* conv_b    = (const float*)d_in[4];
    const float* dt_bias   = (const float*)d_in[5];
    const float* A_log     = (const float*)d_in[6];
    const float* D_param   = (const float*)d_in[7];
    const float* norm_w    = (const float*)d_in[8];
    const float* out_proj_w= (const float*)d_in[9];
    const float* wq        = (const float*)d_in[10];
    const float* wk        = (const float*)d_in[11];
    const float* wv        = (const float*)d_in[12];
    const float* wo        = (const float*)d_in[13];
    const float* wo_b      = (const float*)d_in[14];
    const float* w1        = (const float*)d_in[15];
    const float* b1        = (const float*)d_in[16];
    const float* ln_w      = (const float*)d_in[17];
    const float* ln_b      = (const float*)d_in[18];
    const float* w2        = (const float*)d_in[19];
    const float* b2        = (const float*)d_in[20];
    const float* head_w    = (const float*)d_in[21];
    const float* head_b    = (const float*)d_in[22];
    float* out = (float*)d_out;

    float *p_zx, *p_y, *p_hres, *p_v, *p_o, *p_ob, *p_mlp, *p_h2, *p_qp, *p_kp;
    unsigned *p_whi, *p_wlo;
    cudaGetSymbolAddress((void**)&p_zx,   g_zxbcdt);
    cudaGetSymbolAddress((void**)&p_y,    g_y);
    cudaGetSymbolAddress((void**)&p_hres, g_hres);
    cudaGetSymbolAddress((void**)&p_v,    g_v);
    cudaGetSymbolAddress((void**)&p_o,    g_o);
    cudaGetSymbolAddress((void**)&p_ob,   g_ob);
    cudaGetSymbolAddress((void**)&p_mlp,  g_mlp);
    cudaGetSymbolAddress((void**)&p_h2,   g_h2);
    cudaGetSymbolAddress((void**)&p_qp,   g_qp);
    cudaGetSymbolAddress((void**)&p_kp,   g_kp);
    cudaGetSymbolAddress((void**)&p_whi,  g_whi);
    cudaGetSymbolAddress((void**)&p_wlo,  g_wlo);

    // 0) pre-split all weights into bf16 hi/lo
    pack_w_kernel<<<(WTOTAL + 255) / 256, 256>>>(
        in_proj_w, out_proj_w, wq, wk, wv, wo, w1, w2);
    // 1) in_proj (big tile)
    gemm128_kernel<EPI_NONE><<<dim3((DINPROJ + 127) / 128, M4 / 128), 256>>>(
        x, p_whi + WOFF_INPROJ, p_wlo + WOFF_INPROJ, nullptr, nullptr,
        p_zx, M4, DINPROJ, DMODEL);
    // 2) conv + dt/dA
    conv_dt_kernel<<<M4 / 16, CONVDIM>>>(conv_w, conv_b, dt_bias, A_log);
    // 3) SSD scan: G (C@B^T), state recurrence, combine, Y via tensor cores
    scan_g_kernel<<<BBATCH * NCHUNK, 128>>>();
    scan_chunk_kernel<<<4 * 8 * 2 * NCHUNK, 128>>>(A_log);
    combine_state_kernel<<<256, 256>>>();
    scan_y_kernel<<<BBATCH * NHEADS * NCHUNK, 128>>>();
    // 4) gate + RMSNorm
    gate_rms_kernel<<<M4, DINNER>>>(D_param, norm_w);
    // 5) out_proj + residual
    gemm_bf16_kernel<EPI_RES><<<dim3(DMODEL / 64, M4 / 64), 128>>>(
        p_y, p_whi + WOFF_OUTPROJ, p_wlo + WOFF_OUTPROJ, nullptr, x,
        p_hres, nullptr, M4, DMODEL, DINNER);
    // 6) Q projection (epilogue emits tf32-scaled g_qp)
    gemm_bf16_kernel<EPI_QPACK><<<dim3(DMODEL / 64, M4 / 64), 128>>>(
        p_hres, p_whi + WOFF_WQ, p_wlo + WOFF_WQ, nullptr, nullptr,
        p_qp, nullptr, M4, DMODEL, DMODEL);
    // 6b) fused K+V projection
    gemm_bf16_kernel<EPI_KV><<<dim3(512 / 64, M4 / 64), 128>>>(
        context, p_whi + WOFF_WK, p_wlo + WOFF_WK, nullptr, nullptr,
        p_kp, p_v, M4, 512, DMODEL);
    // 6c) V pack (split bf16 hi/lo)
    v_pack_kernel<<<(BBATCH * NHEADS * 1024 * 32) / 256, 256>>>();
    // 7) attention
    attn_mma_kernel<<<dim3(LSEQ / 128, NHEADS, BBATCH), 256>>>();
    // 8) attn out proj
    gemm_bf16_kernel<EPI_BIAS><<<dim3(DMODEL / 64, M4 / 64), 128>>>(
        p_o, p_whi + WOFF_WO, p_wlo + WOFF_WO, wo_b, nullptr,
        p_ob, nullptr, M4, DMODEL, DMODEL);
    // 9) MLP fc1 + GELU (big tile)
    gemm128_kernel<EPI_BIAS_GELU><<<dim3(MLPH / 128, M4 / 128), 256>>>(
        p_ob, p_whi + WOFF_W1, p_wlo + WOFF_W1, b1, nullptr,
        p_mlp, M4, MLPH, DMODEL);
    // 10) LayerNorm
    layernorm_kernel<<<M4, 256>>>(ln_w, ln_b);
    // 11) MLP fc2
    gemm_bf16_kernel<EPI_BIAS><<<dim3(DMODEL / 64, M4 / 64), 128>>>(
        p_mlp, p_whi + WOFF_W2, p_wlo + WOFF_W2, b2, nullptr,
        p_h2, nullptr, M4, DMODEL, MLPH);
    // 12) two-stage pool + head
    pool1_kernel<<<dim3(BBATCH, 16), 256>>>();
    pool2_kernel<<<BBATCH, 256>>>(head_w, head_b, out);
}

// round 11
// speedup vs baseline: 3.4647x; 1.0103x over previous
#include <cuda_runtime.h>
#include <cuda_bf16.h>
#include <math.h>

// ---------------- problem constants ----------------
#define BBATCH 2
#define LSEQ 2048
#define DMODEL 256
#define DINNER 512
#define DSTATE 128
#define NHEADS 8
#define HEADDIM 64
#define CONVDIM 768          // DINNER + 2*DSTATE
#define DINPROJ 1288         // 2*DINNER + 2*DSTATE + NHEADS
#define AHD 32               // attention head dim
#define MLPH 1024
#define M4 (BBATCH * LSEQ)   // 4096 rows
#define NCHUNK 32
#define CHUNK 64             // LSEQ / NCHUNK

// pre-split weight region offsets (in bf16x2-pair units; region K2 = K/2)
#define WOFF_INPROJ 0          // N=1288 K2=128
#define WOFF_OUTPROJ 164864    // N=256  K2=256
#define WOFF_WQ 230400         // N=256  K2=128
#define WOFF_WK 263168         // N=256  K2=128  (wv follows contiguously)
#define WOFF_WV 295936         // N=256  K2=128
#define WOFF_WO 328704         // N=256  K2=128
#define WOFF_W1 361472         // N=1024 K2=128
#define WOFF_W2 492544         // N=256  K2=512
#define WTOTAL 623616

// ---------------- scratch buffers ----------------
__device__ float g_zxbcdt[(size_t)M4 * DINPROJ];
__device__ float g_xBC[(size_t)M4 * CONVDIM];
__device__ float g_dt[M4 * NHEADS];
__device__ float g_y[(size_t)M4 * DINNER];
__device__ float g_hres[(size_t)M4 * DMODEL];
__device__ float g_v[(size_t)M4 * DMODEL];
__device__ float g_o[(size_t)M4 * DMODEL];
__device__ float g_ob[(size_t)M4 * DMODEL];
__device__ float g_mlp[(size_t)M4 * MLPH];
__device__ float g_h2[(size_t)M4 * DMODEL];
// chunked-scan buffers
__device__ float g_state[(size_t)BBATCH * NHEADS * NCHUNK * HEADDIM * DSTATE];
__device__ float g_H0[(size_t)BBATCH * NHEADS * NCHUNK * HEADDIM * DSTATE];
__device__ float g_P[BBATCH * NHEADS * NCHUNK];
__device__ float g_la[BBATCH * NHEADS * LSEQ];            // log-decay prefix (within chunk)
__device__ float g_G[(size_t)BBATCH * NCHUNK * CHUNK * CHUNK];   // C@B^T per (b,chunk)
// attention packed operands
__device__ float g_qp[(size_t)M4 * DMODEL];
__device__ float g_kp[(size_t)M4 * DMODEL];
__device__ unsigned g_vhi[(size_t)BBATCH * NHEADS * 1024 * 32];
__device__ unsigned g_vlo[(size_t)BBATCH * NHEADS * 1024 * 32];
// pooling partials
__device__ float g_pool[BBATCH * 16 * DMODEL];
// pre-split weights (bf16x2 hi / lo)
__device__ unsigned g_whi[WTOTAL + 64];
__device__ unsigned g_wlo[WTOTAL + 64];

// ---------------- helpers ----------------
__device__ __forceinline__ float to_tf32(float x) {
    unsigned r;
    asm("cvt.rna.tf32.f32 %0, %1;" : "=r"(r) : "f"(x));
    return __uint_as_float(r);
}

__device__ __forceinline__ void mma_tf32(float c[4], const unsigned a[4],
                                         unsigned b0, unsigned b1) {
    asm volatile(
        "mma.sync.aligned.m16n8k8.row.col.f32.tf32.tf32.f32 "
        "{%0,%1,%2,%3},{%4,%5,%6,%7},{%8,%9},{%0,%1,%2,%3};"
        : "+f"(c[0]), "+f"(c[1]), "+f"(c[2]), "+f"(c[3])
        : "r"(a[0]), "r"(a[1]), "r"(a[2]), "r"(a[3]), "r"(b0), "r"(b1));
}

__device__ __forceinline__ void mma_bf16(float c[4], unsigned a0, unsigned a1,
                                         unsigned a2, unsigned a3,
                                         unsigned b0, unsigned b1) {
    asm volatile(
        "mma.sync.aligned.m16n8k16.row.col.f32.bf16.bf16.f32 "
        "{%0,%1,%2,%3},{%4,%5,%6,%7},{%8,%9},{%0,%1,%2,%3};"
        : "+f"(c[0]), "+f"(c[1]), "+f"(c[2]), "+f"(c[3])
        : "r"(a0), "r"(a1), "r"(a2), "r"(a3), "r"(b0), "r"(b1));
}

// split a pair of floats into bf16x2 hi + lo words
__device__ __forceinline__ void bf16_split2(float x, float y,
                                            unsigned& hi, unsigned& lo) {
    __nv_bfloat16 hx = __float2bfloat16_rn(x);
    __nv_bfloat16 hy = __float2bfloat16_rn(y);
    __nv_bfloat16 lx = __float2bfloat16_rn(x - __bfloat162float(hx));
    __nv_bfloat16 ly = __float2bfloat16_rn(y - __bfloat162float(hy));
    __nv_bfloat162 hh = __halves2bfloat162(hx, hy);
    __nv_bfloat162 ll = __halves2bfloat162(lx, ly);
    hi = *(unsigned*)&hh;
    lo = *(unsigned*)&ll;
}

// fast erf (Abramowitz-Stegun 7.1.26, abs err < 1.5e-7)
__device__ __forceinline__ float fast_erf(float x) {
    float ax = fabsf(x);
    float t = __frcp_rn(1.f + 0.3275911f * ax);
    float p = 1.061405429f;
    p = p * t - 1.453152027f;
    p = p * t + 1.421413741f;
    p = p * t - 0.284496736f;
    p = p * t + 0.254829592f;
    float r = 1.f - p * t * __expf(-ax * ax);
    return copysignf(r, x);
}
__device__ __forceinline__ float gelu(float v) {
    return 0.5f * v * (1.f + fast_erf(v * 0.70710678118f));
}

// ---------------- weight pre-split pack ----------------
__global__ void __launch_bounds__(256) pack_w_kernel(
    const float* __restrict__ in_proj_w, const float* __restrict__ out_proj_w,
    const float* __restrict__ wq, const float* __restrict__ wk,
    const float* __restrict__ wv, const float* __restrict__ wo,
    const float* __restrict__ w1, const float* __restrict__ w2)
{
    int idx = blockIdx.x * 256 + threadIdx.x;
    if (idx >= WTOTAL) return;
    const float* src;
    int off, K2;
    if (idx < WOFF_OUTPROJ)      { src = in_proj_w;  off = WOFF_INPROJ;  K2 = 128; }
    else if (idx < WOFF_WQ)      { src = out_proj_w; off = WOFF_OUTPROJ; K2 = 256; }
    else if (idx < WOFF_WK)      { src = wq;         off = WOFF_WQ;      K2 = 128; }
    else if (idx < WOFF_WV)      { src = wk;         off = WOFF_WK;      K2 = 128; }
    else if (idx < WOFF_WO)      { src = wv;         off = WOFF_WV;      K2 = 128; }
    else if (idx < WOFF_W1)      { src = wo;         off = WOFF_WO;      K2 = 128; }
    else if (idx < WOFF_W2)      { src = w1;         off = WOFF_W1;      K2 = 128; }
    else                         { src = w2;         off = WOFF_W2;      K2 = 512; }
    int loc = idx - off;
    int n = loc / K2, kp = loc - n * K2;
    float x0 = src[(size_t)n * (K2 * 2) + 2 * kp];
    float x1 = src[(size_t)n * (K2 * 2) + 2 * kp + 1];
    unsigned hi, lo;
    bf16_split2(x0, x1, hi, lo);
    g_whi[idx] = hi;
    g_wlo[idx] = lo;
}

// ---------------- bf16 split GEMM (64x64 tile, double-buffered) -------------
enum { EPI_NONE = 0, EPI_BIAS = 1, EPI_BIAS_GELU = 2, EPI_RES = 3,
       EPI_QPACK = 4, EPI_KV = 5 };

template <int EPI>
__global__ void __launch_bounds__(128)
gemm_bf16_kernel(const float* __restrict__ A,
                 const unsigned* __restrict__ Whig, const unsigned* __restrict__ Wlog,
                 const float* __restrict__ bias, const float* __restrict__ res,
                 float* __restrict__ C, float* __restrict__ C2,
                 int M, int N, int K)
{
    __shared__ unsigned Ah[2][64][9], Al[2][64][9];
    __shared__ unsigned Wh[2][64][9], Wl[2][64][9];

    const int K2 = K >> 1;
    const int m0 = blockIdx.y * 64, n0 = blockIdx.x * 64;
    const int tid = threadIdx.x;
    const int w = tid >> 5, lane = tid & 31;
    const int qd = lane & 3, g = lane >> 2;
    const int wm = (w & 1) * 32, wn = (w >> 1) * 32;
    const int lrow = tid >> 2;        // 0..31
    const int lc4 = (tid & 3) * 4;    // K float offsets 0,4,8,12
    const int lp  = lc4 >> 1;         // pair index 0,2,4,6

    float c[2][4][4];
#pragma unroll
    for (int mt = 0; mt < 2; mt++)
#pragma unroll
        for (int nt = 0; nt < 4; nt++)
#pragma unroll
            for (int i = 0; i < 4; i++) c[mt][nt][i] = 0.f;

    const float* Aptr0 = A + (size_t)(m0 + lrow) * K + lc4;
    const float* Aptr1 = A + (size_t)(m0 + lrow + 32) * K + lc4;
    const bool wv0 = (n0 + lrow) < N;
    const bool wv1 = (n0 + lrow + 32) < N;
    const unsigned* Whp0 = Whig + (size_t)(wv0 ? (n0 + lrow) : 0) * K2 + lp;
    const unsigned* Wlp0 = Wlog + (size_t)(wv0 ? (n0 + lrow) : 0) * K2 + lp;
    const unsigned* Whp1 = Whig + (size_t)(wv1 ? (n0 + lrow + 32) : 0) * K2 + lp;
    const unsigned* Wlp1 = Wlog + (size_t)(wv1 ? (n0 + lrow + 32) : 0) * K2 + lp;

    float4 pa0 = *(const float4*)Aptr0;
    float4 pa1 = *(const float4*)Aptr1;
    uint2 ph0 = *(const uint2*)Whp0;
    uint2 pl0 = *(const uint2*)Wlp0;
    uint2 ph1 = *(const uint2*)Whp1;
    uint2 pl1 = *(const uint2*)Wlp1;

    int buf = 0;
    for (int k0 = 0; k0 < K; k0 += 16) {
        unsigned hi, lo;
        bf16_split2(pa0.x, pa0.y, hi, lo); Ah[buf][lrow][lp] = hi; Al[buf][lrow][lp] = lo;
        bf16_split2(pa0.z, pa0.w, hi, lo); Ah[buf][lrow][lp + 1] = hi; Al[buf][lrow][lp + 1] = lo;
        bf16_split2(pa1.x, pa1.y, hi, lo); Ah[buf][lrow + 32][lp] = hi; Al[buf][lrow + 32][lp] = lo;
        bf16_split2(pa1.z, pa1.w, hi, lo); Ah[buf][lrow + 32][lp + 1] = hi; Al[buf][lrow + 32][lp + 1] = lo;
        Wh[buf][lrow][lp] = ph0.x;      Wh[buf][lrow][lp + 1] = ph0.y;
        Wl[buf][lrow][lp] = pl0.x;      Wl[buf][lrow][lp + 1] = pl0.y;
        Wh[buf][lrow + 32][lp] = ph1.x; Wh[buf][lrow + 32][lp + 1] = ph1.y;
        Wl[buf][lrow + 32][lp] = pl1.x; Wl[buf][lrow + 32][lp + 1] = pl1.y;
        __syncthreads();

        if (k0 + 16 < K) {
            int kpn = (k0 + 16) >> 1;
            pa0 = *(const float4*)(Aptr0 + k0 + 16);
            pa1 = *(const float4*)(Aptr1 + k0 + 16);
            ph0 = *(const uint2*)(Whp0 + kpn);
            pl0 = *(const uint2*)(Wlp0 + kpn);
            ph1 = *(const uint2*)(Whp1 + kpn);
            pl1 = *(const uint2*)(Wlp1 + kpn);
        }

        unsigned ah[2][4], al[2][4];
#pragma unroll
        for (int mt = 0; mt < 2; mt++) {
            int r = wm + mt * 16;
            ah[mt][0] = Ah[buf][r + g][qd];     ah[mt][1] = Ah[buf][r + g + 8][qd];
            ah[mt][2] = Ah[buf][r + g][qd + 4]; ah[mt][3] = Ah[buf][r + g + 8][qd + 4];
            al[mt][0] = Al[buf][r + g][qd];     al[mt][1] = Al[buf][r + g + 8][qd];
            al[mt][2] = Al[buf][r + g][qd + 4]; al[mt][3] = Al[buf][r + g + 8][qd + 4];
        }
#pragma unroll
        for (int nt = 0; nt < 4; nt++) {
            int cn = wn + nt * 8 + g;
            unsigned bh0 = Wh[buf][cn][qd], bh1 = Wh[buf][cn][qd + 4];
            unsigned bl0 = Wl[buf][cn][qd], bl1 = Wl[buf][cn][qd + 4];
#pragma unroll
            for (int mt = 0; mt < 2; mt++) {
                mma_bf16(c[mt][nt], ah[mt][0], ah[mt][1], ah[mt][2], ah[mt][3], bh0, bh1);
                mma_bf16(c[mt][nt], ah[mt][0], ah[mt][1], ah[mt][2], ah[mt][3], bl0, bl1);
                mma_bf16(c[mt][nt], al[mt][0], al[mt][1], al[mt][2], al[mt][3], bh0, bh1);
            }
        }
        buf ^= 1;
    }

    const float qs = 0.1767766953f;   // 1/sqrt(32)
#pragma unroll
    for (int mt = 0; mt < 2; mt++) {
#pragma unroll
        for (int nt = 0; nt < 4; nt++) {
            int row = m0 + wm + mt * 16 + g;
            int col = n0 + wn + nt * 8 + 2 * qd;
            if (col >= N) continue;
            float v0 = c[mt][nt][0], v1 = c[mt][nt][1];
            float v2 = c[mt][nt][2], v3 = c[mt][nt][3];
            if (EPI == EPI_BIAS || EPI == EPI_BIAS_GELU) {
                float2 bv = *(const float2*)(bias + col);
                v0 += bv.x; v1 += bv.y; v2 += bv.x; v3 += bv.y;
            }
            if (EPI == EPI_BIAS_GELU) {
                v0 = gelu(v0); v1 = gelu(v1); v2 = gelu(v2); v3 = gelu(v3);
            }
            if (EPI == EPI_RES) {
                float2 r0 = *(const float2*)(res + (size_t)row * N + col);
                float2 r1 = *(const float2*)(res + (size_t)(row + 8) * N + col);
                v0 += r0.x; v1 += r0.y; v2 += r1.x; v3 += r1.y;
            }
            if (EPI == EPI_QPACK) {
                *(float2*)(C + (size_t)row * N + col) =
                    make_float2(to_tf32(v0 * qs), to_tf32(v1 * qs));
                *(float2*)(C + (size_t)(row + 8) * N + col) =
                    make_float2(to_tf32(v2 * qs), to_tf32(v3 * qs));
            } else if (EPI == EPI_KV) {
                if (col < DMODEL) {
                    *(float2*)(C + (size_t)row * DMODEL + col) =
                        make_float2(to_tf32(v0), to_tf32(v1));
                    *(float2*)(C + (size_t)(row + 8) * DMODEL + col) =
                        make_float2(to_tf32(v2), to_tf32(v3));
                } else {
                    *(float2*)(C2 + (size_t)row * DMODEL + col - DMODEL) =
                        make_float2(v0, v1);
                    *(float2*)(C2 + (size_t)(row + 8) * DMODEL + col - DMODEL) =
                        make_float2(v2, v3);
                }
            } else {
                *(float2*)(C + (size_t)row * N + col) = make_float2(v0, v1);
                *(float2*)(C + (size_t)(row + 8) * N + col) = make_float2(v2, v3);
            }
        }
    }
}

// ---------------- bf16 split GEMM (128x128 tile, 256 threads) ----------------
template <int EPI>
__global__ void __launch_bounds__(256, 2)
gemm128_kernel(const float* __restrict__ A,
               const unsigned* __restrict__ Whig, const unsigned* __restrict__ Wlog,
               const float* __restrict__ bias, const float* __restrict__ res,
               float* __restrict__ C, int M, int N, int K)
{
    __shared__ unsigned Ah[128][9], Al[128][9];
    __shared__ unsigned Wh[128][9], Wl[128][9];

    const int K2 = K >> 1;
    const int m0 = blockIdx.y * 128, n0 = blockIdx.x * 128;
    const int tid = threadIdx.x;
    const int w = tid >> 5, lane = tid & 31;
    const int qd = lane & 3, g = lane >> 2;
    const int wm = (w & 1) * 64;
    const int wn = (w >> 1) * 32;
    const int lrow = tid >> 1;
    const int lc8 = (tid & 1) * 8;
    const int lp  = lc8 >> 1;

    float c[4][4][4];
#pragma unroll
    for (int mt = 0; mt < 4; mt++)
#pragma unroll
        for (int nt = 0; nt < 4; nt++)
#pragma unroll
            for (int i = 0; i < 4; i++) c[mt][nt][i] = 0.f;

    const float* Aptr = A + (size_t)(m0 + lrow) * K + lc8;
    const bool wvalid = (n0 + lrow) < N;
    const unsigned* Whp = Whig + (size_t)(wvalid ? (n0 + lrow) : 0) * K2 + lp;
    const unsigned* Wlp = Wlog + (size_t)(wvalid ? (n0 + lrow) : 0) * K2 + lp;

    float4 pa0 = *(const float4*)Aptr;
    float4 pa1 = *(const float4*)(Aptr + 4);
    uint4 ph = *(const uint4*)Whp;
    uint4 pl = *(const uint4*)Wlp;

    for (int k0 = 0; k0 < K; k0 += 16) {
        unsigned hi, lo;
        bf16_split2(pa0.x, pa0.y, hi, lo); Ah[lrow][lp] = hi;     Al[lrow][lp] = lo;
        bf16_split2(pa0.z, pa0.w, hi, lo); Ah[lrow][lp + 1] = hi; Al[lrow][lp + 1] = lo;
        bf16_split2(pa1.x, pa1.y, hi, lo); Ah[lrow][lp + 2] = hi; Al[lrow][lp + 2] = lo;
        bf16_split2(pa1.z, pa1.w, hi, lo); Ah[lrow][lp + 3] = hi; Al[lrow][lp + 3] = lo;
        Wh[lrow][lp] = ph.x; Wh[lrow][lp + 1] = ph.y;
        Wh[lrow][lp + 2] = ph.z; Wh[lrow][lp + 3] = ph.w;
        Wl[lrow][lp] = pl.x; Wl[lrow][lp + 1] = pl.y;
        Wl[lrow][lp + 2] = pl.z; Wl[lrow][lp + 3] = pl.w;
        __syncthreads();

        if (k0 + 16 < K) {
            int kpn = (k0 + 16) >> 1;
            pa0 = *(const float4*)(Aptr + k0 + 16);
            pa1 = *(const float4*)(Aptr + k0 + 20);
            ph = *(const uint4*)(Whp + kpn);
            pl = *(const uint4*)(Wlp + kpn);
        }

        unsigned ah[4][4], al[4][4];
#pragma unroll
        for (int mt = 0; mt < 4; mt++) {
            int r = wm + mt * 16;
            ah[mt][0] = Ah[r + g][qd];     ah[mt][1] = Ah[r + g + 8][qd];
            ah[mt][2] = Ah[r + g][qd + 4]; ah[mt][3] = Ah[r + g + 8][qd + 4];
            al[mt][0] = Al[r + g][qd];     al[mt][1] = Al[r + g + 8][qd];
            al[mt][2] = Al[r + g][qd + 4]; al[mt][3] = Al[r + g + 8][qd + 4];
        }
#pragma unroll
        for (int nt = 0; nt < 4; nt++) {
            int cn = wn + nt * 8 + g;
            unsigned bh0 = Wh[cn][qd], bh1 = Wh[cn][qd + 4];
            unsigned bl0 = Wl[cn][qd], bl1 = Wl[cn][qd + 4];
#pragma unroll
            for (int mt = 0; mt < 4; mt++) {
                mma_bf16(c[mt][nt], ah[mt][0], ah[mt][1], ah[mt][2], ah[mt][3], bh0, bh1);
                mma_bf16(c[mt][nt], ah[mt][0], ah[mt][1], ah[mt][2], ah[mt][3], bl0, bl1);
                mma_bf16(c[mt][nt], al[mt][0], al[mt][1], al[mt][2], al[mt][3], bh0, bh1);
            }
        }
        __syncthreads();
    }

#pragma unroll
    for (int mt = 0; mt < 4; mt++) {
#pragma unroll
        for (int nt = 0; nt < 4; nt++) {
            int row = m0 + wm + mt * 16 + g;
            int col = n0 + wn + nt * 8 + 2 * qd;
            if (col >= N) continue;
            float v0 = c[mt][nt][0], v1 = c[mt][nt][1];
            float v2 = c[mt][nt][2], v3 = c[mt][nt][3];
            if (EPI == EPI_BIAS || EPI == EPI_BIAS_GELU) {
                float2 bv = *(const float2*)(bias + col);
                v0 += bv.x; v1 += bv.y; v2 += bv.x; v3 += bv.y;
            }
            if (EPI == EPI_BIAS_GELU) {
                v0 = gelu(v0); v1 = gelu(v1); v2 = gelu(v2); v3 = gelu(v3);
            }
            if (EPI == EPI_RES) {
                float2 r0 = *(const float2*)(res + (size_t)row * N + col);
                float2 r1 = *(const float2*)(res + (size_t)(row + 8) * N + col);
                v0 += r0.x; v1 += r0.y; v2 += r1.x; v3 += r1.y;
            }
            *(float2*)(C + (size_t)row * N + col) = make_float2(v0, v1);
            *(float2*)(C + (size_t)(row + 8) * N + col) = make_float2(v2, v3);
        }
    }
}

// ---------------- conv1d: 16 timesteps per block ----------------
__global__ void __launch_bounds__(CONVDIM) conv_dt_kernel(
    const float* __restrict__ conv_w, const float* __restrict__ conv_b,
    const float* __restrict__ dt_bias, const float* __restrict__ A_log)
{
    int blk = blockIdx.x;
    int b = blk >> 7;
    int l0 = (blk & 127) << 4;
    int c = threadIdx.x;

    const float* src = g_zxbcdt + (size_t)b * LSEQ * DINPROJ + DINNER + c;
    float cw0 = conv_w[c * 4 + 0], cw1 = conv_w[c * 4 + 1];
    float cw2 = conv_w[c * 4 + 2], cw3 = conv_w[c * 4 + 3];
    float cb = conv_b[c];

    float x0 = 0.f, x1 = 0.f, x2 = 0.f;
    if (l0 >= 3) {
        x0 = src[(size_t)(l0 - 3) * DINPROJ];
        x1 = src[(size_t)(l0 - 2) * DINPROJ];
        x2 = src[(size_t)(l0 - 1) * DINPROJ];
    }
    float* dst = g_xBC + (size_t)(b * LSEQ + l0) * CONVDIM + c;
#pragma unroll
    for (int tl = 0; tl < 16; tl++) {
        float x3 = src[(size_t)(l0 + tl) * DINPROJ];
        float accv = cb + cw0 * x0 + cw1 * x1 + cw2 * x2 + cw3 * x3;
        dst[(size_t)tl * CONVDIM] = accv / (1.f + __expf(-accv));
        x0 = x1; x1 = x2; x2 = x3;
    }

    if (c < NHEADS) {
        float db = dt_bias[c];
        const float* dsrc = g_zxbcdt + (size_t)(b * LSEQ + l0) * DINPROJ + DINNER + CONVDIM + c;
#pragma unroll
        for (int tl = 0; tl < 16; tl++) {
            float v = dsrc[(size_t)tl * DINPROJ] + db;
            float dt = (v > 20.f) ? v : log1pf(__expf(v));
            g_dt[(b * LSEQ + l0 + tl) * NHEADS + c] = dt;
        }
    }
}

// ---------------- la prefix kernel: one warp per (bh, chunk) ----------------
__global__ void __launch_bounds__(128) la_kernel(const float* __restrict__ A_log)
{
    int wid = (blockIdx.x * 128 + threadIdx.x) >> 5;   // 0..511
    int lane = threadIdx.x & 31;
    int cch = wid & 31;
    int bh = wid >> 5;                                 // 0..15
    int h = bh & 7, b = bh >> 3;
    float aexp = __expf(A_log[h]);
    int t0 = cch * CHUNK;

    const float* dtb = g_dt + (size_t)(b * LSEQ + t0) * NHEADS + h;
    float d0 = dtb[(size_t)(2 * lane) * NHEADS];
    float d1 = dtb[(size_t)(2 * lane + 1) * NHEADS];
    float acc = d0 + d1;
#pragma unroll
    for (int o = 1; o < 32; o <<= 1) {
        float nv = __shfl_up_sync(0xffffffffu, acc, o);
        if (lane >= o) acc += nv;
    }
    float la1 = -aexp * acc;
    float la0 = -aexp * (acc - d1);
    g_la[(size_t)bh * LSEQ + t0 + 2 * lane] = la0;
    g_la[(size_t)bh * LSEQ + t0 + 2 * lane + 1] = la1;
    if (lane == 31)
        g_P[bh * NCHUNK + cch] = __expf(la1);
}

// ---------------- scan state kernel: H = (w.X)^T @ B (tensor cores) ---------
// H[p][n] = sum_s exp(la_end - la_s) * dt_s * x_s[p] * B_s[n]
__global__ void __launch_bounds__(128) scan_state_kernel()
{
    __shared__ unsigned U0[64][33], U1[64][33], U2[64][33], U3[64][33];
    __shared__ float sw[64];

    const int nh = blockIdx.x & 1;
    const int cch = (blockIdx.x >> 1) & 31;
    const int h = (blockIdx.x >> 6) & 7;
    const int b = blockIdx.x >> 9;
    const int bh = b * NHEADS + h;
    const int t0 = cch * CHUNK;
    const int tid = threadIdx.x;
    const int w = tid >> 5, lane = tid & 31;
    const int qd = lane & 3, g = lane >> 2;
    const int wm = (w & 1) * 32, wn = (w >> 1) * 32;

    if (tid < 64) {
        float la = g_la[(size_t)bh * LSEQ + t0 + tid];
        float laend = g_la[(size_t)bh * LSEQ + t0 + 63];
        float dt = g_dt[(size_t)(b * LSEQ + t0 + tid) * NHEADS + h];
        sw[tid] = __expf(laend - la) * dt;
    }
    __syncthreads();

    // A operand: [p][s] = sw[s] * x[s][p]   (pairs along s)
    const float* xb = g_xBC + (size_t)(b * LSEQ + t0) * CONVDIM + h * HEADDIM;
#pragma unroll
    for (int i = 0; i < 16; i++) {
        int idx = tid + i * 128;
        int p = idx >> 5, sp = idx & 31;
        float v0 = sw[2 * sp] * xb[(size_t)(2 * sp) * CONVDIM + p];
        float v1 = sw[2 * sp + 1] * xb[(size_t)(2 * sp + 1) * CONVDIM + p];
        unsigned hi, lo; bf16_split2(v0, v1, hi, lo);
        U0[p][sp] = hi; U1[p][sp] = lo;
    }
    // W operand: [n][s] = B[s][nh*64 + n]   (pairs along s)
    const float* bb = g_xBC + (size_t)(b * LSEQ + t0) * CONVDIM + DINNER + nh * 64;
#pragma unroll
    for (int i = 0; i < 16; i++) {
        int idx = tid + i * 128;
        int n = idx >> 5, sp = idx & 31;
        float v0 = bb[(size_t)(2 * sp) * CONVDIM + n];
        float v1 = bb[(size_t)(2 * sp + 1) * CONVDIM + n];
        unsigned hi, lo; bf16_split2(v0, v1, hi, lo);
        U2[n][sp] = hi; U3[n][sp] = lo;
    }
    __syncthreads();

    float c[2][4][4];
#pragma unroll
    for (int mt = 0; mt < 2; mt++)
#pragma unroll
        for (int nt = 0; nt < 4; nt++)
#pragma unroll
            for (int i = 0; i < 4; i++) c[mt][nt][i] = 0.f;

#pragma unroll
    for (int ks = 0; ks < 4; ks++) {
        unsigned ah[2][4], al[2][4];
#pragma unroll
        for (int mt = 0; mt < 2; mt++) {
            int r = wm + mt * 16;
            ah[mt][0] = U0[r + g][8 * ks + qd];     ah[mt][1] = U0[r + g + 8][8 * ks + qd];
            ah[mt][2] = U0[r + g][8 * ks + qd + 4]; ah[mt][3] = U0[r + g + 8][8 * ks + qd + 4];
            al[mt][0] = U1[r + g][8 * ks + qd];     al[mt][1] = U1[r + g + 8][8 * ks + qd];
            al[mt][2] = U1[r + g][8 * ks + qd + 4]; al[mt][3] = U1[r + g + 8][8 * ks + qd + 4];
        }
#pragma unroll
        for (int nt = 0; nt < 4; nt++) {
            int cn = wn + nt * 8 + g;
            unsigned bh0 = U2[cn][8 * ks + qd], bh1 = U2[cn][8 * ks + qd + 4];
            unsigned bl0 = U3[cn][8 * ks + qd], bl1 = U3[cn][8 * ks + qd + 4];
#pragma unroll
            for (int mt = 0; mt < 2; mt++) {
                mma_bf16(c[mt][nt], ah[mt][0], ah[mt][1], ah[mt][2], ah[mt][3], bh0, bh1);
                mma_bf16(c[mt][nt], ah[mt][0], ah[mt][1], ah[mt][2], ah[mt][3], bl0, bl1);
                mma_bf16(c[mt][nt], al[mt][0], al[mt][1], al[mt][2], al[mt][3], bh0, bh1);
            }
        }
    }

    float* Hout = g_state + (((size_t)bh * NCHUNK + cch) * HEADDIM) * DSTATE + nh * 64;
#pragma unroll
    for (int mt = 0; mt < 2; mt++) {
#pragma unroll
        for (int nt = 0; nt < 4; nt++) {
            int prow = wm + mt * 16 + g;
            int col = wn + nt * 8 + 2 * qd;
            *(float2*)(Hout + (size_t)prow * DSTATE + col) =
                make_float2(c[mt][nt][0], c[mt][nt][1]);
            *(float2*)(Hout + (size_t)(prow + 8) * DSTATE + col) =
                make_float2(c[mt][nt][2], c[mt][nt][3]);
        }
    }
}

// ---------------- scan G kernel: G = C @ B^T per (b, chunk) -----------------
__global__ void __launch_bounds__(128) scan_g_kernel()
{
    __shared__ unsigned Ah[2][64][9], Al[2][64][9];
    __shared__ unsigned Wh[2][64][9], Wl[2][64][9];

    const int cch = blockIdx.x & 31, b = blockIdx.x >> 5;
    const int t0 = cch * CHUNK;
    const int tid = threadIdx.x;
    const int w = tid >> 5, lane = tid & 31;
    const int qd = lane & 3, g = lane >> 2;
    const int wm = (w & 1) * 32, wn = (w >> 1) * 32;
    const int lrow = tid >> 2;
    const int lc4 = (tid & 3) * 4;
    const int lp  = lc4 >> 1;

    float c[2][4][4];
#pragma unroll
    for (int mt = 0; mt < 2; mt++)
#pragma unroll
        for (int nt = 0; nt < 4; nt++)
#pragma unroll
            for (int i = 0; i < 4; i++) c[mt][nt][i] = 0.f;

    const float* Aptr0 = g_xBC + (size_t)(b * LSEQ + t0 + lrow) * CONVDIM + DINNER + DSTATE + lc4;
    const float* Aptr1 = Aptr0 + (size_t)32 * CONVDIM;
    const float* Wptr0 = g_xBC + (size_t)(b * LSEQ + t0 + lrow) * CONVDIM + DINNER + lc4;
    const float* Wptr1 = Wptr0 + (size_t)32 * CONVDIM;

    float4 pa0 = *(const float4*)Aptr0;
    float4 pa1 = *(const float4*)Aptr1;
    float4 pw0 = *(const float4*)Wptr0;
    float4 pw1 = *(const float4*)Wptr1;

    int buf = 0;
    for (int k0 = 0; k0 < DSTATE; k0 += 16) {
        unsigned hi, lo;
        bf16_split2(pa0.x, pa0.y, hi, lo); Ah[buf][lrow][lp] = hi; Al[buf][lrow][lp] = lo;
        bf16_split2(pa0.z, pa0.w, hi, lo); Ah[buf][lrow][lp + 1] = hi; Al[buf][lrow][lp + 1] = lo;
        bf16_split2(pa1.x, pa1.y, hi, lo); Ah[buf][lrow + 32][lp] = hi; Al[buf][lrow + 32][lp] = lo;
        bf16_split2(pa1.z, pa1.w, hi, lo); Ah[buf][lrow + 32][lp + 1] = hi; Al[buf][lrow + 32][lp + 1] = lo;
        bf16_split2(pw0.x, pw0.y, hi, lo); Wh[buf][lrow][lp] = hi; Wl[buf][lrow][lp] = lo;
        bf16_split2(pw0.z, pw0.w, hi, lo); Wh[buf][lrow][lp + 1] = hi; Wl[buf][lrow][lp + 1] = lo;
        bf16_split2(pw1.x, pw1.y, hi, lo); Wh[buf][lrow + 32][lp] = hi; Wl[buf][lrow + 32][lp] = lo;
        bf16_split2(pw1.z, pw1.w, hi, lo); Wh[buf][lrow + 32][lp + 1] = hi; Wl[buf][lrow + 32][lp + 1] = lo;
        __syncthreads();

        if (k0 + 16 < DSTATE) {
            pa0 = *(const float4*)(Aptr0 + k0 + 16);
            pa1 = *(const float4*)(Aptr1 + k0 + 16);
            pw0 = *(const float4*)(Wptr0 + k0 + 16);
            pw1 = *(const float4*)(Wptr1 + k0 + 16);
        }

        unsigned ah[2][4], al[2][4];
#pragma unroll
        for (int mt = 0; mt < 2; mt++) {
            int r = wm + mt * 16;
            ah[mt][0] = Ah[buf][r + g][qd];     ah[mt][1] = Ah[buf][r + g + 8][qd];
            ah[mt][2] = Ah[buf][r + g][qd + 4]; ah[mt][3] = Ah[buf][r + g + 8][qd + 4];
            al[mt][0] = Al[buf][r + g][qd];     al[mt][1] = Al[buf][r + g + 8][qd];
            al[mt][2] = Al[buf][r + g][qd + 4]; al[mt][3] = Al[buf][r + g + 8][qd + 4];
        }
#pragma unroll
        for (int nt = 0; nt < 4; nt++) {
            int cn = wn + nt * 8 + g;
            unsigned bh0 = Wh[buf][cn][qd], bh1 = Wh[buf][cn][qd + 4];
            unsigned bl0 = Wl[buf][cn][qd], bl1 = Wl[buf][cn][qd + 4];
#pragma unroll
            for (int mt = 0; mt < 2; mt++) {
                mma_bf16(c[mt][nt], ah[mt][0], ah[mt][1], ah[mt][2], ah[mt][3], bh0, bh1);
                mma_bf16(c[mt][nt], ah[mt][0], ah[mt][1], ah[mt][2], ah[mt][3], bl0, bl1);
                mma_bf16(c[mt][nt], al[mt][0], al[mt][1], al[mt][2], al[mt][3], bh0, bh1);
            }
        }
        buf ^= 1;
    }

    float* Gout = g_G + (size_t)(b * NCHUNK + cch) * (CHUNK * CHUNK);
#pragma unroll
    for (int mt = 0; mt < 2; mt++) {
#pragma unroll
        for (int nt = 0; nt < 4; nt++) {
            int row = wm + mt * 16 + g;
            int col = wn + nt * 8 + 2 * qd;
            *(float2*)(Gout + (size_t)row * CHUNK + col) =
                make_float2(c[mt][nt][0], c[mt][nt][1]);
            *(float2*)(Gout + (size_t)(row + 8) * CHUNK + col) =
                make_float2(c[mt][nt][2], c[mt][nt][3]);
        }
    }
}

// ---------------- pass B: sequential combine with batched prefetch ----------
__global__ void __launch_bounds__(256) combine_state_kernel()
{
    int idx = blockIdx.x * blockDim.x + threadIdx.x;
    int nq = idx & 63;
    int p  = (idx >> 6) & 63;
    int bh = idx >> 12;
    float2 H = make_float2(0.f, 0.f);
    const float* Pb = g_P + bh * NCHUNK;
    size_t base = (((size_t)bh * NCHUNK) * HEADDIM + p) * DSTATE + nq * 2;
    const size_t cstride = (size_t)HEADDIM * DSTATE;

    for (int cc0 = 0; cc0 < NCHUNK; cc0 += 8) {
        float2 S[8];
#pragma unroll
        for (int j = 0; j < 8; j++)
            S[j] = *(const float2*)&g_state[base + (size_t)(cc0 + j) * cstride];
#pragma unroll
        for (int j = 0; j < 8; j++) {
            *(float2*)&g_H0[base + (size_t)(cc0 + j) * cstride] = H;
            float P = Pb[cc0 + j];
            H.x = S[j].x + P * H.x;
            H.y = S[j].y + P * H.y;
        }
    }
}

// ---------------- scan Y kernel: y = M@X + (a_t C)@H0^T (tensor cores) ------
__global__ void __launch_bounds__(128) scan_y_kernel()
{
    __shared__ unsigned U0[64][33], U1[64][33], U2[64][33], U3[64][33];
    __shared__ float sla[64], sdt[64];

    const int cch = blockIdx.x & 31;
    const int h = (blockIdx.x >> 5) & 7;
    const int b = blockIdx.x >> 8;
    const int bh = b * NHEADS + h;
    const int t0 = cch * CHUNK;
    const int tid = threadIdx.x;
    const int w = tid >> 5, lane = tid & 31;
    const int qd = lane & 3, g = lane >> 2;
    const int wm = (w & 1) * 32, wn = (w >> 1) * 32;

    if (tid < 64) {
        sla[tid] = g_la[(size_t)bh * LSEQ + t0 + tid];
        sdt[tid] = g_dt[(size_t)(b * LSEQ + t0 + tid) * NHEADS + h];
    }
    __syncthreads();

    // build M = G * L * dt (masked, split bf16, pairs along s)
    const float* Gp = g_G + (size_t)(b * NCHUNK + cch) * (CHUNK * CHUNK);
#pragma unroll
    for (int i = 0; i < 16; i++) {
        int idx = tid + i * 128;
        int t = idx >> 5, sp = idx & 31;
        int s0 = 2 * sp, s1 = s0 + 1;
        float m0 = (s0 <= t) ? Gp[t * 64 + s0] * __expf(sla[t] - sla[s0]) * sdt[s0] : 0.f;
        float m1 = (s1 <= t) ? Gp[t * 64 + s1] * __expf(sla[t] - sla[s1]) * sdt[s1] : 0.f;
        unsigned hi, lo; bf16_split2(m0, m1, hi, lo);
        U0[t][sp] = hi; U1[t][sp] = lo;
    }
    // build X^T (p rows, pairs along s)
    const float* xb = g_xBC + (size_t)(b * LSEQ + t0) * CONVDIM + h * HEADDIM;
#pragma unroll
    for (int i = 0; i < 16; i++) {
        int idx = tid + i * 128;
        int p = idx >> 5, sp = idx & 31;
        float v0 = xb[(size_t)(2 * sp) * CONVDIM + p];
        float v1 = xb[(size_t)(2 * sp + 1) * CONVDIM + p];
        unsigned hi, lo; bf16_split2(v0, v1, hi, lo);
        U2[p][sp] = hi; U3[p][sp] = lo;
    }
    __syncthreads();

    float c[2][4][4];
#pragma unroll
    for (int mt = 0; mt < 2; mt++)
#pragma unroll
        for (int nt = 0; nt < 4; nt++)
#pragma unroll
            for (int i = 0; i < 4; i++) c[mt][nt][i] = 0.f;

    // phase 1: Y += M @ X  (K = 64 s values = 4 slabs)
#pragma unroll
    for (int ks = 0; ks < 4; ks++) {
        unsigned ah[2][4], al[2][4];
#pragma unroll
        for (int mt = 0; mt < 2; mt++) {
            int r = wm + mt * 16;
            ah[mt][0] = U0[r + g][8 * ks + qd];     ah[mt][1] = U0[r + g + 8][8 * ks + qd];
            ah[mt][2] = U0[r + g][8 * ks + qd + 4]; ah[mt][3] = U0[r + g + 8][8 * ks + qd + 4];
            al[mt][0] = U1[r + g][8 * ks + qd];     al[mt][1] = U1[r + g + 8][8 * ks + qd];
            al[mt][2] = U1[r + g][8 * ks + qd + 4]; al[mt][3] = U1[r + g + 8][8 * ks + qd + 4];
        }
#pragma unroll
        for (int nt = 0; nt < 4; nt++) {
            int cn = wn + nt * 8 + g;
            unsigned bh0 = U2[cn][8 * ks + qd], bh1 = U2[cn][8 * ks + qd + 4];
            unsigned bl0 = U3[cn][8 * ks + qd], bl1 = U3[cn][8 * ks + qd + 4];
#pragma unroll
            for (int mt = 0; mt < 2; mt++) {
                mma_bf16(c[mt][nt], ah[mt][0], ah[mt][1], ah[mt][2], ah[mt][3], bh0, bh1);
                mma_bf16(c[mt][nt], ah[mt][0], ah[mt][1], ah[mt][2], ah[mt][3], bl0, bl1);
                mma_bf16(c[mt][nt], al[mt][0], al[mt][1], al[mt][2], al[mt][3], bh0, bh1);
            }
        }
    }
    __syncthreads();

    // phase 2: Y += (a_t * C) @ H0^T  (K = 128 n, two halves of 64)
    const float* cb = g_xBC + (size_t)(b * LSEQ + t0) * CONVDIM + DINNER + DSTATE;
    const float* h0b = g_H0 + (((size_t)bh * NCHUNK + cch) * HEADDIM) * DSTATE;
    for (int nh = 0; nh < 2; nh++) {
#pragma unroll
        for (int i = 0; i < 16; i++) {
            int idx = tid + i * 128;
            int t = idx >> 5, np = idx & 31;
            float at = __expf(sla[t]);
            int nn = nh * 64 + 2 * np;
            float c0 = at * cb[(size_t)t * CONVDIM + nn];
            float c1 = at * cb[(size_t)t * CONVDIM + nn + 1];
            unsigned hi, lo; bf16_split2(c0, c1, hi, lo);
            U0[t][np] = hi; U1[t][np] = lo;
        }
#pragma unroll
        for (int i = 0; i < 16; i++) {
            int idx = tid + i * 128;
            int p = idx >> 5, np = idx & 31;
            int nn = nh * 64 + 2 * np;
            float v0 = h0b[(size_t)p * DSTATE + nn];
            float v1 = h0b[(size_t)p * DSTATE + nn + 1];
            unsigned hi, lo; bf16_split2(v0, v1, hi, lo);
            U2[p][np] = hi; U3[p][np] = lo;
        }
        __syncthreads();
#pragma unroll
        for (int ks = 0; ks < 4; ks++) {
            unsigned ah[2][4], al[2][4];
#pragma unroll
            for (int mt = 0; mt < 2; mt++) {
                int r = wm + mt * 16;
                ah[mt][0] = U0[r + g][8 * ks + qd];     ah[mt][1] = U0[r + g + 8][8 * ks + qd];
                ah[mt][2] = U0[r + g][8 * ks + qd + 4]; ah[mt][3] = U0[r + g + 8][8 * ks + qd + 4];
                al[mt][0] = U1[r + g][8 * ks + qd];     al[mt][1] = U1[r + g + 8][8 * ks + qd];
                al[mt][2] = U1[r + g][8 * ks + qd + 4]; al[mt][3] = U1[r + g + 8][8 * ks + qd + 4];
            }
#pragma unroll
            for (int nt = 0; nt < 4; nt++) {
                int cn = wn + nt * 8 + g;
                unsigned bh0 = U2[cn][8 * ks + qd], bh1 = U2[cn][8 * ks + qd + 4];
                unsigned bl0 = U3[cn][8 * ks + qd], bl1 = U3[cn][8 * ks + qd + 4];
#pragma unroll
                for (int mt = 0; mt < 2; mt++) {
                    mma_bf16(c[mt][nt], ah[mt][0], ah[mt][1], ah[mt][2], ah[mt][3], bh0, bh1);
                    mma_bf16(c[mt][nt], ah[mt][0], ah[mt][1], ah[mt][2], ah[mt][3], bl0, bl1);
                    mma_bf16(c[mt][nt], al[mt][0], al[mt][1], al[mt][2], al[mt][3], bh0, bh1);
                }
            }
        }
        __syncthreads();
    }

    // epilogue: write y
#pragma unroll
    for (int mt = 0; mt < 2; mt++) {
#pragma unroll
        for (int nt = 0; nt < 4; nt++) {
            int trow = wm + mt * 16 + g;
            int col = wn + nt * 8 + 2 * qd;
            *(float2*)(g_y + (size_t)(b * LSEQ + t0 + trow) * DINNER + h * HEADDIM + col) =
                make_float2(c[mt][nt][0], c[mt][nt][1]);
            *(float2*)(g_y + (size_t)(b * LSEQ + t0 + trow + 8) * DINNER + h * HEADDIM + col) =
                make_float2(c[mt][nt][2], c[mt][nt][3]);
        }
    }
}

// ---------------- gate + RMSNorm ----------------
__global__ void __launch_bounds__(512) gate_rms_kernel(const float* __restrict__ D_param,
                                                       const float* __restrict__ norm_w)
{
    int bl = blockIdx.x;
    int d = threadIdx.x;
    float y = g_y[(size_t)bl * DINNER + d] +
              D_param[d >> 6] * g_xBC[(size_t)bl * CONVDIM + d];
    float z = g_zxbcdt[(size_t)bl * DINPROJ + d];
    float g = y * (z / (1.f + __expf(-z)));

    __shared__ float sh[16];
    float s = g * g;
    int lane = d & 31, w = d >> 5;
#pragma unroll
    for (int o = 16; o; o >>= 1) s += __shfl_xor_sync(0xffffffffu, s, o);
    if (lane == 0) sh[w] = s;
    __syncthreads();
    if (w == 0) {
        float v = (lane < 16) ? sh[lane] : 0.f;
#pragma unroll
        for (int o = 16; o; o >>= 1) v += __shfl_xor_sync(0xffffffffu, v, o);
        if (lane == 0) sh[0] = v;
    }
    __syncthreads();
    float scale = rsqrtf(sh[0] * (1.f / DINNER) + 1e-5f);
    g_y[(size_t)bl * DINNER + d] = g * scale * norm_w[d];
}

// ---------------- V packing (split bf16 hi/lo, key-paired) ----------------
__global__ void __launch_bounds__(256) v_pack_kernel()
{
    int idx = blockIdx.x * blockDim.x + threadIdx.x;
    int d  = idx & 31;
    int kp = (idx >> 5) & 1023;
    int h  = (idx >> 15) & 7;
    int b  = idx >> 18;
    size_t src = ((size_t)(b * LSEQ + 2 * kp)) * DMODEL + h * AHD + d;
    float v0 = g_v[src];
    float v1 = g_v[src + DMODEL];
    unsigned hi, lo;
    bf16_split2(v0, v1, hi, lo);
    g_vhi[idx] = hi;
    g_vlo[idx] = lo;
}

// ---------------- flash attention: 128 queries/block, split-bf16 V ----------
__global__ void __launch_bounds__(256) attn_mma_kernel()
{
    __shared__ float Qs[128][40];
    __shared__ float Ks[64][40];
    __shared__ unsigned Vh[32][40];
    __shared__ unsigned Vl[32][40];

    const int q0 = blockIdx.x * 128;
    const int h = blockIdx.y;
    const int b = blockIdx.z;
    const int tid = threadIdx.x;
    const int w = tid >> 5, lane = tid & 31;
    const int qd = lane & 3, g = lane >> 2;

    const size_t base = (size_t)b * LSEQ * DMODEL + h * AHD;
    const unsigned* vhib = g_vhi + ((size_t)(b * NHEADS + h)) * 1024 * 32;
    const unsigned* vlob = g_vlo + ((size_t)(b * NHEADS + h)) * 1024 * 32;

#pragma unroll
    for (int i = 0; i < 4; i++) {
        int e = tid + i * 256;
        int row = e >> 3, c4 = (e & 7) * 4;
        *(float4*)&Qs[row][c4] =
            *(const float4*)(g_qp + base + (size_t)(q0 + row) * DMODEL + c4);
    }
    __syncthreads();

    unsigned qa[4][4];
#pragma unroll
    for (int ks = 0; ks < 4; ks++) {
        int r = w * 16;
        qa[ks][0] = __float_as_uint(Qs[r + g][8 * ks + qd]);
        qa[ks][1] = __float_as_uint(Qs[r + g + 8][8 * ks + qd]);
        qa[ks][2] = __float_as_uint(Qs[r + g][8 * ks + qd + 4]);
        qa[ks][3] = __float_as_uint(Qs[r + g + 8][8 * ks + qd + 4]);
    }

    float m0 = -1e30f, m1 = -1e30f, l0 = 0.f, l1 = 0.f;
    float o[4][4];
#pragma unroll
    for (int nt = 0; nt < 4; nt++)
#pragma unroll
        for (int i = 0; i < 4; i++) o[nt][i] = 0.f;

    for (int kt = 0; kt < LSEQ / 64; kt++) {
        __syncthreads();
#pragma unroll
        for (int i = 0; i < 2; i++) {
            int e = tid + i * 256;
            int row = e >> 3, c4 = (e & 7) * 4;
            *(float4*)&Ks[row][c4] =
                *(const float4*)(g_kp + base + (size_t)(kt * 64 + row) * DMODEL + c4);
        }
        {
            int kp = tid >> 3, q4 = (tid & 7) * 4;
            size_t gsrc = (size_t)(kt * 32 + kp) * 32 + q4;
            *(uint4*)&Vh[kp][q4] = *(const uint4*)(vhib + gsrc);
            *(uint4*)&Vl[kp][q4] = *(const uint4*)(vlob + gsrc);
        }
        __syncthreads();

        float s[8][4];
#pragma unroll
        for (int nt = 0; nt < 8; nt++)
#pragma unroll
            for (int i = 0; i < 4; i++) s[nt][i] = 0.f;
#pragma unroll
        for (int ks = 0; ks < 4; ks++) {
#pragma unroll
            for (int nt = 0; nt < 8; nt++) {
                unsigned b0 = __float_as_uint(Ks[nt * 8 + g][8 * ks + qd]);
                unsigned b1 = __float_as_uint(Ks[nt * 8 + g][8 * ks + qd + 4]);
                mma_tf32(s[nt], qa[ks], b0, b1);
            }
        }

        float r0 = -1e30f, r1 = -1e30f;
#pragma unroll
        for (int nt = 0; nt < 8; nt++) {
            r0 = fmaxf(r0, fmaxf(s[nt][0], s[nt][1]));
            r1 = fmaxf(r1, fmaxf(s[nt][2], s[nt][3]));
        }
        r0 = fmaxf(r0, __shfl_xor_sync(0xffffffffu, r0, 1));
        r0 = fmaxf(r0, __shfl_xor_sync(0xffffffffu, r0, 2));
        r1 = fmaxf(r1, __shfl_xor_sync(0xffffffffu, r1, 1));
        r1 = fmaxf(r1, __shfl_xor_sync(0xffffffffu, r1, 2));
        float nm0 = fmaxf(m0, r0), nm1 = fmaxf(m1, r1);
        float cf0 = __expf(m0 - nm0), cf1 = __expf(m1 - nm1);
        m0 = nm0; m1 = nm1;
        l0 *= cf0; l1 *= cf1;
#pragma unroll
        for (int nt = 0; nt < 4; nt++) {
            o[nt][0] *= cf0; o[nt][1] *= cf0;
            o[nt][2] *= cf1; o[nt][3] *= cf1;
        }

        unsigned plo[8], phi[8];
#pragma unroll
        for (int nt = 0; nt < 8; nt++) {
            float p0 = __expf(s[nt][0] - m0);
            float p1 = __expf(s[nt][1] - m0);
            float p2 = __expf(s[nt][2] - m1);
            float p3 = __expf(s[nt][3] - m1);
            l0 += p0 + p1;
            l1 += p2 + p3;
            __nv_bfloat162 lo = __floats2bfloat162_rn(p0, p1);
            __nv_bfloat162 hi = __floats2bfloat162_rn(p2, p3);
            plo[nt] = *(unsigned*)&lo;
            phi[nt] = *(unsigned*)&hi;
        }

#pragma unroll
        for (int kk = 0; kk < 4; kk++) {
            unsigned a0 = plo[2 * kk], a1 = phi[2 * kk];
            unsigned a2 = plo[2 * kk + 1], a3 = phi[2 * kk + 1];
#pragma unroll
            for (int nt = 0; nt < 4; nt++) {
                unsigned bh0 = Vh[kk * 8 + qd][nt * 8 + g];
                unsigned bh1 = Vh[kk * 8 + qd + 4][nt * 8 + g];
                mma_bf16(o[nt], a0, a1, a2, a3, bh0, bh1);
                unsigned bl0 = Vl[kk * 8 + qd][nt * 8 + g];
                unsigned bl1 = Vl[kk * 8 + qd + 4][nt * 8 + g];
                mma_bf16(o[nt], a0, a1, a2, a3, bl0, bl1);
            }
        }
    }

    l0 += __shfl_xor_sync(0xffffffffu, l0, 1);
    l0 += __shfl_xor_sync(0xffffffffu, l0, 2);
    l1 += __shfl_xor_sync(0xffffffffu, l1, 1);
    l1 += __shfl_xor_sync(0xffffffffu, l1, 2);

    float inv0 = 1.f / l0, inv1 = 1.f / l1;
    int row = q0 + w * 16 + g;
#pragma unroll
    for (int nt = 0; nt < 4; nt++) {
        int col = h * AHD + nt * 8 + 2 * qd;
        *(float2*)(g_o + (size_t)(b * LSEQ + row) * DMODEL + col) =
            make_float2(o[nt][0] * inv0, o[nt][1] * inv0);
        *(float2*)(g_o + (size_t)(b * LSEQ + row + 8) * DMODEL + col) =
            make_float2(o[nt][2] * inv1, o[nt][3] * inv1);
    }
}

// ---------------- LayerNorm over 1024 ----------------
__global__ void __launch_bounds__(256) layernorm_kernel(const float* __restrict__ ln_w,
                                                        const float* __restrict__ ln_b)
{
    int bl = blockIdx.x, tid = threadIdx.x;
    float4 v = *(const float4*)(g_mlp + (size_t)bl * MLPH + tid * 4);
    float s = v.x + v.y + v.z + v.w;
    float s2 = v.x * v.x + v.y * v.y + v.z * v.z + v.w * v.w;

    __shared__ float shs[8], shs2[8];
    int lane = tid & 31, w = tid >> 5;
#pragma unroll
    for (int o = 16; o; o >>= 1) {
        s += __shfl_xor_sync(0xffffffffu, s, o);
        s2 += __shfl_xor_sync(0xffffffffu, s2, o);
    }
    if (lane == 0) { shs[w] = s; shs2[w] = s2; }
    __syncthreads();
    if (w == 0) {
        float a = (lane < 8) ? shs[lane] : 0.f;
        float b2 = (lane < 8) ? shs2[lane] : 0.f;
#pragma unroll
        for (int o = 4; o; o >>= 1) {
            a += __shfl_xor_sync(0xffffffffu, a, o);
            b2 += __shfl_xor_sync(0xffffffffu, b2, o);
        }
        if (lane == 0) { shs[0] = a; shs2[0] = b2; }
    }
    __syncthreads();
    float mu = shs[0] * (1.f / MLPH);
    float var = shs2[0] * (1.f / MLPH) - mu * mu;
    float inv = rsqrtf(var + 1e-5f);

    float4 wv = *(const float4*)(ln_w + tid * 4);
    float4 bv = *(const float4*)(ln_b + tid * 4);
    float4 r;
    r.x = (v.x - mu) * inv * wv.x + bv.x;
    r.y = (v.y - mu) * inv * wv.y + bv.y;
    r.z = (v.z - mu) * inv * wv.z + bv.z;
    r.w = (v.w - mu) * inv * wv.w + bv.w;
    *(float4*)(g_mlp + (size_t)bl * MLPH + tid * 4) = r;
}

// ---------------- two-stage mean-pool + head ----------------
__global__ void __launch_bounds__(256) pool1_kernel()
{
    int b = blockIdx.x, seg = blockIdx.y;
    int d = threadIdx.x;
    float s = 0.f;
    int t0 = seg * 128;
#pragma unroll 8
    for (int t = 0; t < 128; t++)
        s += g_h2[((size_t)(b * LSEQ + t0 + t)) * DMODEL + d];
    g_pool[(b * 16 + seg) * DMODEL + d] = s;
}

__global__ void __launch_bounds__(256) pool2_kernel(const float* __restrict__ head_w,
                                                    const float* __restrict__ head_b,
                                                    float* __restrict__ out)
{
    int b = blockIdx.x;
    int d = threadIdx.x;
    float s = 0.f;
#pragma unroll
    for (int seg = 0; seg < 16; seg++)
        s += g_pool[(b * 16 + seg) * DMODEL + d];
    __shared__ float pooled[DMODEL];
    pooled[d] = s * (1.f / LSEQ);
    __syncthreads();
    if (d < 2) {
        float accv = head_b[d];
        for (int j = 0; j < DMODEL; j++) accv += pooled[j] * head_w[d * DMODEL + j];
        out[b * 2 + d] = accv;
    }
}

// ---------------- host launcher ----------------
extern "C" void kernel_launch(void* const* d_in, const int* in_sizes, int n_in,
                              void* d_out, int out_size)
{
    (void)in_sizes; (void)n_in; (void)out_size;
    const float* x         = (const float*)d_in[0];
    const float* context   = (const float*)d_in[1];
    const float* in_proj_w = (const float*)d_in[2];
    const float* conv_w    = (const float*)d_in[3];
    const float* conv_b    = (const float*)d_in[4];
    const float* dt_bias   = (const float*)d_in[5];
    const float* A_log     = (const float*)d_in[6];
    const float* D_param   = (const float*)d_in[7];
    const float* norm_w    = (const float*)d_in[8];
    const float* out_proj_w= (const float*)d_in[9];
    const float* wq        = (const float*)d_in[10];
    const float* wk        = (const float*)d_in[11];
    const float* wv        = (const float*)d_in[12];
    const float* wo        = (const float*)d_in[13];
    const float* wo_b      = (const float*)d_in[14];
    const float* w1        = (const float*)d_in[15];
    const float* b1        = (const float*)d_in[16];
    const float* ln_w      = (const float*)d_in[17];
    const float* ln_b      = (const float*)d_in[18];
    const float* w2        = (const float*)d_in[19];
    const float* b2        = (const float*)d_in[20];
    const float* head_w    = (const float*)d_in[21];
    const float* head_b    = (const float*)d_in[22];
    float* out = (float*)d_out;

    float *p_zx, *p_y, *p_hres, *p_v, *p_o, *p_ob, *p_mlp, *p_h2, *p_qp, *p_kp;
    unsigned *p_whi, *p_wlo;
    cudaGetSymbolAddress((void**)&p_zx,   g_zxbcdt);
    cudaGetSymbolAddress((void**)&p_y,    g_y);
    cudaGetSymbolAddress((void**)&p_hres, g_hres);
    cudaGetSymbolAddress((void**)&p_v,    g_v);
    cudaGetSymbolAddress((void**)&p_o,    g_o);
    cudaGetSymbolAddress((void**)&p_ob,   g_ob);
    cudaGetSymbolAddress((void**)&p_mlp,  g_mlp);
    cudaGetSymbolAddress((void**)&p_h2,   g_h2);
    cudaGetSymbolAddress((void**)&p_qp,   g_qp);
    cudaGetSymbolAddress((void**)&p_kp,   g_kp);
    cudaGetSymbolAddress((void**)&p_whi,  g_whi);
    cudaGetSymbolAddress((void**)&p_wlo,  g_wlo);

    // 0) pre-split all weights into bf16 hi/lo
    pack_w_kernel<<<(WTOTAL + 255) / 256, 256>>>(
        in_proj_w, out_proj_w, wq, wk, wv, wo, w1, w2);
    // 1) in_proj (big tile)
    gemm128_kernel<EPI_NONE><<<dim3((DINPROJ + 127) / 128, M4 / 128), 256>>>(
        x, p_whi + WOFF_INPROJ, p_wlo + WOFF_INPROJ, nullptr, nullptr,
        p_zx, M4, DINPROJ, DMODEL);
    // 2) conv + dt
    conv_dt_kernel<<<M4 / 16, CONVDIM>>>(conv_w, conv_b, dt_bias, A_log);
    // 3) SSD scan: all tensor-core now
    la_kernel<<<128, 128>>>(A_log);
    scan_g_kernel<<<BBATCH * NCHUNK, 128>>>();
    scan_state_kernel<<<BBATCH * NHEADS * NCHUNK * 2, 128>>>();
    combine_state_kernel<<<256, 256>>>();
    scan_y_kernel<<<BBATCH * NHEADS * NCHUNK, 128>>>();
    // 4) gate + RMSNorm
    gate_rms_kernel<<<M4, DINNER>>>(D_param, norm_w);
    // 5) out_proj + residual
    gemm_bf16_kernel<EPI_RES><<<dim3(DMODEL / 64, M4 / 64), 128>>>(
        p_y, p_whi + WOFF_OUTPROJ, p_wlo + WOFF_OUTPROJ, nullptr, x,
        p_hres, nullptr, M4, DMODEL, DINNER);
    // 6) Q projection (epilogue emits tf32-scaled g_qp)
    gemm_bf16_kernel<EPI_QPACK><<<dim3(DMODEL / 64, M4 / 64), 128>>>(
        p_hres, p_whi + WOFF_WQ, p_wlo + WOFF_WQ, nullptr, nullptr,
        p_qp, nullptr, M4, DMODEL, DMODEL);
    // 6b) fused K+V projection
    gemm_bf16_kernel<EPI_KV><<<dim3(512 / 64, M4 / 64), 128>>>(
        context, p_whi + WOFF_WK, p_wlo + WOFF_WK, nullptr, nullptr,
        p_kp, p_v, M4, 512, DMODEL);
    // 6c) V pack (split bf16 hi/lo)
    v_pack_kernel<<<(BBATCH * NHEADS * 1024 * 32) / 256, 256>>>();
    // 7) attention
    attn_mma_kernel<<<dim3(LSEQ / 128, NHEADS, BBATCH), 256>>>();
    // 8) attn out proj
    gemm_bf16_kernel<EPI_BIAS><<<dim3(DMODEL / 64, M4 / 64), 128>>>(
        p_o, p_whi + WOFF_WO, p_wlo + WOFF_WO, wo_b, nullptr,
        p_ob, nullptr, M4, DMODEL, DMODEL);
    // 9) MLP fc1 + GELU (big tile)
    gemm128_kernel<EPI_BIAS_GELU><<<dim3(MLPH / 128, M4 / 128), 256>>>(
        p_ob, p_whi + WOFF_W1, p_wlo + WOFF_W1, b1, nullptr,
        p_mlp, M4, MLPH, DMODEL);
    // 10) LayerNorm
    layernorm_kernel<<<M4, 256>>>(ln_w, ln_b);
    // 11) MLP fc2
    gemm_bf16_kernel<EPI_BIAS><<<dim3(DMODEL / 64, M4 / 64), 128>>>(
        p_mlp, p_whi + WOFF_W2, p_wlo + WOFF_W2, b2, nullptr,
        p_h2, nullptr, M4, DMODEL, MLPH);
    // 12) two-stage pool + head
    pool1_kernel<<<dim3(BBATCH, 16), 256>>>();
    pool2_kernel<<<BBATCH, 256>>>(head_w, head_b, out);
}